// round 5
// baseline (speedup 1.0000x reference)
#include <cuda_runtime.h>
#include <cuda_bf16.h>
#include <cstdint>

#define CB   4
#define CN   2048
#define CH   8
#define CDH  64
#define CDIM 512
#define ATT_SCALE 0.125f
#define SSTR 72            // smem row stride in bf16 (64 data + 8 pad)

typedef __nv_bfloat16 bf16;

// ---------------- scratch (__device__ globals; no allocation allowed) -------
__device__ bf16 g_xhi[CB * CN * CDIM];
__device__ bf16 g_xlo[CB * CN * CDIM];
__device__ bf16 g_qh[CB * CN * CDIM];
__device__ bf16 g_ql[CB * CN * CDIM];
__device__ bf16 g_kh[CB * CN * CDIM];
__device__ bf16 g_kl[CB * CN * CDIM];
__device__ bf16 g_vh[CB * CN * CDIM];
__device__ bf16 g_vl[CB * CN * CDIM];
__device__ bf16 g_ohi[CB * CN * CDIM];
__device__ bf16 g_olo[CB * CN * CDIM];
__device__ bf16 g_wh[4][CDIM * CDIM];
__device__ bf16 g_wl[4][CDIM * CDIM];
__device__ int  g_idx[CB * CN];      // compacted unmasked key indices per batch
__device__ int  g_cnt[CB];           // unmasked count per batch
__device__ float g_sv[CB * CDIM];    // sum of V rows over masked keys

// ---------------- helpers ----------------------------------------------------
__device__ __forceinline__ void mma16816(float* c, const uint32_t* a, uint32_t b0, uint32_t b1) {
    asm volatile(
        "mma.sync.aligned.m16n8k16.row.col.f32.bf16.bf16.f32 "
        "{%0,%1,%2,%3}, {%4,%5,%6,%7}, {%8,%9}, {%0,%1,%2,%3};\n"
        : "+f"(c[0]), "+f"(c[1]), "+f"(c[2]), "+f"(c[3])
        : "r"(a[0]), "r"(a[1]), "r"(a[2]), "r"(a[3]), "r"(b0), "r"(b1));
}
__device__ __forceinline__ uint32_t packbf(bf16 x, bf16 y) {
    __nv_bfloat162 t = __halves2bfloat162(x, y);
    return *reinterpret_cast<uint32_t*>(&t);
}
__device__ __forceinline__ uint32_t smem_u32(const void* p) {
    uint32_t a;
    asm("{ .reg .u64 t; cvta.to.shared.u64 t, %1; cvt.u32.u64 %0, t; }" : "=r"(a) : "l"(p));
    return a;
}
__device__ __forceinline__ void cp_async16(uint32_t saddr, const void* g) {
    asm volatile("cp.async.cg.shared.global [%0], [%1], 16;" :: "r"(saddr), "l"(g));
}
__device__ __forceinline__ void cp_commit() { asm volatile("cp.async.commit_group;"); }
template<int N> __device__ __forceinline__ void cp_wait() {
    asm volatile("cp.async.wait_group %0;" :: "n"(N));
}
__device__ __forceinline__ void split2(float v, bf16& h, bf16& l) {
    h = __float2bfloat16(v);
    l = __float2bfloat16(v - __bfloat162float(h));
}

// ---------------- fp32 -> bf16 hi/lo split -----------------------------------
__global__ void split_kernel(const float* __restrict__ src,
                             bf16* __restrict__ hi, bf16* __restrict__ lo, int n)
{
    int i = (blockIdx.x * blockDim.x + threadIdx.x) * 4;
    if (i >= n) return;
    float4 v = *(const float4*)(src + i);
    bf16 h0, h1, h2, h3, l0, l1, l2, l3;
    split2(v.x, h0, l0); split2(v.y, h1, l1);
    split2(v.z, h2, l2); split2(v.w, h3, l3);
    *(uint32_t*)(hi + i)     = packbf(h0, h1);
    *(uint32_t*)(hi + i + 2) = packbf(h2, h3);
    *(uint32_t*)(lo + i)     = packbf(l0, l1);
    *(uint32_t*)(lo + i + 2) = packbf(l2, l3);
}

// ---------------- mask scan: compact unmasked key list -----------------------
// one block per batch; 256 threads x 8 keys. Also zeroes g_sv for this batch.
__global__ void scan_kernel(const int* __restrict__ mask,
                            int* __restrict__ idxl, int* __restrict__ cnt,
                            float* __restrict__ sv)
{
    __shared__ int ps[256];
    const int b = blockIdx.x, t = threadIdx.x;
    sv[b * CDIM + t]       = 0.f;
    sv[b * CDIM + 256 + t] = 0.f;
    int loc[8], c = 0;
#pragma unroll
    for (int i = 0; i < 8; i++) {
        loc[i] = c;
        c += (mask[b * CN + t * 8 + i] != 0);
    }
    ps[t] = c;
    __syncthreads();
    for (int off = 1; off < 256; off <<= 1) {
        int v = (t >= off) ? ps[t - off] : 0;
        __syncthreads();
        ps[t] += v;
        __syncthreads();
    }
    int excl = ps[t] - c;
#pragma unroll
    for (int i = 0; i < 8; i++)
        if (mask[b * CN + t * 8 + i] != 0)
            idxl[b * CN + excl + loc[i]] = t * 8 + i;
    if (t == 255) cnt[b] = ps[255];
}

// ---------------- masked-V row sums ------------------------------------------
// grid (4 colchunks, CB, 8 rowsegs), 128 threads: one channel each, 256 rows.
__global__ void svsum_kernel(const bf16* __restrict__ vh, const bf16* __restrict__ vl,
                             const int* __restrict__ mask, float* __restrict__ sv)
{
    const int c  = blockIdx.x * 128 + threadIdx.x;
    const int b  = blockIdx.y;
    const int r0 = blockIdx.z * 256;
    float s = 0.f;
    for (int i = 0; i < 256; i++) {
        int row = r0 + i;
        if (mask[b * CN + row] == 0) {
            size_t gi = (size_t)(b * CN + row) * CDIM + c;
            s += __bfloat162float(vh[gi]) + __bfloat162float(vl[gi]);
        }
    }
    atomicAdd(&sv[b * CDIM + c], s);
}

// ---------------- GEMM mainloop (shared via macro) ---------------------------
#define TEN_B   (128 * SSTR * 2)
#define STAGE_B (4 * TEN_B)

#define GEMM_LOAD_CHUNK(st, kc)                                                   \
    {                                                                             \
        _Pragma("unroll")                                                         \
        for (int i = 0; i < 4; i++) {                                             \
            int idx = tid + 256 * i;                                              \
            int r = idx >> 3, u = idx & 7;                                        \
            uint32_t so = sbase + (uint32_t)((st) * STAGE_B + (r * SSTR + 8 * u) * 2); \
            cp_async16(so + 0 * TEN_B, Ah_g + (size_t)(rowBase + r) * CDIM + (kc) + 8 * u); \
            cp_async16(so + 1 * TEN_B, Al_g + (size_t)(rowBase + r) * CDIM + (kc) + 8 * u); \
            cp_async16(so + 2 * TEN_B, Bh_g + (size_t)(colBase + r) * CDIM + (kc) + 8 * u); \
            cp_async16(so + 3 * TEN_B, Bl_g + (size_t)(colBase + r) * CDIM + (kc) + 8 * u); \
        }                                                                         \
        cp_commit();                                                              \
    }

#define GEMM_COMPUTE_CHUNK(st)                                                    \
    {                                                                             \
        const bf16* Ah = gs + (st) * 4 * 128 * SSTR;                              \
        const bf16* Al = Ah + 128 * SSTR;                                         \
        const bf16* Bh = Al + 128 * SSTR;                                         \
        const bf16* Bl = Bh + 128 * SSTR;                                         \
        _Pragma("unroll")                                                         \
        for (int ka = 0; ka < 4; ka++) {                                          \
            const int ko = 16 * ka + 2 * tig;                                     \
            uint32_t a_h[2][4], a_l[2][4];                                        \
            _Pragma("unroll")                                                     \
            for (int m = 0; m < 2; m++) {                                         \
                int rb = 32 * wM + 16 * m;                                        \
                a_h[m][0] = *(const uint32_t*)&Ah[(rb + g)     * SSTR + ko];      \
                a_h[m][1] = *(const uint32_t*)&Ah[(rb + g + 8) * SSTR + ko];      \
                a_h[m][2] = *(const uint32_t*)&Ah[(rb + g)     * SSTR + ko + 8];  \
                a_h[m][3] = *(const uint32_t*)&Ah[(rb + g + 8) * SSTR + ko + 8];  \
                a_l[m][0] = *(const uint32_t*)&Al[(rb + g)     * SSTR + ko];      \
                a_l[m][1] = *(const uint32_t*)&Al[(rb + g + 8) * SSTR + ko];      \
                a_l[m][2] = *(const uint32_t*)&Al[(rb + g)     * SSTR + ko + 8];  \
                a_l[m][3] = *(const uint32_t*)&Al[(rb + g + 8) * SSTR + ko + 8];  \
            }                                                                     \
            _Pragma("unroll")                                                     \
            for (int j = 0; j < 8; j++) {                                         \
                int cr = 64 * wN + 8 * j + g;                                     \
                uint32_t b0h = *(const uint32_t*)&Bh[cr * SSTR + ko];             \
                uint32_t b1h = *(const uint32_t*)&Bh[cr * SSTR + ko + 8];         \
                uint32_t b0l = *(const uint32_t*)&Bl[cr * SSTR + ko];             \
                uint32_t b1l = *(const uint32_t*)&Bl[cr * SSTR + ko + 8];         \
                _Pragma("unroll")                                                 \
                for (int m = 0; m < 2; m++) {                                     \
                    mma16816(acc[m][j], a_h[m], b0h, b1h);                        \
                    mma16816(acc[m][j], a_h[m], b0l, b1l);                        \
                    mma16816(acc[m][j], a_l[m], b0h, b1h);                        \
                }                                                                 \
            }                                                                     \
        }                                                                         \
    }

#define GEMM_PREAMBLE()                                                           \
    const int tid  = threadIdx.x;                                                 \
    const int w    = tid >> 5;                                                    \
    const int lane = tid & 31;                                                    \
    const int g    = lane >> 2;                                                   \
    const int tig  = lane & 3;                                                    \
    const int wM   = w >> 1;                                                      \
    const int wN   = w & 1;                                                       \
    float acc[2][8][4];                                                           \
    _Pragma("unroll")                                                             \
    for (int m = 0; m < 2; m++)                                                   \
        _Pragma("unroll")                                                         \
        for (int j = 0; j < 8; j++)                                               \
            _Pragma("unroll")                                                     \
            for (int t = 0; t < 4; t++) acc[m][j][t] = 0.f;

#define GEMM_MAINLOOP()                                                           \
    GEMM_LOAD_CHUNK(0, 0)                                                         \
    _Pragma("unroll 1")                                                           \
    for (int ch = 0; ch < 8; ch++) {                                              \
        if (ch + 1 < 8) GEMM_LOAD_CHUNK((ch + 1) & 1, 64 * (ch + 1))              \
        if (ch + 1 < 8) cp_wait<1>(); else cp_wait<0>();                          \
        __syncthreads();                                                          \
        GEMM_COMPUTE_CHUNK(ch & 1)                                                \
        __syncthreads();                                                          \
    }

// ---------------- fused QKV projection (bf16 split output) -------------------
__global__ __launch_bounds__(256, 1) void qkv_gemm_kernel(
    const bf16* __restrict__ Ah_g, const bf16* __restrict__ Al_g,
    const bf16* __restrict__ w0h, const bf16* __restrict__ w0l,
    const bf16* __restrict__ w1h, const bf16* __restrict__ w1l,
    const bf16* __restrict__ w2h, const bf16* __restrict__ w2l,
    bf16* __restrict__ q_h, bf16* __restrict__ q_l,
    bf16* __restrict__ k_h, bf16* __restrict__ k_l,
    bf16* __restrict__ v_h, bf16* __restrict__ v_l)
{
    extern __shared__ bf16 gs[];
    const uint32_t sbase = smem_u32(gs);
    const int wsel    = blockIdx.x >> 2;
    const int colBase = (blockIdx.x & 3) * 128;
    const int rowBase = blockIdx.y * 128;
    const bf16* Bh_g = (wsel == 0) ? w0h : (wsel == 1) ? w1h : w2h;
    const bf16* Bl_g = (wsel == 0) ? w0l : (wsel == 1) ? w1l : w2l;
    bf16* outH = (wsel == 0) ? q_h : (wsel == 1) ? k_h : v_h;
    bf16* outL = (wsel == 0) ? q_l : (wsel == 1) ? k_l : v_l;
    const float scale = (wsel == 0) ? ATT_SCALE : 1.0f;

    GEMM_PREAMBLE()
    GEMM_MAINLOOP()

#pragma unroll
    for (int m = 0; m < 2; m++)
#pragma unroll
        for (int j = 0; j < 8; j++) {
            int row = rowBase + 32 * wM + 16 * m + g;
            int col = colBase + 64 * wN + 8 * j + 2 * tig;
            bf16 h0, h1, h2, h3, l0, l1, l2, l3;
            split2(acc[m][j][0] * scale, h0, l0);
            split2(acc[m][j][1] * scale, h1, l1);
            split2(acc[m][j][2] * scale, h2, l2);
            split2(acc[m][j][3] * scale, h3, l3);
            *(uint32_t*)&outH[(size_t)row * CDIM + col]       = packbf(h0, h1);
            *(uint32_t*)&outL[(size_t)row * CDIM + col]       = packbf(l0, l1);
            *(uint32_t*)&outH[(size_t)(row + 8) * CDIM + col] = packbf(h2, h3);
            *(uint32_t*)&outL[(size_t)(row + 8) * CDIM + col] = packbf(l2, l3);
        }
}

// ---------------- output projection (fp32 out) -------------------------------
__global__ __launch_bounds__(256, 1) void out_gemm_kernel(
    const bf16* __restrict__ Ah_g, const bf16* __restrict__ Al_g,
    const bf16* __restrict__ Bh_g, const bf16* __restrict__ Bl_g,
    float* __restrict__ C)
{
    extern __shared__ bf16 gs[];
    const uint32_t sbase = smem_u32(gs);
    const int colBase = blockIdx.x * 128;
    const int rowBase = blockIdx.y * 128;

    GEMM_PREAMBLE()
    GEMM_MAINLOOP()

#pragma unroll
    for (int m = 0; m < 2; m++)
#pragma unroll
        for (int j = 0; j < 8; j++) {
            int row = rowBase + 32 * wM + 16 * m + g;
            int col = colBase + 64 * wN + 8 * j + 2 * tig;
            *(float2*)&C[(size_t)row * CDIM + col]       = make_float2(acc[m][j][0], acc[m][j][1]);
            *(float2*)&C[(size_t)(row + 8) * CDIM + col] = make_float2(acc[m][j][2], acc[m][j][3]);
        }
}

// ---------------- flash attention over COMPACTED keys ------------------------
// 128 queries / block, 8 warps x 16 rows, key tiles of 64 (gathered), Dh = 64.
// Masked keys folded in exactly via constant-weight virtual tile in epilogue.
__global__ __launch_bounds__(256, 1) void attn_mma_kernel(
    const bf16* __restrict__ qh_g, const bf16* __restrict__ ql_g,
    const bf16* __restrict__ kh_g, const bf16* __restrict__ kl_g,
    const bf16* __restrict__ vh_g, const bf16* __restrict__ vl_g,
    const int* __restrict__ idxl, const int* __restrict__ cntp,
    const float* __restrict__ sv,
    bf16* __restrict__ OH, bf16* __restrict__ OL)
{
    extern __shared__ bf16 sm[];
    bf16* Kh = sm;                    // [key][dh]
    bf16* Kl = Kh + 64 * SSTR;
    bf16* Vh = Kl + 64 * SSTR;        // transposed [dh][key]
    bf16* Vl = Vh + 64 * SSTR;
    bf16* Qs = Vl + 64 * SSTR;        // staging for Qh then Ql

    const int tid  = threadIdx.x;
    const int w    = tid >> 5;
    const int lane = tid & 31;
    const int g    = lane >> 2;
    const int tig  = lane & 3;
    const int q0   = blockIdx.x * 128;
    const int h    = blockIdx.y & 7;
    const int b    = blockIdx.y >> 3;
    const int cb   = h * CDH;

    const int cnt1 = cntp[b];
    const int cnt0 = CN - cnt1;
    const int kend = (cnt1 + 63) & ~63;
    const int* bidx = idxl + b * CN;

    // ---- preload Q fragments (hi then lo via shared staging) ----
    uint32_t qfh[4][4], qfl[4][4];
#pragma unroll
    for (int pass = 0; pass < 2; pass++) {
        const bf16* src = pass ? ql_g : qh_g;
#pragma unroll
        for (int i = 0; i < 4; i++) {
            int idx = tid + 256 * i;
            int r = idx >> 3, u = idx & 7;
            *(uint4*)&Qs[r * SSTR + 8 * u] =
                *((const uint4*)(src + (size_t)(b * CN + q0 + r) * CDIM + cb) + u);
        }
        __syncthreads();
        uint32_t (*dst)[4] = pass ? qfl : qfh;
#pragma unroll
        for (int ka = 0; ka < 4; ka++) {
            int rb = 16 * w;
            int ko = 16 * ka + 2 * tig;
            dst[ka][0] = *(const uint32_t*)&Qs[(rb + g)     * SSTR + ko];
            dst[ka][1] = *(const uint32_t*)&Qs[(rb + g + 8) * SSTR + ko];
            dst[ka][2] = *(const uint32_t*)&Qs[(rb + g)     * SSTR + ko + 8];
            dst[ka][3] = *(const uint32_t*)&Qs[(rb + g + 8) * SSTR + ko + 8];
        }
        __syncthreads();
    }

    float o[8][4];
#pragma unroll
    for (int n = 0; n < 8; n++)
#pragma unroll
        for (int t = 0; t < 4; t++) o[n][t] = 0.f;
    float m0 = -1e30f, m1 = -1e30f, l0 = 0.f, l1 = 0.f;

    for (int kb = 0; kb < kend; kb += 64) {
        __syncthreads();

        // K tile gather (indices L1-broadcast across the 8-thread row group)
#pragma unroll
        for (int i = 0; i < 2; i++) {
            int idx = tid + 256 * i;
            int r = idx >> 3, u = idx & 7;
            int kk = kb + r;
            int ki = (kk < cnt1) ? bidx[kk] : 0;
            const size_t grow = (size_t)(b * CN + ki) * CDIM + cb;
            *(uint4*)&Kh[r * SSTR + 8 * u] = *((const uint4*)(kh_g + grow) + u);
            *(uint4*)&Kl[r * SSTR + 8 * u] = *((const uint4*)(kl_g + grow) + u);
        }
        // V tile gather, transposed: Vh[dh][key]
        {
            int d = tid & 63;
            int kg0 = tid >> 6;
#pragma unroll
            for (int kgi = 0; kgi < 2; kgi++) {
                int kg = kg0 + 4 * kgi;
                bf16 hv[8], lv[8];
#pragma unroll
                for (int i = 0; i < 8; i++) {
                    int kk = kb + kg * 8 + i;
                    int ki = (kk < cnt1) ? bidx[kk] : 0;
                    size_t gi = (size_t)(b * CN + ki) * CDIM + cb + d;
                    hv[i] = vh_g[gi];
                    lv[i] = vl_g[gi];
                }
#pragma unroll
                for (int p = 0; p < 4; p++) {
                    *(uint32_t*)&Vh[d * SSTR + kg * 8 + 2 * p] = packbf(hv[2 * p], hv[2 * p + 1]);
                    *(uint32_t*)&Vl[d * SSTR + kg * 8 + 2 * p] = packbf(lv[2 * p], lv[2 * p + 1]);
                }
            }
        }
        __syncthreads();

        // ---- S = Q K^T (3-pass split) ----
        float s[8][4];
#pragma unroll
        for (int j = 0; j < 8; j++)
#pragma unroll
            for (int t = 0; t < 4; t++) s[j][t] = 0.f;
#pragma unroll
        for (int ka = 0; ka < 4; ka++) {
            const int ko = 16 * ka + 2 * tig;
#pragma unroll
            for (int j = 0; j < 8; j++) {
                int kr = 8 * j + g;
                uint32_t b0h = *(const uint32_t*)&Kh[kr * SSTR + ko];
                uint32_t b1h = *(const uint32_t*)&Kh[kr * SSTR + ko + 8];
                uint32_t b0l = *(const uint32_t*)&Kl[kr * SSTR + ko];
                uint32_t b1l = *(const uint32_t*)&Kl[kr * SSTR + ko + 8];
                mma16816(s[j], qfh[ka], b0h, b1h);
                mma16816(s[j], qfh[ka], b0l, b1l);
                mma16816(s[j], qfl[ka], b0h, b1h);
            }
        }

        // ---- tail exclusion for padding keys (exact: weight 0) ----
        if (kb + 64 > cnt1) {
#pragma unroll
            for (int j = 0; j < 8; j++) {
                int kc0 = kb + 8 * j + 2 * tig;
                if (kc0     >= cnt1) { s[j][0] = -1e30f; s[j][2] = -1e30f; }
                if (kc0 + 1 >= cnt1) { s[j][1] = -1e30f; s[j][3] = -1e30f; }
            }
        }

        // ---- online softmax ----
        float rm0 = -1e30f, rm1 = -1e30f;
#pragma unroll
        for (int j = 0; j < 8; j++) {
            rm0 = fmaxf(rm0, fmaxf(s[j][0], s[j][1]));
            rm1 = fmaxf(rm1, fmaxf(s[j][2], s[j][3]));
        }
        rm0 = fmaxf(rm0, __shfl_xor_sync(0xffffffffu, rm0, 1));
        rm0 = fmaxf(rm0, __shfl_xor_sync(0xffffffffu, rm0, 2));
        rm1 = fmaxf(rm1, __shfl_xor_sync(0xffffffffu, rm1, 1));
        rm1 = fmaxf(rm1, __shfl_xor_sync(0xffffffffu, rm1, 2));
        float mn0 = fmaxf(m0, rm0), mn1 = fmaxf(m1, rm1);
        float al0 = __expf(m0 - mn0), al1 = __expf(m1 - mn1);
        m0 = mn0; m1 = mn1;
        float rs0 = 0.f, rs1 = 0.f;
#pragma unroll
        for (int j = 0; j < 8; j++) {
            s[j][0] = __expf(s[j][0] - m0); rs0 += s[j][0];
            s[j][1] = __expf(s[j][1] - m0); rs0 += s[j][1];
            s[j][2] = __expf(s[j][2] - m1); rs1 += s[j][2];
            s[j][3] = __expf(s[j][3] - m1); rs1 += s[j][3];
        }
        rs0 += __shfl_xor_sync(0xffffffffu, rs0, 1);
        rs0 += __shfl_xor_sync(0xffffffffu, rs0, 2);
        rs1 += __shfl_xor_sync(0xffffffffu, rs1, 1);
        rs1 += __shfl_xor_sync(0xffffffffu, rs1, 2);
        l0 = l0 * al0 + rs0;
        l1 = l1 * al1 + rs1;
#pragma unroll
        for (int n = 0; n < 8; n++) {
            o[n][0] *= al0; o[n][1] *= al0; o[n][2] *= al1; o[n][3] *= al1;
        }

        // ---- O += P V (P re-split in regs; 3-pass) ----
#pragma unroll
        for (int ka = 0; ka < 4; ka++) {
            const int j0 = 2 * ka, j1 = 2 * ka + 1;
            uint32_t ph[4], pl[4];
            {
                bf16 h00, h01, h02, h03, h10, h11, h12, h13;
                bf16 e00, e01, e02, e03, e10, e11, e12, e13;
                split2(s[j0][0], h00, e00); split2(s[j0][1], h01, e01);
                split2(s[j0][2], h02, e02); split2(s[j0][3], h03, e03);
                split2(s[j1][0], h10, e10); split2(s[j1][1], h11, e11);
                split2(s[j1][2], h12, e12); split2(s[j1][3], h13, e13);
                ph[0] = packbf(h00, h01); ph[1] = packbf(h02, h03);
                ph[2] = packbf(h10, h11); ph[3] = packbf(h12, h13);
                pl[0] = packbf(e00, e01); pl[1] = packbf(e02, e03);
                pl[2] = packbf(e10, e11); pl[3] = packbf(e12, e13);
            }
            const int ko = 16 * ka + 2 * tig;
#pragma unroll
            for (int n = 0; n < 8; n++) {
                int vr = 8 * n + g;
                uint32_t b0h = *(const uint32_t*)&Vh[vr * SSTR + ko];
                uint32_t b1h = *(const uint32_t*)&Vh[vr * SSTR + ko + 8];
                uint32_t b0l = *(const uint32_t*)&Vl[vr * SSTR + ko];
                uint32_t b1l = *(const uint32_t*)&Vl[vr * SSTR + ko + 8];
                mma16816(o[n], ph, b0h, b1h);
                mma16816(o[n], pl, b0h, b1h);
                mma16816(o[n], ph, b0l, b1l);
            }
        }
    }

    // ---- virtual tile: masked keys, all with score exactly 1e-9 ----
    float w0c = 0.f, w1c = 0.f, lf0 = l0, lf1 = l1;
    if (cnt0 > 0) {
        float mf0 = fmaxf(m0, 1e-9f);
        float mf1 = fmaxf(m1, 1e-9f);
        float sc0 = __expf(m0 - mf0);
        float sc1 = __expf(m1 - mf1);
        w0c = __expf(1e-9f - mf0);
        w1c = __expf(1e-9f - mf1);
        lf0 = l0 * sc0 + (float)cnt0 * w0c;
        lf1 = l1 * sc1 + (float)cnt0 * w1c;
#pragma unroll
        for (int n = 0; n < 8; n++) {
            o[n][0] *= sc0; o[n][1] *= sc0; o[n][2] *= sc1; o[n][3] *= sc1;
        }
    }

    // ---- epilogue: add masked-V correction, normalize, split-store ----
    float inv0 = 1.f / lf0, inv1 = 1.f / lf1;
    int qr = q0 + 16 * w + g;
#pragma unroll
    for (int n = 0; n < 8; n++) {
        int col = cb + 8 * n + 2 * tig;
        float sv0 = sv[b * CDIM + col];
        float sv1 = sv[b * CDIM + col + 1];
        float a0 = (o[n][0] + w0c * sv0) * inv0;
        float a1 = (o[n][1] + w0c * sv1) * inv0;
        float a2 = (o[n][2] + w1c * sv0) * inv1;
        float a3 = (o[n][3] + w1c * sv1) * inv1;
        bf16 h0, h1, h2, h3, e0, e1, e2, e3;
        split2(a0, h0, e0); split2(a1, h1, e1);
        split2(a2, h2, e2); split2(a3, h3, e3);
        *(uint32_t*)&OH[(size_t)(b * CN + qr) * CDIM + col]     = packbf(h0, h1);
        *(uint32_t*)&OL[(size_t)(b * CN + qr) * CDIM + col]     = packbf(e0, e1);
        *(uint32_t*)&OH[(size_t)(b * CN + qr + 8) * CDIM + col] = packbf(h2, h3);
        *(uint32_t*)&OL[(size_t)(b * CN + qr + 8) * CDIM + col] = packbf(e2, e3);
    }
}

// ---------------------------------------------------------------------------
extern "C" void kernel_launch(void* const* d_in, const int* in_sizes, int n_in,
                              void* d_out, int out_size)
{
    const float* x    = (const float*)d_in[0];
    const int*   mask = (const int*)  d_in[1];
    const float* W[4] = { (const float*)d_in[2], (const float*)d_in[3],
                          (const float*)d_in[4], (const float*)d_in[5] };
    float* out = (float*)d_out;

    bf16 *xh, *xl, *qh, *ql, *kh, *kl, *vh, *vl, *oh, *ol, *wh, *wl;
    int *idxl, *cnt;
    float *sv;
    cudaGetSymbolAddress((void**)&xh, g_xhi);
    cudaGetSymbolAddress((void**)&xl, g_xlo);
    cudaGetSymbolAddress((void**)&qh, g_qh);
    cudaGetSymbolAddress((void**)&ql, g_ql);
    cudaGetSymbolAddress((void**)&kh, g_kh);
    cudaGetSymbolAddress((void**)&kl, g_kl);
    cudaGetSymbolAddress((void**)&vh, g_vh);
    cudaGetSymbolAddress((void**)&vl, g_vl);
    cudaGetSymbolAddress((void**)&oh, g_ohi);
    cudaGetSymbolAddress((void**)&ol, g_olo);
    cudaGetSymbolAddress((void**)&wh, g_wh);
    cudaGetSymbolAddress((void**)&wl, g_wl);
    cudaGetSymbolAddress((void**)&idxl, g_idx);
    cudaGetSymbolAddress((void**)&cnt, g_cnt);
    cudaGetSymbolAddress((void**)&sv, g_sv);

    const int M  = CB * CN;            // 8192
    const int NX = M * CDIM;
    const int NW = CDIM * CDIM;

    split_kernel<<<NX / 4 / 256, 256>>>(x, xh, xl, NX);
    for (int w = 0; w < 4; w++)
        split_kernel<<<NW / 4 / 256, 256>>>(W[w], wh + (size_t)w * NW, wl + (size_t)w * NW, NW);
    scan_kernel<<<CB, 256>>>(mask, idxl, cnt, sv);

    const int gsm = 2 * STAGE_B;
    const int asmb = (4 * 64 + 128) * SSTR * (int)sizeof(bf16);
    cudaFuncSetAttribute(qkv_gemm_kernel, cudaFuncAttributeMaxDynamicSharedMemorySize, gsm);
    cudaFuncSetAttribute(out_gemm_kernel, cudaFuncAttributeMaxDynamicSharedMemorySize, gsm);
    cudaFuncSetAttribute(attn_mma_kernel, cudaFuncAttributeMaxDynamicSharedMemorySize, asmb);

    qkv_gemm_kernel<<<dim3(12, M / 128), 256, gsm>>>(
        xh, xl,
        wh + 0 * (size_t)NW, wl + 0 * (size_t)NW,
        wh + 1 * (size_t)NW, wl + 1 * (size_t)NW,
        wh + 2 * (size_t)NW, wl + 2 * (size_t)NW,
        qh, ql, kh, kl, vh, vl);

    svsum_kernel<<<dim3(CDIM / 128, CB, 8), 128>>>(vh, vl, mask, sv);

    attn_mma_kernel<<<dim3(CN / 128, CH * CB), 256, asmb>>>(
        qh, ql, kh, kl, vh, vl, idxl, cnt, sv, oh, ol);

    out_gemm_kernel<<<dim3(CDIM / 128, M / 128), 256, gsm>>>(
        oh, ol, wh + 3 * (size_t)NW, wl + 3 * (size_t)NW, out);
}

// round 6
// speedup vs baseline: 1.1672x; 1.1672x over previous
#include <cuda_runtime.h>
#include <cuda_bf16.h>
#include <cstdint>

#define CB   4
#define CN   2048
#define CH   8
#define CDH  64
#define CDIM 512
#define ATT_SCALE 0.125f
#define SSTR 72            // smem row stride in bf16 (64 data + 8 pad) = 144B

typedef __nv_bfloat16 bf16;

// ---------------- scratch (__device__ globals; no allocation allowed) -------
__device__ bf16 g_xhi[CB * CN * CDIM];
__device__ bf16 g_xlo[CB * CN * CDIM];
__device__ bf16 g_qh[CB * CN * CDIM];
__device__ bf16 g_ql[CB * CN * CDIM];
__device__ bf16 g_kh[CB * CN * CDIM];
__device__ bf16 g_kl[CB * CN * CDIM];
__device__ bf16 g_vh[CB * CN * CDIM];
__device__ bf16 g_vl[CB * CN * CDIM];
__device__ bf16 g_ohi[CB * CN * CDIM];
__device__ bf16 g_olo[CB * CN * CDIM];
__device__ bf16 g_wh[4][CDIM * CDIM];
__device__ bf16 g_wl[4][CDIM * CDIM];

// ---------------- helpers ----------------------------------------------------
__device__ __forceinline__ void mma16816(float* c, const uint32_t* a, uint32_t b0, uint32_t b1) {
    asm volatile(
        "mma.sync.aligned.m16n8k16.row.col.f32.bf16.bf16.f32 "
        "{%0,%1,%2,%3}, {%4,%5,%6,%7}, {%8,%9}, {%0,%1,%2,%3};\n"
        : "+f"(c[0]), "+f"(c[1]), "+f"(c[2]), "+f"(c[3])
        : "r"(a[0]), "r"(a[1]), "r"(a[2]), "r"(a[3]), "r"(b0), "r"(b1));
}
__device__ __forceinline__ void ldsm_x2_t(uint32_t& r0, uint32_t& r1, uint32_t saddr) {
    asm volatile("ldmatrix.sync.aligned.m8n8.x2.trans.shared.b16 {%0,%1}, [%2];"
                 : "=r"(r0), "=r"(r1) : "r"(saddr));
}
__device__ __forceinline__ uint32_t packbf(bf16 x, bf16 y) {
    __nv_bfloat162 t = __halves2bfloat162(x, y);
    return *reinterpret_cast<uint32_t*>(&t);
}
__device__ __forceinline__ uint32_t smem_u32(const void* p) {
    uint32_t a;
    asm("{ .reg .u64 t; cvta.to.shared.u64 t, %1; cvt.u32.u64 %0, t; }" : "=r"(a) : "l"(p));
    return a;
}
__device__ __forceinline__ void cp_async16(uint32_t saddr, const void* g) {
    asm volatile("cp.async.cg.shared.global [%0], [%1], 16;" :: "r"(saddr), "l"(g));
}
__device__ __forceinline__ void cp_commit() { asm volatile("cp.async.commit_group;"); }
template<int N> __device__ __forceinline__ void cp_wait() {
    asm volatile("cp.async.wait_group %0;" :: "n"(N));
}
__device__ __forceinline__ void split2(float v, bf16& h, bf16& l) {
    h = __float2bfloat16(v);
    l = __float2bfloat16(v - __bfloat162float(h));
}

// ---------------- fp32 -> bf16 hi/lo split -----------------------------------
__global__ void split_kernel(const float* __restrict__ src,
                             bf16* __restrict__ hi, bf16* __restrict__ lo, int n)
{
    int i = (blockIdx.x * blockDim.x + threadIdx.x) * 4;
    if (i >= n) return;
    float4 v = *(const float4*)(src + i);
    bf16 h0, h1, h2, h3, l0, l1, l2, l3;
    split2(v.x, h0, l0); split2(v.y, h1, l1);
    split2(v.z, h2, l2); split2(v.w, h3, l3);
    *(uint32_t*)(hi + i)     = packbf(h0, h1);
    *(uint32_t*)(hi + i + 2) = packbf(h2, h3);
    *(uint32_t*)(lo + i)     = packbf(l0, l1);
    *(uint32_t*)(lo + i + 2) = packbf(l2, l3);
}

// ---------------- GEMM mainloop (shared via macro) ---------------------------
#define TEN_B   (128 * SSTR * 2)
#define STAGE_B (4 * TEN_B)

#define GEMM_LOAD_CHUNK(st, kc)                                                   \
    {                                                                             \
        _Pragma("unroll")                                                         \
        for (int i = 0; i < 4; i++) {                                             \
            int idx = tid + 256 * i;                                              \
            int r = idx >> 3, u = idx & 7;                                        \
            uint32_t so = sbase + (uint32_t)((st) * STAGE_B + (r * SSTR + 8 * u) * 2); \
            cp_async16(so + 0 * TEN_B, Ah_g + (size_t)(rowBase + r) * CDIM + (kc) + 8 * u); \
            cp_async16(so + 1 * TEN_B, Al_g + (size_t)(rowBase + r) * CDIM + (kc) + 8 * u); \
            cp_async16(so + 2 * TEN_B, Bh_g + (size_t)(colBase + r) * CDIM + (kc) + 8 * u); \
            cp_async16(so + 3 * TEN_B, Bl_g + (size_t)(colBase + r) * CDIM + (kc) + 8 * u); \
        }                                                                         \
        cp_commit();                                                              \
    }

#define GEMM_COMPUTE_CHUNK(st)                                                    \
    {                                                                             \
        const bf16* Ah = gs + (st) * 4 * 128 * SSTR;                              \
        const bf16* Al = Ah + 128 * SSTR;                                         \
        const bf16* Bh = Al + 128 * SSTR;                                         \
        const bf16* Bl = Bh + 128 * SSTR;                                         \
        _Pragma("unroll")                                                         \
        for (int ka = 0; ka < 4; ka++) {                                          \
            const int ko = 16 * ka + 2 * tig;                                     \
            uint32_t a_h[2][4], a_l[2][4];                                        \
            _Pragma("unroll")                                                     \
            for (int m = 0; m < 2; m++) {                                         \
                int rb = 32 * wM + 16 * m;                                        \
                a_h[m][0] = *(const uint32_t*)&Ah[(rb + g)     * SSTR + ko];      \
                a_h[m][1] = *(const uint32_t*)&Ah[(rb + g + 8) * SSTR + ko];      \
                a_h[m][2] = *(const uint32_t*)&Ah[(rb + g)     * SSTR + ko + 8];  \
                a_h[m][3] = *(const uint32_t*)&Ah[(rb + g + 8) * SSTR + ko + 8];  \
                a_l[m][0] = *(const uint32_t*)&Al[(rb + g)     * SSTR + ko];      \
                a_l[m][1] = *(const uint32_t*)&Al[(rb + g + 8) * SSTR + ko];      \
                a_l[m][2] = *(const uint32_t*)&Al[(rb + g)     * SSTR + ko + 8];  \
                a_l[m][3] = *(const uint32_t*)&Al[(rb + g + 8) * SSTR + ko + 8];  \
            }                                                                     \
            _Pragma("unroll")                                                     \
            for (int j = 0; j < 8; j++) {                                         \
                int cr = 64 * wN + 8 * j + g;                                     \
                uint32_t b0h = *(const uint32_t*)&Bh[cr * SSTR + ko];             \
                uint32_t b1h = *(const uint32_t*)&Bh[cr * SSTR + ko + 8];         \
                uint32_t b0l = *(const uint32_t*)&Bl[cr * SSTR + ko];             \
                uint32_t b1l = *(const uint32_t*)&Bl[cr * SSTR + ko + 8];         \
                _Pragma("unroll")                                                 \
                for (int m = 0; m < 2; m++) {                                     \
                    mma16816(acc[m][j], a_h[m], b0h, b1h);                        \
                    mma16816(acc[m][j], a_h[m], b0l, b1l);                        \
                    mma16816(acc[m][j], a_l[m], b0h, b1h);                        \
                }                                                                 \
            }                                                                     \
        }                                                                         \
    }

#define GEMM_PREAMBLE()                                                           \
    const int tid  = threadIdx.x;                                                 \
    const int w    = tid >> 5;                                                    \
    const int lane = tid & 31;                                                    \
    const int g    = lane >> 2;                                                   \
    const int tig  = lane & 3;                                                    \
    const int wM   = w >> 1;                                                      \
    const int wN   = w & 1;                                                       \
    float acc[2][8][4];                                                           \
    _Pragma("unroll")                                                             \
    for (int m = 0; m < 2; m++)                                                   \
        _Pragma("unroll")                                                         \
        for (int j = 0; j < 8; j++)                                               \
            _Pragma("unroll")                                                     \
            for (int t = 0; t < 4; t++) acc[m][j][t] = 0.f;

#define GEMM_MAINLOOP()                                                           \
    GEMM_LOAD_CHUNK(0, 0)                                                         \
    _Pragma("unroll 1")                                                           \
    for (int ch = 0; ch < 8; ch++) {                                              \
        if (ch + 1 < 8) GEMM_LOAD_CHUNK((ch + 1) & 1, 64 * (ch + 1))              \
        if (ch + 1 < 8) cp_wait<1>(); else cp_wait<0>();                          \
        __syncthreads();                                                          \
        GEMM_COMPUTE_CHUNK(ch & 1)                                                \
        __syncthreads();                                                          \
    }

// ---------------- fused QKV projection (bf16 split output) -------------------
__global__ __launch_bounds__(256, 1) void qkv_gemm_kernel(
    const bf16* __restrict__ Ah_g, const bf16* __restrict__ Al_g,
    const bf16* __restrict__ w0h, const bf16* __restrict__ w0l,
    const bf16* __restrict__ w1h, const bf16* __restrict__ w1l,
    const bf16* __restrict__ w2h, const bf16* __restrict__ w2l,
    bf16* __restrict__ q_h, bf16* __restrict__ q_l,
    bf16* __restrict__ k_h, bf16* __restrict__ k_l,
    bf16* __restrict__ v_h, bf16* __restrict__ v_l)
{
    extern __shared__ bf16 gs[];
    const uint32_t sbase = smem_u32(gs);
    const int wsel    = blockIdx.x >> 2;
    const int colBase = (blockIdx.x & 3) * 128;
    const int rowBase = blockIdx.y * 128;
    const bf16* Bh_g = (wsel == 0) ? w0h : (wsel == 1) ? w1h : w2h;
    const bf16* Bl_g = (wsel == 0) ? w0l : (wsel == 1) ? w1l : w2l;
    bf16* outH = (wsel == 0) ? q_h : (wsel == 1) ? k_h : v_h;
    bf16* outL = (wsel == 0) ? q_l : (wsel == 1) ? k_l : v_l;
    const float scale = (wsel == 0) ? ATT_SCALE : 1.0f;

    GEMM_PREAMBLE()
    GEMM_MAINLOOP()

#pragma unroll
    for (int m = 0; m < 2; m++)
#pragma unroll
        for (int j = 0; j < 8; j++) {
            int row = rowBase + 32 * wM + 16 * m + g;
            int col = colBase + 64 * wN + 8 * j + 2 * tig;
            bf16 h0, h1, h2, h3, l0, l1, l2, l3;
            split2(acc[m][j][0] * scale, h0, l0);
            split2(acc[m][j][1] * scale, h1, l1);
            split2(acc[m][j][2] * scale, h2, l2);
            split2(acc[m][j][3] * scale, h3, l3);
            *(uint32_t*)&outH[(size_t)row * CDIM + col]       = packbf(h0, h1);
            *(uint32_t*)&outL[(size_t)row * CDIM + col]       = packbf(l0, l1);
            *(uint32_t*)&outH[(size_t)(row + 8) * CDIM + col] = packbf(h2, h3);
            *(uint32_t*)&outL[(size_t)(row + 8) * CDIM + col] = packbf(l2, l3);
        }
}

// ---------------- output projection (fp32 out) -------------------------------
__global__ __launch_bounds__(256, 1) void out_gemm_kernel(
    const bf16* __restrict__ Ah_g, const bf16* __restrict__ Al_g,
    const bf16* __restrict__ Bh_g, const bf16* __restrict__ Bl_g,
    float* __restrict__ C)
{
    extern __shared__ bf16 gs[];
    const uint32_t sbase = smem_u32(gs);
    const int colBase = blockIdx.x * 128;
    const int rowBase = blockIdx.y * 128;

    GEMM_PREAMBLE()
    GEMM_MAINLOOP()

#pragma unroll
    for (int m = 0; m < 2; m++)
#pragma unroll
        for (int j = 0; j < 8; j++) {
            int row = rowBase + 32 * wM + 16 * m + g;
            int col = colBase + 64 * wN + 8 * j + 2 * tig;
            *(float2*)&C[(size_t)row * CDIM + col]       = make_float2(acc[m][j][0], acc[m][j][1]);
            *(float2*)&C[(size_t)(row + 8) * CDIM + col] = make_float2(acc[m][j][2], acc[m][j][3]);
        }
}

// ---------------- flash attention: cp.async pipeline + ldmatrix.trans --------
// 128 queries / block, 8 warps x 16 rows, key tiles of 64, Dh = 64.
// K and V both stored [key][dh] in smem (pure 16B copies); PV B-fragments via
// ldmatrix.x2.trans. 2-stage double buffer on the 4 K/V tensors.
#define ATEN (64 * SSTR)               // one tensor, bf16 units
#define ASTG (4 * ATEN)                // one stage (Kh,Kl,Vh,Vl)

__global__ __launch_bounds__(256, 1) void attn_mma_kernel(
    const bf16* __restrict__ qh_g, const bf16* __restrict__ ql_g,
    const bf16* __restrict__ kh_g, const bf16* __restrict__ kl_g,
    const bf16* __restrict__ vh_g, const bf16* __restrict__ vl_g,
    const int* __restrict__ mask,
    bf16* __restrict__ OH, bf16* __restrict__ OL)
{
    extern __shared__ bf16 sm[];       // [2 stages][4 tensors][64*SSTR], then Q staging, then mask
    bf16* Qs = sm + 2 * ASTG;
    int*  Ms = (int*)(Qs + 128 * SSTR);

    const uint32_t sbase = smem_u32(sm);
    const int tid  = threadIdx.x;
    const int w    = tid >> 5;
    const int lane = tid & 31;
    const int g    = lane >> 2;
    const int tig  = lane & 3;
    const int q0   = blockIdx.x * 128;
    const int h    = blockIdx.y & 7;
    const int b    = blockIdx.y >> 3;
    const int cb   = h * CDH;

    // per-lane ldmatrix row address base (row = lane&15 within 16-key slab)
    const uint32_t lrow = (uint32_t)(lane & 15) * SSTR * 2;

    // ---- preload Q fragments (hi then lo via shared staging) ----
    uint32_t qfh[4][4], qfl[4][4];
#pragma unroll
    for (int pass = 0; pass < 2; pass++) {
        const bf16* src = pass ? ql_g : qh_g;
#pragma unroll
        for (int i = 0; i < 4; i++) {
            int idx = tid + 256 * i;
            int r = idx >> 3, u = idx & 7;
            *(uint4*)&Qs[r * SSTR + 8 * u] =
                *((const uint4*)(src + (size_t)(b * CN + q0 + r) * CDIM + cb) + u);
        }
        __syncthreads();
        uint32_t (*dst)[4] = pass ? qfl : qfh;
#pragma unroll
        for (int ka = 0; ka < 4; ka++) {
            int rb = 16 * w;
            int ko = 16 * ka + 2 * tig;
            dst[ka][0] = *(const uint32_t*)&Qs[(rb + g)     * SSTR + ko];
            dst[ka][1] = *(const uint32_t*)&Qs[(rb + g + 8) * SSTR + ko];
            dst[ka][2] = *(const uint32_t*)&Qs[(rb + g)     * SSTR + ko + 8];
            dst[ka][3] = *(const uint32_t*)&Qs[(rb + g + 8) * SSTR + ko + 8];
        }
        __syncthreads();
    }

    float o[8][4];
#pragma unroll
    for (int n = 0; n < 8; n++)
#pragma unroll
        for (int t = 0; t < 4; t++) o[n][t] = 0.f;
    float m0 = -1e30f, m1 = -1e30f, l0 = 0.f, l1 = 0.f;

    // ---- K/V tile loader: 4 tensors x 64 rows x 8 uint4, 8 cp per thread ----
#define ATT_LOAD(st, kb_)                                                          \
    {                                                                              \
        _Pragma("unroll")                                                          \
        for (int i = 0; i < 2; i++) {                                              \
            int idx = tid + 256 * i;          /* 0..511 */                         \
            int r = idx >> 3, u = idx & 7;                                         \
            size_t grow = (size_t)(b * CN + (kb_) + r) * CDIM + cb + 8 * u;        \
            uint32_t so = sbase + (uint32_t)(((st) * ASTG + r * SSTR + 8 * u) * 2);\
            cp_async16(so + 0 * ATEN * 2, kh_g + grow);                            \
            cp_async16(so + 1 * ATEN * 2, kl_g + grow);                            \
            cp_async16(so + 2 * ATEN * 2, vh_g + grow);                            \
            cp_async16(so + 3 * ATEN * 2, vl_g + grow);                            \
        }                                                                          \
        cp_commit();                                                               \
    }

    ATT_LOAD(0, 0)

#pragma unroll 1
    for (int it = 0; it < CN / 64; it++) {
        const int kb = it * 64;
        const int st = it & 1;
        if (it + 1 < CN / 64) ATT_LOAD((it + 1) & 1, kb + 64)
        if (it + 1 < CN / 64) cp_wait<1>(); else cp_wait<0>();
        if (tid < 64) Ms[tid] = mask[b * CN + kb + tid];
        __syncthreads();

        const bf16* Kh = sm + st * ASTG;
        const bf16* Kl = Kh + ATEN;
        const uint32_t vhb = sbase + (uint32_t)((st * ASTG + 2 * ATEN) * 2) + lrow;
        const uint32_t vlb = vhb + (uint32_t)(ATEN * 2);

        // ---- S = Q K^T (3-pass split) ----
        float s[8][4];
#pragma unroll
        for (int j = 0; j < 8; j++)
#pragma unroll
            for (int t = 0; t < 4; t++) s[j][t] = 0.f;
#pragma unroll
        for (int ka = 0; ka < 4; ka++) {
            const int ko = 16 * ka + 2 * tig;
#pragma unroll
            for (int j = 0; j < 8; j++) {
                int kr = 8 * j + g;
                uint32_t b0h = *(const uint32_t*)&Kh[kr * SSTR + ko];
                uint32_t b1h = *(const uint32_t*)&Kh[kr * SSTR + ko + 8];
                uint32_t b0l = *(const uint32_t*)&Kl[kr * SSTR + ko];
                uint32_t b1l = *(const uint32_t*)&Kl[kr * SSTR + ko + 8];
                mma16816(s[j], qfh[ka], b0h, b1h);
                mma16816(s[j], qfh[ka], b0l, b1l);
                mma16816(s[j], qfl[ka], b0h, b1h);
            }
        }

        // ---- constant masked-fill (1e-9, per reference) ----
#pragma unroll
        for (int j = 0; j < 8; j++) {
            int k0 = 8 * j + 2 * tig;
            if (Ms[k0]     == 0) { s[j][0] = 1e-9f; s[j][2] = 1e-9f; }
            if (Ms[k0 + 1] == 0) { s[j][1] = 1e-9f; s[j][3] = 1e-9f; }
        }

        // ---- online softmax ----
        float rm0 = -1e30f, rm1 = -1e30f;
#pragma unroll
        for (int j = 0; j < 8; j++) {
            rm0 = fmaxf(rm0, fmaxf(s[j][0], s[j][1]));
            rm1 = fmaxf(rm1, fmaxf(s[j][2], s[j][3]));
        }
        rm0 = fmaxf(rm0, __shfl_xor_sync(0xffffffffu, rm0, 1));
        rm0 = fmaxf(rm0, __shfl_xor_sync(0xffffffffu, rm0, 2));
        rm1 = fmaxf(rm1, __shfl_xor_sync(0xffffffffu, rm1, 1));
        rm1 = fmaxf(rm1, __shfl_xor_sync(0xffffffffu, rm1, 2));
        float mn0 = fmaxf(m0, rm0), mn1 = fmaxf(m1, rm1);
        float al0 = __expf(m0 - mn0), al1 = __expf(m1 - mn1);
        m0 = mn0; m1 = mn1;
        float rs0 = 0.f, rs1 = 0.f;
#pragma unroll
        for (int j = 0; j < 8; j++) {
            s[j][0] = __expf(s[j][0] - m0); rs0 += s[j][0];
            s[j][1] = __expf(s[j][1] - m0); rs0 += s[j][1];
            s[j][2] = __expf(s[j][2] - m1); rs1 += s[j][2];
            s[j][3] = __expf(s[j][3] - m1); rs1 += s[j][3];
        }
        rs0 += __shfl_xor_sync(0xffffffffu, rs0, 1);
        rs0 += __shfl_xor_sync(0xffffffffu, rs0, 2);
        rs1 += __shfl_xor_sync(0xffffffffu, rs1, 1);
        rs1 += __shfl_xor_sync(0xffffffffu, rs1, 2);
        l0 = l0 * al0 + rs0;
        l1 = l1 * al1 + rs1;
#pragma unroll
        for (int n = 0; n < 8; n++) {
            o[n][0] *= al0; o[n][1] *= al0; o[n][2] *= al1; o[n][3] *= al1;
        }

        // ---- O += P V (B-frags via ldmatrix.trans on [key][dh] tiles) ----
#pragma unroll
        for (int ka = 0; ka < 4; ka++) {
            const int j0 = 2 * ka, j1 = 2 * ka + 1;
            uint32_t ph[4], pl[4];
            {
                bf16 h00, h01, h02, h03, h10, h11, h12, h13;
                bf16 e00, e01, e02, e03, e10, e11, e12, e13;
                split2(s[j0][0], h00, e00); split2(s[j0][1], h01, e01);
                split2(s[j0][2], h02, e02); split2(s[j0][3], h03, e03);
                split2(s[j1][0], h10, e10); split2(s[j1][1], h11, e11);
                split2(s[j1][2], h12, e12); split2(s[j1][3], h13, e13);
                ph[0] = packbf(h00, h01); ph[1] = packbf(h02, h03);
                ph[2] = packbf(h10, h11); ph[3] = packbf(h12, h13);
                pl[0] = packbf(e00, e01); pl[1] = packbf(e02, e03);
                pl[2] = packbf(e10, e11); pl[3] = packbf(e12, e13);
            }
            const uint32_t ksl = (uint32_t)(ka * 16 * SSTR * 2);  // key-slab byte offset
#pragma unroll
            for (int n = 0; n < 8; n++) {
                uint32_t b0h, b1h, b0l, b1l;
                ldsm_x2_t(b0h, b1h, vhb + ksl + 16 * n);
                ldsm_x2_t(b0l, b1l, vlb + ksl + 16 * n);
                mma16816(o[n], ph, b0h, b1h);
                mma16816(o[n], pl, b0h, b1h);
                mma16816(o[n], ph, b0l, b1l);
            }
        }
        __syncthreads();
    }

    // ---- epilogue: normalize + hi/lo split store ----
    float inv0 = 1.f / l0, inv1 = 1.f / l1;
    int qr = q0 + 16 * w + g;
#pragma unroll
    for (int n = 0; n < 8; n++) {
        int col = cb + 8 * n + 2 * tig;
        float a0 = o[n][0] * inv0, a1 = o[n][1] * inv0;
        float a2 = o[n][2] * inv1, a3 = o[n][3] * inv1;
        bf16 h0, h1, h2, h3, e0, e1, e2, e3;
        split2(a0, h0, e0); split2(a1, h1, e1);
        split2(a2, h2, e2); split2(a3, h3, e3);
        *(uint32_t*)&OH[(size_t)(b * CN + qr) * CDIM + col]     = packbf(h0, h1);
        *(uint32_t*)&OL[(size_t)(b * CN + qr) * CDIM + col]     = packbf(e0, e1);
        *(uint32_t*)&OH[(size_t)(b * CN + qr + 8) * CDIM + col] = packbf(h2, h3);
        *(uint32_t*)&OL[(size_t)(b * CN + qr + 8) * CDIM + col] = packbf(e2, e3);
    }
}

// ---------------------------------------------------------------------------
extern "C" void kernel_launch(void* const* d_in, const int* in_sizes, int n_in,
                              void* d_out, int out_size)
{
    const float* x    = (const float*)d_in[0];
    const int*   mask = (const int*)  d_in[1];
    const float* W[4] = { (const float*)d_in[2], (const float*)d_in[3],
                          (const float*)d_in[4], (const float*)d_in[5] };
    float* out = (float*)d_out;

    bf16 *xh, *xl, *qh, *ql, *kh, *kl, *vh, *vl, *oh, *ol, *wh, *wl;
    cudaGetSymbolAddress((void**)&xh, g_xhi);
    cudaGetSymbolAddress((void**)&xl, g_xlo);
    cudaGetSymbolAddress((void**)&qh, g_qh);
    cudaGetSymbolAddress((void**)&ql, g_ql);
    cudaGetSymbolAddress((void**)&kh, g_kh);
    cudaGetSymbolAddress((void**)&kl, g_kl);
    cudaGetSymbolAddress((void**)&vh, g_vh);
    cudaGetSymbolAddress((void**)&vl, g_vl);
    cudaGetSymbolAddress((void**)&oh, g_ohi);
    cudaGetSymbolAddress((void**)&ol, g_olo);
    cudaGetSymbolAddress((void**)&wh, g_wh);
    cudaGetSymbolAddress((void**)&wl, g_wl);

    const int M  = CB * CN;            // 8192
    const int NX = M * CDIM;
    const int NW = CDIM * CDIM;

    split_kernel<<<NX / 4 / 256, 256>>>(x, xh, xl, NX);
    for (int w = 0; w < 4; w++)
        split_kernel<<<NW / 4 / 256, 256>>>(W[w], wh + (size_t)w * NW, wl + (size_t)w * NW, NW);

    const int gsm  = 2 * STAGE_B;
    const int asmb = (2 * 4 * 64 + 128) * SSTR * (int)sizeof(bf16) + 64 * (int)sizeof(int);
    cudaFuncSetAttribute(qkv_gemm_kernel, cudaFuncAttributeMaxDynamicSharedMemorySize, gsm);
    cudaFuncSetAttribute(out_gemm_kernel, cudaFuncAttributeMaxDynamicSharedMemorySize, gsm);
    cudaFuncSetAttribute(attn_mma_kernel, cudaFuncAttributeMaxDynamicSharedMemorySize, asmb);

    qkv_gemm_kernel<<<dim3(12, M / 128), 256, gsm>>>(
        xh, xl,
        wh + 0 * (size_t)NW, wl + 0 * (size_t)NW,
        wh + 1 * (size_t)NW, wl + 1 * (size_t)NW,
        wh + 2 * (size_t)NW, wl + 2 * (size_t)NW,
        qh, ql, kh, kl, vh, vl);

    attn_mma_kernel<<<dim3(CN / 128, CH * CB), 256, asmb>>>(
        qh, ql, kh, kl, vh, vl, mask, oh, ol);

    out_gemm_kernel<<<dim3(CDIM / 128, M / 128), 256, gsm>>>(
        oh, ol, wh + 3 * (size_t)NW, wl + 3 * (size_t)NW, out);
}

// round 7
// speedup vs baseline: 1.6124x; 1.3814x over previous
#include <cuda_runtime.h>
#include <cuda_bf16.h>
#include <cstdint>

#define CB   4
#define CN   2048
#define CH   8
#define CDH  64
#define CDIM 512
#define ATT_SCALE 0.125f
#define SSTR 72            // smem row stride in bf16 (64 data + 8 pad) = 144B

typedef __nv_bfloat16 bf16;

// ---------------- scratch (__device__ globals; no allocation allowed) -------
__device__ bf16 g_xhi[CB * CN * CDIM];
__device__ bf16 g_xlo[CB * CN * CDIM];
__device__ bf16 g_qh[CB * CN * CDIM];
__device__ bf16 g_ql[CB * CN * CDIM];
__device__ bf16 g_kh[CB * CN * CDIM];
__device__ bf16 g_kl[CB * CN * CDIM];
__device__ bf16 g_vh[CB * CN * CDIM];
__device__ bf16 g_vl[CB * CN * CDIM];
__device__ bf16 g_ohi[CB * CN * CDIM];
__device__ bf16 g_olo[CB * CN * CDIM];
__device__ bf16 g_wh[4][CDIM * CDIM];
__device__ bf16 g_wl[4][CDIM * CDIM];
__device__ int  g_idx[CB * CN];
__device__ int  g_cnt[CB];
__device__ float g_sv[CB * CDIM];

// ---------------- helpers ----------------------------------------------------
__device__ __forceinline__ void mma16816(float* c, const uint32_t* a, uint32_t b0, uint32_t b1) {
    asm volatile(
        "mma.sync.aligned.m16n8k16.row.col.f32.bf16.bf16.f32 "
        "{%0,%1,%2,%3}, {%4,%5,%6,%7}, {%8,%9}, {%0,%1,%2,%3};\n"
        : "+f"(c[0]), "+f"(c[1]), "+f"(c[2]), "+f"(c[3])
        : "r"(a[0]), "r"(a[1]), "r"(a[2]), "r"(a[3]), "r"(b0), "r"(b1));
}
__device__ __forceinline__ void ldsm_x2_t(uint32_t& r0, uint32_t& r1, uint32_t saddr) {
    asm volatile("ldmatrix.sync.aligned.m8n8.x2.trans.shared.b16 {%0,%1}, [%2];"
                 : "=r"(r0), "=r"(r1) : "r"(saddr));
}
__device__ __forceinline__ uint32_t packbf(bf16 x, bf16 y) {
    __nv_bfloat162 t = __halves2bfloat162(x, y);
    return *reinterpret_cast<uint32_t*>(&t);
}
__device__ __forceinline__ uint32_t smem_u32(const void* p) {
    uint32_t a;
    asm("{ .reg .u64 t; cvta.to.shared.u64 t, %1; cvt.u32.u64 %0, t; }" : "=r"(a) : "l"(p));
    return a;
}
__device__ __forceinline__ void cp_async16(uint32_t saddr, const void* g) {
    asm volatile("cp.async.cg.shared.global [%0], [%1], 16;" :: "r"(saddr), "l"(g));
}
__device__ __forceinline__ void cp_commit() { asm volatile("cp.async.commit_group;"); }
template<int N> __device__ __forceinline__ void cp_wait() {
    asm volatile("cp.async.wait_group %0;" :: "n"(N));
}
__device__ __forceinline__ void split2(float v, bf16& h, bf16& l) {
    h = __float2bfloat16(v);
    l = __float2bfloat16(v - __bfloat162float(h));
}

// ---------------- fp32 -> bf16 hi/lo split -----------------------------------
__global__ void split_kernel(const float* __restrict__ src,
                             bf16* __restrict__ hi, bf16* __restrict__ lo, int n)
{
    int i = (blockIdx.x * blockDim.x + threadIdx.x) * 4;
    if (i >= n) return;
    float4 v = *(const float4*)(src + i);
    bf16 h0, h1, h2, h3, l0, l1, l2, l3;
    split2(v.x, h0, l0); split2(v.y, h1, l1);
    split2(v.z, h2, l2); split2(v.w, h3, l3);
    *(uint32_t*)(hi + i)     = packbf(h0, h1);
    *(uint32_t*)(hi + i + 2) = packbf(h2, h3);
    *(uint32_t*)(lo + i)     = packbf(l0, l1);
    *(uint32_t*)(lo + i + 2) = packbf(l2, l3);
}

// ---------------- mask scan: compact unmasked key list -----------------------
__global__ void scan_kernel(const int* __restrict__ mask,
                            int* __restrict__ idxl, int* __restrict__ cnt,
                            float* __restrict__ sv)
{
    __shared__ int ps[256];
    const int b = blockIdx.x, t = threadIdx.x;
    sv[b * CDIM + t]       = 0.f;
    sv[b * CDIM + 256 + t] = 0.f;
    int loc[8], c = 0;
#pragma unroll
    for (int i = 0; i < 8; i++) {
        loc[i] = c;
        c += (mask[b * CN + t * 8 + i] != 0);
    }
    ps[t] = c;
    __syncthreads();
    for (int off = 1; off < 256; off <<= 1) {
        int v = (t >= off) ? ps[t - off] : 0;
        __syncthreads();
        ps[t] += v;
        __syncthreads();
    }
    int excl = ps[t] - c;
#pragma unroll
    for (int i = 0; i < 8; i++)
        if (mask[b * CN + t * 8 + i] != 0)
            idxl[b * CN + excl + loc[i]] = t * 8 + i;
    if (t == 255) cnt[b] = ps[255];
}

// ---------------- masked-V row sums ------------------------------------------
__global__ void svsum_kernel(const bf16* __restrict__ vh, const bf16* __restrict__ vl,
                             const int* __restrict__ mask, float* __restrict__ sv)
{
    const int c  = blockIdx.x * 128 + threadIdx.x;
    const int b  = blockIdx.y;
    const int r0 = blockIdx.z * 256;
    float s = 0.f;
    for (int i = 0; i < 256; i++) {
        int row = r0 + i;
        if (mask[b * CN + row] == 0) {
            size_t gi = (size_t)(b * CN + row) * CDIM + c;
            s += __bfloat162float(vh[gi]) + __bfloat162float(vl[gi]);
        }
    }
    atomicAdd(&sv[b * CDIM + c], s);
}

// ---------------- GEMM mainloop (shared via macro) ---------------------------
#define TEN_B   (128 * SSTR * 2)
#define STAGE_B (4 * TEN_B)

#define GEMM_LOAD_CHUNK(st, kc)                                                   \
    {                                                                             \
        _Pragma("unroll")                                                         \
        for (int i = 0; i < 4; i++) {                                             \
            int idx = tid + 256 * i;                                              \
            int r = idx >> 3, u = idx & 7;                                        \
            uint32_t so = sbase + (uint32_t)((st) * STAGE_B + (r * SSTR + 8 * u) * 2); \
            cp_async16(so + 0 * TEN_B, Ah_g + (size_t)(rowBase + r) * CDIM + (kc) + 8 * u); \
            cp_async16(so + 1 * TEN_B, Al_g + (size_t)(rowBase + r) * CDIM + (kc) + 8 * u); \
            cp_async16(so + 2 * TEN_B, Bh_g + (size_t)(colBase + r) * CDIM + (kc) + 8 * u); \
            cp_async16(so + 3 * TEN_B, Bl_g + (size_t)(colBase + r) * CDIM + (kc) + 8 * u); \
        }                                                                         \
        cp_commit();                                                              \
    }

#define GEMM_COMPUTE_CHUNK(st)                                                    \
    {                                                                             \
        const bf16* Ah = gs + (st) * 4 * 128 * SSTR;                              \
        const bf16* Al = Ah + 128 * SSTR;                                         \
        const bf16* Bh = Al + 128 * SSTR;                                         \
        const bf16* Bl = Bh + 128 * SSTR;                                         \
        _Pragma("unroll")                                                         \
        for (int ka = 0; ka < 4; ka++) {                                          \
            const int ko = 16 * ka + 2 * tig;                                     \
            uint32_t a_h[2][4], a_l[2][4];                                        \
            _Pragma("unroll")                                                     \
            for (int m = 0; m < 2; m++) {                                         \
                int rb = 32 * wM + 16 * m;                                        \
                a_h[m][0] = *(const uint32_t*)&Ah[(rb + g)     * SSTR + ko];      \
                a_h[m][1] = *(const uint32_t*)&Ah[(rb + g + 8) * SSTR + ko];      \
                a_h[m][2] = *(const uint32_t*)&Ah[(rb + g)     * SSTR + ko + 8];  \
                a_h[m][3] = *(const uint32_t*)&Ah[(rb + g + 8) * SSTR + ko + 8];  \
                a_l[m][0] = *(const uint32_t*)&Al[(rb + g)     * SSTR + ko];      \
                a_l[m][1] = *(const uint32_t*)&Al[(rb + g + 8) * SSTR + ko];      \
                a_l[m][2] = *(const uint32_t*)&Al[(rb + g)     * SSTR + ko + 8];  \
                a_l[m][3] = *(const uint32_t*)&Al[(rb + g + 8) * SSTR + ko + 8];  \
            }                                                                     \
            _Pragma("unroll")                                                     \
            for (int j = 0; j < 8; j++) {                                         \
                int cr = 64 * wN + 8 * j + g;                                     \
                uint32_t b0h = *(const uint32_t*)&Bh[cr * SSTR + ko];             \
                uint32_t b1h = *(const uint32_t*)&Bh[cr * SSTR + ko + 8];         \
                uint32_t b0l = *(const uint32_t*)&Bl[cr * SSTR + ko];             \
                uint32_t b1l = *(const uint32_t*)&Bl[cr * SSTR + ko + 8];         \
                _Pragma("unroll")                                                 \
                for (int m = 0; m < 2; m++) {                                     \
                    mma16816(acc[m][j], a_h[m], b0h, b1h);                        \
                    mma16816(acc[m][j], a_h[m], b0l, b1l);                        \
                    mma16816(acc[m][j], a_l[m], b0h, b1h);                        \
                }                                                                 \
            }                                                                     \
        }                                                                         \
    }

#define GEMM_PREAMBLE()                                                           \
    const int tid  = threadIdx.x;                                                 \
    const int w    = tid >> 5;                                                    \
    const int lane = tid & 31;                                                    \
    const int g    = lane >> 2;                                                   \
    const int tig  = lane & 3;                                                    \
    const int wM   = w >> 1;                                                      \
    const int wN   = w & 1;                                                       \
    float acc[2][8][4];                                                           \
    _Pragma("unroll")                                                             \
    for (int m = 0; m < 2; m++)                                                   \
        _Pragma("unroll")                                                         \
        for (int j = 0; j < 8; j++)                                               \
            _Pragma("unroll")                                                     \
            for (int t = 0; t < 4; t++) acc[m][j][t] = 0.f;

#define GEMM_MAINLOOP()                                                           \
    GEMM_LOAD_CHUNK(0, 0)                                                         \
    _Pragma("unroll 1")                                                           \
    for (int ch = 0; ch < 8; ch++) {                                              \
        if (ch + 1 < 8) GEMM_LOAD_CHUNK((ch + 1) & 1, 64 * (ch + 1))              \
        if (ch + 1 < 8) cp_wait<1>(); else cp_wait<0>();                          \
        __syncthreads();                                                          \
        GEMM_COMPUTE_CHUNK(ch & 1)                                                \
        __syncthreads();                                                          \
    }

// ---------------- fused QKV projection (bf16 split output) -------------------
__global__ __launch_bounds__(256, 1) void qkv_gemm_kernel(
    const bf16* __restrict__ Ah_g, const bf16* __restrict__ Al_g,
    const bf16* __restrict__ w0h, const bf16* __restrict__ w0l,
    const bf16* __restrict__ w1h, const bf16* __restrict__ w1l,
    const bf16* __restrict__ w2h, const bf16* __restrict__ w2l,
    bf16* __restrict__ q_h, bf16* __restrict__ q_l,
    bf16* __restrict__ k_h, bf16* __restrict__ k_l,
    bf16* __restrict__ v_h, bf16* __restrict__ v_l)
{
    extern __shared__ bf16 gs[];
    const uint32_t sbase = smem_u32(gs);
    const int wsel    = blockIdx.x >> 2;
    const int colBase = (blockIdx.x & 3) * 128;
    const int rowBase = blockIdx.y * 128;
    const bf16* Bh_g = (wsel == 0) ? w0h : (wsel == 1) ? w1h : w2h;
    const bf16* Bl_g = (wsel == 0) ? w0l : (wsel == 1) ? w1l : w2l;
    bf16* outH = (wsel == 0) ? q_h : (wsel == 1) ? k_h : v_h;
    bf16* outL = (wsel == 0) ? q_l : (wsel == 1) ? k_l : v_l;
    const float scale = (wsel == 0) ? ATT_SCALE : 1.0f;

    GEMM_PREAMBLE()
    GEMM_MAINLOOP()

#pragma unroll
    for (int m = 0; m < 2; m++)
#pragma unroll
        for (int j = 0; j < 8; j++) {
            int row = rowBase + 32 * wM + 16 * m + g;
            int col = colBase + 64 * wN + 8 * j + 2 * tig;
            bf16 h0, h1, h2, h3, l0, l1, l2, l3;
            split2(acc[m][j][0] * scale, h0, l0);
            split2(acc[m][j][1] * scale, h1, l1);
            split2(acc[m][j][2] * scale, h2, l2);
            split2(acc[m][j][3] * scale, h3, l3);
            *(uint32_t*)&outH[(size_t)row * CDIM + col]       = packbf(h0, h1);
            *(uint32_t*)&outL[(size_t)row * CDIM + col]       = packbf(l0, l1);
            *(uint32_t*)&outH[(size_t)(row + 8) * CDIM + col] = packbf(h2, h3);
            *(uint32_t*)&outL[(size_t)(row + 8) * CDIM + col] = packbf(l2, l3);
        }
}

// ---------------- output projection (fp32 out) -------------------------------
__global__ __launch_bounds__(256, 1) void out_gemm_kernel(
    const bf16* __restrict__ Ah_g, const bf16* __restrict__ Al_g,
    const bf16* __restrict__ Bh_g, const bf16* __restrict__ Bl_g,
    float* __restrict__ C)
{
    extern __shared__ bf16 gs[];
    const uint32_t sbase = smem_u32(gs);
    const int colBase = blockIdx.x * 128;
    const int rowBase = blockIdx.y * 128;

    GEMM_PREAMBLE()
    GEMM_MAINLOOP()

#pragma unroll
    for (int m = 0; m < 2; m++)
#pragma unroll
        for (int j = 0; j < 8; j++) {
            int row = rowBase + 32 * wM + 16 * m + g;
            int col = colBase + 64 * wN + 8 * j + 2 * tig;
            *(float2*)&C[(size_t)row * CDIM + col]       = make_float2(acc[m][j][0], acc[m][j][1]);
            *(float2*)&C[(size_t)(row + 8) * CDIM + col] = make_float2(acc[m][j][2], acc[m][j][3]);
        }
}

// ---------------- flash attention over COMPACTED keys ------------------------
// R6 machinery (cp.async double-buffer + ldmatrix.trans V) + R5 compaction math.
#define ATEN (64 * SSTR)
#define ASTG (4 * ATEN)

__global__ __launch_bounds__(256, 1) void attn_mma_kernel(
    const bf16* __restrict__ qh_g, const bf16* __restrict__ ql_g,
    const bf16* __restrict__ kh_g, const bf16* __restrict__ kl_g,
    const bf16* __restrict__ vh_g, const bf16* __restrict__ vl_g,
    const int* __restrict__ idxl, const int* __restrict__ cntp,
    const float* __restrict__ sv,
    bf16* __restrict__ OH, bf16* __restrict__ OL)
{
    extern __shared__ bf16 sm[];       // [2 stages][4 tensors][64*SSTR] + Q staging
    bf16* Qs = sm + 2 * ASTG;

    const uint32_t sbase = smem_u32(sm);
    const int tid  = threadIdx.x;
    const int w    = tid >> 5;
    const int lane = tid & 31;
    const int g    = lane >> 2;
    const int tig  = lane & 3;
    const int q0   = blockIdx.x * 128;
    const int h    = blockIdx.y & 7;
    const int b    = blockIdx.y >> 3;
    const int cb   = h * CDH;

    const int cnt1 = cntp[b];
    const int cnt0 = CN - cnt1;
    const int nt   = (cnt1 + 63) >> 6;
    const int* bidx = idxl + b * CN;

    const uint32_t lrow = (uint32_t)(lane & 15) * SSTR * 2;

    // ---- preload Q fragments (hi then lo via shared staging) ----
    uint32_t qfh[4][4], qfl[4][4];
#pragma unroll
    for (int pass = 0; pass < 2; pass++) {
        const bf16* src = pass ? ql_g : qh_g;
#pragma unroll
        for (int i = 0; i < 4; i++) {
            int idx = tid + 256 * i;
            int r = idx >> 3, u = idx & 7;
            *(uint4*)&Qs[r * SSTR + 8 * u] =
                *((const uint4*)(src + (size_t)(b * CN + q0 + r) * CDIM + cb) + u);
        }
        __syncthreads();
        uint32_t (*dst)[4] = pass ? qfl : qfh;
#pragma unroll
        for (int ka = 0; ka < 4; ka++) {
            int rb = 16 * w;
            int ko = 16 * ka + 2 * tig;
            dst[ka][0] = *(const uint32_t*)&Qs[(rb + g)     * SSTR + ko];
            dst[ka][1] = *(const uint32_t*)&Qs[(rb + g + 8) * SSTR + ko];
            dst[ka][2] = *(const uint32_t*)&Qs[(rb + g)     * SSTR + ko + 8];
            dst[ka][3] = *(const uint32_t*)&Qs[(rb + g + 8) * SSTR + ko + 8];
        }
        __syncthreads();
    }

    float o[8][4];
#pragma unroll
    for (int n = 0; n < 8; n++)
#pragma unroll
        for (int t = 0; t < 4; t++) o[n][t] = 0.f;
    float m0 = -1e30f, m1 = -1e30f, l0 = 0.f, l1 = 0.f;

    // ---- K/V tile loader with index gather ----
#define ATT_LOAD(st, kb_)                                                          \
    {                                                                              \
        _Pragma("unroll")                                                          \
        for (int i = 0; i < 2; i++) {                                              \
            int idx = tid + 256 * i;          /* 0..511 */                         \
            int r = idx >> 3, u = idx & 7;                                         \
            int kk = (kb_) + r;                                                    \
            int ki = (kk < cnt1) ? bidx[kk] : 0;                                   \
            size_t grow = (size_t)(b * CN + ki) * CDIM + cb + 8 * u;               \
            uint32_t so = sbase + (uint32_t)(((st) * ASTG + r * SSTR + 8 * u) * 2);\
            cp_async16(so + 0 * ATEN * 2, kh_g + grow);                            \
            cp_async16(so + 1 * ATEN * 2, kl_g + grow);                            \
            cp_async16(so + 2 * ATEN * 2, vh_g + grow);                            \
            cp_async16(so + 3 * ATEN * 2, vl_g + grow);                            \
        }                                                                          \
        cp_commit();                                                               \
    }

    ATT_LOAD(0, 0)

#pragma unroll 1
    for (int it = 0; it < nt; it++) {
        const int kb = it * 64;
        const int st = it & 1;
        if (it + 1 < nt) ATT_LOAD((it + 1) & 1, kb + 64)
        if (it + 1 < nt) cp_wait<1>(); else cp_wait<0>();
        __syncthreads();

        const bf16* Kh = sm + st * ASTG;
        const bf16* Kl = Kh + ATEN;
        const uint32_t vhb = sbase + (uint32_t)((st * ASTG + 2 * ATEN) * 2) + lrow;
        const uint32_t vlb = vhb + (uint32_t)(ATEN * 2);

        // ---- S = Q K^T (3-pass split) ----
        float s[8][4];
#pragma unroll
        for (int j = 0; j < 8; j++)
#pragma unroll
            for (int t = 0; t < 4; t++) s[j][t] = 0.f;
#pragma unroll
        for (int ka = 0; ka < 4; ka++) {
            const int ko = 16 * ka + 2 * tig;
#pragma unroll
            for (int j = 0; j < 8; j++) {
                int kr = 8 * j + g;
                uint32_t b0h = *(const uint32_t*)&Kh[kr * SSTR + ko];
                uint32_t b1h = *(const uint32_t*)&Kh[kr * SSTR + ko + 8];
                uint32_t b0l = *(const uint32_t*)&Kl[kr * SSTR + ko];
                uint32_t b1l = *(const uint32_t*)&Kl[kr * SSTR + ko + 8];
                mma16816(s[j], qfh[ka], b0h, b1h);
                mma16816(s[j], qfh[ka], b0l, b1l);
                mma16816(s[j], qfl[ka], b0h, b1h);
            }
        }

        // ---- tail exclusion for padding keys (exact: weight 0) ----
        if (kb + 64 > cnt1) {
#pragma unroll
            for (int j = 0; j < 8; j++) {
                int kc0 = kb + 8 * j + 2 * tig;
                if (kc0     >= cnt1) { s[j][0] = -1e30f; s[j][2] = -1e30f; }
                if (kc0 + 1 >= cnt1) { s[j][1] = -1e30f; s[j][3] = -1e30f; }
            }
        }

        // ---- online softmax ----
        float rm0 = -1e30f, rm1 = -1e30f;
#pragma unroll
        for (int j = 0; j < 8; j++) {
            rm0 = fmaxf(rm0, fmaxf(s[j][0], s[j][1]));
            rm1 = fmaxf(rm1, fmaxf(s[j][2], s[j][3]));
        }
        rm0 = fmaxf(rm0, __shfl_xor_sync(0xffffffffu, rm0, 1));
        rm0 = fmaxf(rm0, __shfl_xor_sync(0xffffffffu, rm0, 2));
        rm1 = fmaxf(rm1, __shfl_xor_sync(0xffffffffu, rm1, 1));
        rm1 = fmaxf(rm1, __shfl_xor_sync(0xffffffffu, rm1, 2));
        float mn0 = fmaxf(m0, rm0), mn1 = fmaxf(m1, rm1);
        float al0 = __expf(m0 - mn0), al1 = __expf(m1 - mn1);
        m0 = mn0; m1 = mn1;
        float rs0 = 0.f, rs1 = 0.f;
#pragma unroll
        for (int j = 0; j < 8; j++) {
            s[j][0] = __expf(s[j][0] - m0); rs0 += s[j][0];
            s[j][1] = __expf(s[j][1] - m0); rs0 += s[j][1];
            s[j][2] = __expf(s[j][2] - m1); rs1 += s[j][2];
            s[j][3] = __expf(s[j][3] - m1); rs1 += s[j][3];
        }
        rs0 += __shfl_xor_sync(0xffffffffu, rs0, 1);
        rs0 += __shfl_xor_sync(0xffffffffu, rs0, 2);
        rs1 += __shfl_xor_sync(0xffffffffu, rs1, 1);
        rs1 += __shfl_xor_sync(0xffffffffu, rs1, 2);
        l0 = l0 * al0 + rs0;
        l1 = l1 * al1 + rs1;
#pragma unroll
        for (int n = 0; n < 8; n++) {
            o[n][0] *= al0; o[n][1] *= al0; o[n][2] *= al1; o[n][3] *= al1;
        }

        // ---- O += P V (B-frags via ldmatrix.trans) ----
#pragma unroll
        for (int ka = 0; ka < 4; ka++) {
            const int j0 = 2 * ka, j1 = 2 * ka + 1;
            uint32_t ph[4], pl[4];
            {
                bf16 h00, h01, h02, h03, h10, h11, h12, h13;
                bf16 e00, e01, e02, e03, e10, e11, e12, e13;
                split2(s[j0][0], h00, e00); split2(s[j0][1], h01, e01);
                split2(s[j0][2], h02, e02); split2(s[j0][3], h03, e03);
                split2(s[j1][0], h10, e10); split2(s[j1][1], h11, e11);
                split2(s[j1][2], h12, e12); split2(s[j1][3], h13, e13);
                ph[0] = packbf(h00, h01); ph[1] = packbf(h02, h03);
                ph[2] = packbf(h10, h11); ph[3] = packbf(h12, h13);
                pl[0] = packbf(e00, e01); pl[1] = packbf(e02, e03);
                pl[2] = packbf(e10, e11); pl[3] = packbf(e12, e13);
            }
            const uint32_t ksl = (uint32_t)(ka * 16 * SSTR * 2);
#pragma unroll
            for (int n = 0; n < 8; n++) {
                uint32_t b0h, b1h, b0l, b1l;
                ldsm_x2_t(b0h, b1h, vhb + ksl + 16 * n);
                ldsm_x2_t(b0l, b1l, vlb + ksl + 16 * n);
                mma16816(o[n], ph, b0h, b1h);
                mma16816(o[n], pl, b0h, b1h);
                mma16816(o[n], ph, b0l, b1l);
            }
        }
        __syncthreads();
    }

    // ---- virtual tile: masked keys, all with score exactly 1e-9 ----
    float w0c = 0.f, w1c = 0.f, lf0 = l0, lf1 = l1;
    if (cnt0 > 0) {
        float mf0 = fmaxf(m0, 1e-9f);
        float mf1 = fmaxf(m1, 1e-9f);
        float sc0 = __expf(m0 - mf0);
        float sc1 = __expf(m1 - mf1);
        w0c = __expf(1e-9f - mf0);
        w1c = __expf(1e-9f - mf1);
        lf0 = l0 * sc0 + (float)cnt0 * w0c;
        lf1 = l1 * sc1 + (float)cnt0 * w1c;
#pragma unroll
        for (int n = 0; n < 8; n++) {
            o[n][0] *= sc0; o[n][1] *= sc0; o[n][2] *= sc1; o[n][3] *= sc1;
        }
    }

    // ---- epilogue: masked-V correction, normalize, split-store ----
    float inv0 = 1.f / lf0, inv1 = 1.f / lf1;
    int qr = q0 + 16 * w + g;
#pragma unroll
    for (int n = 0; n < 8; n++) {
        int col = cb + 8 * n + 2 * tig;
        float sv0 = sv[b * CDIM + col];
        float sv1 = sv[b * CDIM + col + 1];
        float a0 = (o[n][0] + w0c * sv0) * inv0;
        float a1 = (o[n][1] + w0c * sv1) * inv0;
        float a2 = (o[n][2] + w1c * sv0) * inv1;
        float a3 = (o[n][3] + w1c * sv1) * inv1;
        bf16 h0, h1, h2, h3, e0, e1, e2, e3;
        split2(a0, h0, e0); split2(a1, h1, e1);
        split2(a2, h2, e2); split2(a3, h3, e3);
        *(uint32_t*)&OH[(size_t)(b * CN + qr) * CDIM + col]     = packbf(h0, h1);
        *(uint32_t*)&OL[(size_t)(b * CN + qr) * CDIM + col]     = packbf(e0, e1);
        *(uint32_t*)&OH[(size_t)(b * CN + qr + 8) * CDIM + col] = packbf(h2, h3);
        *(uint32_t*)&OL[(size_t)(b * CN + qr + 8) * CDIM + col] = packbf(e2, e3);
    }
}

// ---------------------------------------------------------------------------
extern "C" void kernel_launch(void* const* d_in, const int* in_sizes, int n_in,
                              void* d_out, int out_size)
{
    const float* x    = (const float*)d_in[0];
    const int*   mask = (const int*)  d_in[1];
    const float* W[4] = { (const float*)d_in[2], (const float*)d_in[3],
                          (const float*)d_in[4], (const float*)d_in[5] };
    float* out = (float*)d_out;

    bf16 *xh, *xl, *qh, *ql, *kh, *kl, *vh, *vl, *oh, *ol, *wh, *wl;
    int *idxl, *cnt;
    float *sv;
    cudaGetSymbolAddress((void**)&xh, g_xhi);
    cudaGetSymbolAddress((void**)&xl, g_xlo);
    cudaGetSymbolAddress((void**)&qh, g_qh);
    cudaGetSymbolAddress((void**)&ql, g_ql);
    cudaGetSymbolAddress((void**)&kh, g_kh);
    cudaGetSymbolAddress((void**)&kl, g_kl);
    cudaGetSymbolAddress((void**)&vh, g_vh);
    cudaGetSymbolAddress((void**)&vl, g_vl);
    cudaGetSymbolAddress((void**)&oh, g_ohi);
    cudaGetSymbolAddress((void**)&ol, g_olo);
    cudaGetSymbolAddress((void**)&wh, g_wh);
    cudaGetSymbolAddress((void**)&wl, g_wl);
    cudaGetSymbolAddress((void**)&idxl, g_idx);
    cudaGetSymbolAddress((void**)&cnt, g_cnt);
    cudaGetSymbolAddress((void**)&sv, g_sv);

    const int M  = CB * CN;            // 8192
    const int NX = M * CDIM;
    const int NW = CDIM * CDIM;

    split_kernel<<<NX / 4 / 256, 256>>>(x, xh, xl, NX);
    for (int w = 0; w < 4; w++)
        split_kernel<<<NW / 4 / 256, 256>>>(W[w], wh + (size_t)w * NW, wl + (size_t)w * NW, NW);
    scan_kernel<<<CB, 256>>>(mask, idxl, cnt, sv);

    const int gsm  = 2 * STAGE_B;
    const int asmb = (2 * 4 * 64 + 128) * SSTR * (int)sizeof(bf16);
    cudaFuncSetAttribute(qkv_gemm_kernel, cudaFuncAttributeMaxDynamicSharedMemorySize, gsm);
    cudaFuncSetAttribute(out_gemm_kernel, cudaFuncAttributeMaxDynamicSharedMemorySize, gsm);
    cudaFuncSetAttribute(attn_mma_kernel, cudaFuncAttributeMaxDynamicSharedMemorySize, asmb);

    qkv_gemm_kernel<<<dim3(12, M / 128), 256, gsm>>>(
        xh, xl,
        wh + 0 * (size_t)NW, wl + 0 * (size_t)NW,
        wh + 1 * (size_t)NW, wl + 1 * (size_t)NW,
        wh + 2 * (size_t)NW, wl + 2 * (size_t)NW,
        qh, ql, kh, kl, vh, vl);

    svsum_kernel<<<dim3(CDIM / 128, CB, 8), 128>>>(vh, vl, mask, sv);

    attn_mma_kernel<<<dim3(CN / 128, CH * CB), 256, asmb>>>(
        qh, ql, kh, kl, vh, vl, idxl, cnt, sv, oh, ol);

    out_gemm_kernel<<<dim3(CDIM / 128, M / 128), 256, gsm>>>(
        oh, ol, wh + 3 * (size_t)NW, wl + 3 * (size_t)NW, out);
}

// round 8
// speedup vs baseline: 1.6788x; 1.0412x over previous
#include <cuda_runtime.h>
#include <cuda_bf16.h>
#include <cstdint>

#define CB   4
#define CN   2048
#define CH   8
#define CDH  64
#define CDIM 512
#define ATT_SCALE 0.125f
#define SSTR 72            // smem row stride in bf16 (64 data + 8 pad) = 144B

typedef __nv_bfloat16 bf16;

// ---------------- scratch (__device__ globals; no allocation allowed) -------
__device__ bf16 g_xhi[CB * CN * CDIM];
__device__ bf16 g_xlo[CB * CN * CDIM];
__device__ bf16 g_qh[CB * CN * CDIM];
__device__ bf16 g_ql[CB * CN * CDIM];
__device__ bf16 g_kh[CB * CN * CDIM];   // compacted K rows
__device__ bf16 g_kl[CB * CN * CDIM];
__device__ bf16 g_vh[CB * CN * CDIM];   // compacted V rows
__device__ bf16 g_vl[CB * CN * CDIM];
__device__ bf16 g_ohi[CB * CN * CDIM];
__device__ bf16 g_olo[CB * CN * CDIM];
__device__ bf16 g_wh[4][CDIM * CDIM];
__device__ bf16 g_wl[4][CDIM * CDIM];
__device__ int  g_idx[CB * CN];
__device__ int  g_cnt[CB];
__device__ float g_sv[CB * CDIM];       // sum of V over masked keys (exact fp32)
__device__ float g_xm[CB * CDIM];       // sum of x over masked keys

// ---------------- helpers ----------------------------------------------------
__device__ __forceinline__ void mma16816(float* c, const uint32_t* a, uint32_t b0, uint32_t b1) {
    asm volatile(
        "mma.sync.aligned.m16n8k16.row.col.f32.bf16.bf16.f32 "
        "{%0,%1,%2,%3}, {%4,%5,%6,%7}, {%8,%9}, {%0,%1,%2,%3};\n"
        : "+f"(c[0]), "+f"(c[1]), "+f"(c[2]), "+f"(c[3])
        : "r"(a[0]), "r"(a[1]), "r"(a[2]), "r"(a[3]), "r"(b0), "r"(b1));
}
__device__ __forceinline__ void ldsm_x2_t(uint32_t& r0, uint32_t& r1, uint32_t saddr) {
    asm volatile("ldmatrix.sync.aligned.m8n8.x2.trans.shared.b16 {%0,%1}, [%2];"
                 : "=r"(r0), "=r"(r1) : "r"(saddr));
}
__device__ __forceinline__ uint32_t packbf(bf16 x, bf16 y) {
    __nv_bfloat162 t = __halves2bfloat162(x, y);
    return *reinterpret_cast<uint32_t*>(&t);
}
__device__ __forceinline__ uint32_t smem_u32(const void* p) {
    uint32_t a;
    asm("{ .reg .u64 t; cvta.to.shared.u64 t, %1; cvt.u32.u64 %0, t; }" : "=r"(a) : "l"(p));
    return a;
}
__device__ __forceinline__ void cp_async16(uint32_t saddr, const void* g) {
    asm volatile("cp.async.cg.shared.global [%0], [%1], 16;" :: "r"(saddr), "l"(g));
}
__device__ __forceinline__ void cp_commit() { asm volatile("cp.async.commit_group;"); }
template<int N> __device__ __forceinline__ void cp_wait() {
    asm volatile("cp.async.wait_group %0;" :: "n"(N));
}
__device__ __forceinline__ void split2(float v, bf16& h, bf16& l) {
    h = __float2bfloat16(v);
    l = __float2bfloat16(v - __bfloat162float(h));
}

// ---------------- fp32 -> bf16 hi/lo split -----------------------------------
__global__ void split_kernel(const float* __restrict__ src,
                             bf16* __restrict__ hi, bf16* __restrict__ lo, int n)
{
    int i = (blockIdx.x * blockDim.x + threadIdx.x) * 4;
    if (i >= n) return;
    float4 v = *(const float4*)(src + i);
    bf16 h0, h1, h2, h3, l0, l1, l2, l3;
    split2(v.x, h0, l0); split2(v.y, h1, l1);
    split2(v.z, h2, l2); split2(v.w, h3, l3);
    *(uint32_t*)(hi + i)     = packbf(h0, h1);
    *(uint32_t*)(hi + i + 2) = packbf(h2, h3);
    *(uint32_t*)(lo + i)     = packbf(l0, l1);
    *(uint32_t*)(lo + i + 2) = packbf(l2, l3);
}

// ---------------- mask scan: compact unmasked key list -----------------------
__global__ void scan_kernel(const int* __restrict__ mask,
                            int* __restrict__ idxl, int* __restrict__ cnt,
                            float* __restrict__ xm)
{
    __shared__ int ps[256];
    const int b = blockIdx.x, t = threadIdx.x;
    xm[b * CDIM + t]       = 0.f;
    xm[b * CDIM + 256 + t] = 0.f;
    int loc[8], c = 0;
#pragma unroll
    for (int i = 0; i < 8; i++) {
        loc[i] = c;
        c += (mask[b * CN + t * 8 + i] != 0);
    }
    ps[t] = c;
    __syncthreads();
    for (int off = 1; off < 256; off <<= 1) {
        int v = (t >= off) ? ps[t - off] : 0;
        __syncthreads();
        ps[t] += v;
        __syncthreads();
    }
    int excl = ps[t] - c;
#pragma unroll
    for (int i = 0; i < 8; i++)
        if (mask[b * CN + t * 8 + i] != 0)
            idxl[b * CN + excl + loc[i]] = t * 8 + i;
    if (t == 255) cnt[b] = ps[255];
}

// ---------------- masked-x column sums ---------------------------------------
__global__ void xmsum_kernel(const float* __restrict__ x, const int* __restrict__ mask,
                             float* __restrict__ xm)
{
    const int c  = blockIdx.x * 128 + threadIdx.x;
    const int b  = blockIdx.y;
    const int r0 = blockIdx.z * 256;
    float s = 0.f;
#pragma unroll 4
    for (int i = 0; i < 256; i++) {
        int t = r0 + i;
        if (mask[b * CN + t] == 0)
            s += x[(size_t)(b * CN + t) * CDIM + c];
    }
    atomicAdd(&xm[b * CDIM + c], s);
}

// ---------------- sv = Wv * xm (fp32 GEMV per batch) -------------------------
__global__ void gemv_sv_kernel(const float* __restrict__ Wv, const float* __restrict__ xm,
                               float* __restrict__ sv)
{
    const int n = blockIdx.x * 128 + threadIdx.x;
    const int b = blockIdx.y;
    const float* wr = Wv + (size_t)n * CDIM;
    const float* xr = xm + b * CDIM;
    float s = 0.f;
#pragma unroll 8
    for (int c = 0; c < CDIM; c++) s += wr[c] * xr[c];
    sv[b * CDIM + n] = s;
}

// ---------------- GEMM mainloop (shared via macro) ---------------------------
#define TEN_B   (128 * SSTR * 2)
#define STAGE_B (4 * TEN_B)

#define GEMM_LOAD_CHUNK(st, kc)                                                   \
    {                                                                             \
        _Pragma("unroll")                                                         \
        for (int i = 0; i < 4; i++) {                                             \
            int idx = tid + 256 * i;                                              \
            int r = idx >> 3, u = idx & 7;                                        \
            uint32_t so = sbase + (uint32_t)((st) * STAGE_B + (r * SSTR + 8 * u) * 2); \
            cp_async16(so + 0 * TEN_B, Ah_g + (size_t)(rowBase + r) * CDIM + (kc) + 8 * u); \
            cp_async16(so + 1 * TEN_B, Al_g + (size_t)(rowBase + r) * CDIM + (kc) + 8 * u); \
            cp_async16(so + 2 * TEN_B, Bh_g + (size_t)(colBase + r) * CDIM + (kc) + 8 * u); \
            cp_async16(so + 3 * TEN_B, Bl_g + (size_t)(colBase + r) * CDIM + (kc) + 8 * u); \
        }                                                                         \
        cp_commit();                                                              \
    }

#define KV_LOAD_CHUNK(st, kc)                                                     \
    {                                                                             \
        _Pragma("unroll")                                                         \
        for (int i = 0; i < 4; i++) {                                             \
            int idx = tid + 256 * i;                                              \
            int r = idx >> 3, u = idx & 7;                                        \
            uint32_t so = sbase + (uint32_t)((st) * STAGE_B + (r * SSTR + 8 * u) * 2); \
            cp_async16(so + 0 * TEN_B, Ah_g + (size_t)(b * CN + toks[i]) * CDIM + (kc) + 8 * u); \
            cp_async16(so + 1 * TEN_B, Al_g + (size_t)(b * CN + toks[i]) * CDIM + (kc) + 8 * u); \
            cp_async16(so + 2 * TEN_B, Bh_g + (size_t)(colBase + r) * CDIM + (kc) + 8 * u); \
            cp_async16(so + 3 * TEN_B, Bl_g + (size_t)(colBase + r) * CDIM + (kc) + 8 * u); \
        }                                                                         \
        cp_commit();                                                              \
    }

#define GEMM_COMPUTE_CHUNK(st)                                                    \
    {                                                                             \
        const bf16* Ah = gs + (st) * 4 * 128 * SSTR;                              \
        const bf16* Al = Ah + 128 * SSTR;                                         \
        const bf16* Bh = Al + 128 * SSTR;                                         \
        const bf16* Bl = Bh + 128 * SSTR;                                         \
        _Pragma("unroll")                                                         \
        for (int ka = 0; ka < 4; ka++) {                                          \
            const int ko = 16 * ka + 2 * tig;                                     \
            uint32_t a_h[2][4], a_l[2][4];                                        \
            _Pragma("unroll")                                                     \
            for (int m = 0; m < 2; m++) {                                         \
                int rb = 32 * wM + 16 * m;                                        \
                a_h[m][0] = *(const uint32_t*)&Ah[(rb + g)     * SSTR + ko];      \
                a_h[m][1] = *(const uint32_t*)&Ah[(rb + g + 8) * SSTR + ko];      \
                a_h[m][2] = *(const uint32_t*)&Ah[(rb + g)     * SSTR + ko + 8];  \
                a_h[m][3] = *(const uint32_t*)&Ah[(rb + g + 8) * SSTR + ko + 8];  \
                a_l[m][0] = *(const uint32_t*)&Al[(rb + g)     * SSTR + ko];      \
                a_l[m][1] = *(const uint32_t*)&Al[(rb + g + 8) * SSTR + ko];      \
                a_l[m][2] = *(const uint32_t*)&Al[(rb + g)     * SSTR + ko + 8];  \
                a_l[m][3] = *(const uint32_t*)&Al[(rb + g + 8) * SSTR + ko + 8];  \
            }                                                                     \
            _Pragma("unroll")                                                     \
            for (int j = 0; j < 8; j++) {                                         \
                int cr = 64 * wN + 8 * j + g;                                     \
                uint32_t b0h = *(const uint32_t*)&Bh[cr * SSTR + ko];             \
                uint32_t b1h = *(const uint32_t*)&Bh[cr * SSTR + ko + 8];         \
                uint32_t b0l = *(const uint32_t*)&Bl[cr * SSTR + ko];             \
                uint32_t b1l = *(const uint32_t*)&Bl[cr * SSTR + ko + 8];         \
                _Pragma("unroll")                                                 \
                for (int m = 0; m < 2; m++) {                                     \
                    mma16816(acc[m][j], a_h[m], b0h, b1h);                        \
                    mma16816(acc[m][j], a_h[m], b0l, b1l);                        \
                    mma16816(acc[m][j], a_l[m], b0h, b1h);                        \
                }                                                                 \
            }                                                                     \
        }                                                                         \
    }

#define GEMM_PREAMBLE()                                                           \
    const int tid  = threadIdx.x;                                                 \
    const int w    = tid >> 5;                                                    \
    const int lane = tid & 31;                                                    \
    const int g    = lane >> 2;                                                   \
    const int tig  = lane & 3;                                                    \
    const int wM   = w >> 1;                                                      \
    const int wN   = w & 1;                                                       \
    float acc[2][8][4];                                                           \
    _Pragma("unroll")                                                             \
    for (int m = 0; m < 2; m++)                                                   \
        _Pragma("unroll")                                                         \
        for (int j = 0; j < 8; j++)                                               \
            _Pragma("unroll")                                                     \
            for (int t = 0; t < 4; t++) acc[m][j][t] = 0.f;

#define GEMM_MAINLOOP(LOADM)                                                      \
    LOADM(0, 0)                                                                   \
    _Pragma("unroll 1")                                                           \
    for (int ch = 0; ch < 8; ch++) {                                              \
        if (ch + 1 < 8) LOADM((ch + 1) & 1, 64 * (ch + 1))                        \
        if (ch + 1 < 8) cp_wait<1>(); else cp_wait<0>();                          \
        __syncthreads();                                                          \
        GEMM_COMPUTE_CHUNK(ch & 1)                                                \
        __syncthreads();                                                          \
    }

#define GEMM_EPI_SPLIT(outH, outL, rowB, scale)                                   \
    _Pragma("unroll")                                                             \
    for (int m = 0; m < 2; m++)                                                   \
        _Pragma("unroll")                                                         \
        for (int j = 0; j < 8; j++) {                                             \
            int row = (rowB) + 32 * wM + 16 * m + g;                              \
            int col = colBase + 64 * wN + 8 * j + 2 * tig;                        \
            bf16 h0, h1, h2, h3, l0, l1, l2, l3;                                  \
            split2(acc[m][j][0] * (scale), h0, l0);                               \
            split2(acc[m][j][1] * (scale), h1, l1);                               \
            split2(acc[m][j][2] * (scale), h2, l2);                               \
            split2(acc[m][j][3] * (scale), h3, l3);                               \
            *(uint32_t*)&(outH)[(size_t)row * CDIM + col]       = packbf(h0, h1); \
            *(uint32_t*)&(outL)[(size_t)row * CDIM + col]       = packbf(l0, l1); \
            *(uint32_t*)&(outH)[(size_t)(row + 8) * CDIM + col] = packbf(h2, h3); \
            *(uint32_t*)&(outL)[(size_t)(row + 8) * CDIM + col] = packbf(l2, l3); \
        }

// ---------------- Q projection (full rows, scaled split output) --------------
__global__ __launch_bounds__(256, 1) void q_gemm_kernel(
    const bf16* __restrict__ Ah_g, const bf16* __restrict__ Al_g,
    const bf16* __restrict__ Bh_g, const bf16* __restrict__ Bl_g,
    bf16* __restrict__ q_h, bf16* __restrict__ q_l)
{
    extern __shared__ bf16 gs[];
    const uint32_t sbase = smem_u32(gs);
    const int colBase = blockIdx.x * 128;
    const int rowBase = blockIdx.y * 128;
    GEMM_PREAMBLE()
    GEMM_MAINLOOP(GEMM_LOAD_CHUNK)
    GEMM_EPI_SPLIT(q_h, q_l, rowBase, ATT_SCALE)
}

// ---------------- K/V projection over COMPACTED rows -------------------------
__global__ __launch_bounds__(256, 1) void kv_gemm_kernel(
    const bf16* __restrict__ Ah_g, const bf16* __restrict__ Al_g,
    const bf16* __restrict__ wkh, const bf16* __restrict__ wkl,
    const bf16* __restrict__ wvh, const bf16* __restrict__ wvl,
    const int* __restrict__ idxl, const int* __restrict__ cntp,
    bf16* __restrict__ kch, bf16* __restrict__ kcl,
    bf16* __restrict__ vch, bf16* __restrict__ vcl)
{
    extern __shared__ bf16 gs[];
    const uint32_t sbase = smem_u32(gs);
    const int wsel    = blockIdx.x >> 2;
    const int colBase = (blockIdx.x & 3) * 128;
    const int b       = blockIdx.y >> 4;
    const int tile    = blockIdx.y & 15;
    const int cnt1    = cntp[b];
    const int kend    = (cnt1 + 63) & ~63;
    if (tile * 128 >= kend) return;
    const int* bidx = idxl + b * CN;
    const bf16* Bh_g = wsel ? wvh : wkh;
    const bf16* Bl_g = wsel ? wvl : wkl;
    bf16* outH = wsel ? vch : kch;
    bf16* outL = wsel ? vcl : kcl;

    GEMM_PREAMBLE()

    // gathered token index per load slot (clamped into valid compact range)
    int toks[4];
#pragma unroll
    for (int i = 0; i < 4; i++) {
        int r = (tid + 256 * i) >> 3;
        int jj = tile * 128 + r;
        toks[i] = bidx[jj < cnt1 ? jj : cnt1 - 1];
    }

    GEMM_MAINLOOP(KV_LOAD_CHUNK)

    const int rowB = b * CN + tile * 128;   // compact row base (global row index)
    GEMM_EPI_SPLIT(outH, outL, rowB, 1.0f)
}

// ---------------- output projection (fp32 out) -------------------------------
__global__ __launch_bounds__(256, 1) void out_gemm_kernel(
    const bf16* __restrict__ Ah_g, const bf16* __restrict__ Al_g,
    const bf16* __restrict__ Bh_g, const bf16* __restrict__ Bl_g,
    float* __restrict__ C)
{
    extern __shared__ bf16 gs[];
    const uint32_t sbase = smem_u32(gs);
    const int colBase = blockIdx.x * 128;
    const int rowBase = blockIdx.y * 128;

    GEMM_PREAMBLE()
    GEMM_MAINLOOP(GEMM_LOAD_CHUNK)

#pragma unroll
    for (int m = 0; m < 2; m++)
#pragma unroll
        for (int j = 0; j < 8; j++) {
            int row = rowBase + 32 * wM + 16 * m + g;
            int col = colBase + 64 * wN + 8 * j + 2 * tig;
            *(float2*)&C[(size_t)row * CDIM + col]       = make_float2(acc[m][j][0], acc[m][j][1]);
            *(float2*)&C[(size_t)(row + 8) * CDIM + col] = make_float2(acc[m][j][2], acc[m][j][3]);
        }
}

// ---------------- flash attention over compacted (contiguous) keys -----------
#define ATEN (64 * SSTR)
#define ASTG (4 * ATEN)

__global__ __launch_bounds__(256, 1) void attn_mma_kernel(
    const bf16* __restrict__ qh_g, const bf16* __restrict__ ql_g,
    const bf16* __restrict__ kh_g, const bf16* __restrict__ kl_g,
    const bf16* __restrict__ vh_g, const bf16* __restrict__ vl_g,
    const int* __restrict__ cntp, const float* __restrict__ sv,
    bf16* __restrict__ OH, bf16* __restrict__ OL)
{
    extern __shared__ bf16 sm[];       // [2 stages][4 tensors][64*SSTR] + Q staging
    bf16* Qs = sm + 2 * ASTG;

    const uint32_t sbase = smem_u32(sm);
    const int tid  = threadIdx.x;
    const int w    = tid >> 5;
    const int lane = tid & 31;
    const int g    = lane >> 2;
    const int tig  = lane & 3;
    const int q0   = blockIdx.x * 128;
    const int h    = blockIdx.y & 7;
    const int b    = blockIdx.y >> 3;
    const int cb   = h * CDH;

    const int cnt1 = cntp[b];
    const int cnt0 = CN - cnt1;
    const int nt   = (cnt1 + 63) >> 6;

    const uint32_t lrow = (uint32_t)(lane & 15) * SSTR * 2;

    // ---- preload Q fragments (hi then lo via shared staging) ----
    uint32_t qfh[4][4], qfl[4][4];
#pragma unroll
    for (int pass = 0; pass < 2; pass++) {
        const bf16* src = pass ? ql_g : qh_g;
#pragma unroll
        for (int i = 0; i < 4; i++) {
            int idx = tid + 256 * i;
            int r = idx >> 3, u = idx & 7;
            *(uint4*)&Qs[r * SSTR + 8 * u] =
                *((const uint4*)(src + (size_t)(b * CN + q0 + r) * CDIM + cb) + u);
        }
        __syncthreads();
        uint32_t (*dst)[4] = pass ? qfl : qfh;
#pragma unroll
        for (int ka = 0; ka < 4; ka++) {
            int rb = 16 * w;
            int ko = 16 * ka + 2 * tig;
            dst[ka][0] = *(const uint32_t*)&Qs[(rb + g)     * SSTR + ko];
            dst[ka][1] = *(const uint32_t*)&Qs[(rb + g + 8) * SSTR + ko];
            dst[ka][2] = *(const uint32_t*)&Qs[(rb + g)     * SSTR + ko + 8];
            dst[ka][3] = *(const uint32_t*)&Qs[(rb + g + 8) * SSTR + ko + 8];
        }
        __syncthreads();
    }

    float o[8][4];
#pragma unroll
    for (int n = 0; n < 8; n++)
#pragma unroll
        for (int t = 0; t < 4; t++) o[n][t] = 0.f;
    float m0 = -1e30f, m1 = -1e30f, l0 = 0.f, l1 = 0.f;

#define ATT_LOAD(st, kb_)                                                          \
    {                                                                              \
        _Pragma("unroll")                                                          \
        for (int i = 0; i < 2; i++) {                                              \
            int idx = tid + 256 * i;          /* 0..511 */                         \
            int r = idx >> 3, u = idx & 7;                                         \
            size_t grow = (size_t)(b * CN + (kb_) + r) * CDIM + cb + 8 * u;        \
            uint32_t so = sbase + (uint32_t)(((st) * ASTG + r * SSTR + 8 * u) * 2);\
            cp_async16(so + 0 * ATEN * 2, kh_g + grow);                            \
            cp_async16(so + 1 * ATEN * 2, kl_g + grow);                            \
            cp_async16(so + 2 * ATEN * 2, vh_g + grow);                            \
            cp_async16(so + 3 * ATEN * 2, vl_g + grow);                            \
        }                                                                          \
        cp_commit();                                                               \
    }

    if (nt > 0) ATT_LOAD(0, 0)

#pragma unroll 1
    for (int it = 0; it < nt; it++) {
        const int kb = it * 64;
        const int st = it & 1;
        if (it + 1 < nt) ATT_LOAD((it + 1) & 1, kb + 64)
        if (it + 1 < nt) cp_wait<1>(); else cp_wait<0>();
        __syncthreads();

        const bf16* Kh = sm + st * ASTG;
        const bf16* Kl = Kh + ATEN;
        const uint32_t vhb = sbase + (uint32_t)((st * ASTG + 2 * ATEN) * 2) + lrow;
        const uint32_t vlb = vhb + (uint32_t)(ATEN * 2);

        // ---- S = Q K^T (3-pass split) ----
        float s[8][4];
#pragma unroll
        for (int j = 0; j < 8; j++)
#pragma unroll
            for (int t = 0; t < 4; t++) s[j][t] = 0.f;
#pragma unroll
        for (int ka = 0; ka < 4; ka++) {
            const int ko = 16 * ka + 2 * tig;
#pragma unroll
            for (int j = 0; j < 8; j++) {
                int kr = 8 * j + g;
                uint32_t b0h = *(const uint32_t*)&Kh[kr * SSTR + ko];
                uint32_t b1h = *(const uint32_t*)&Kh[kr * SSTR + ko + 8];
                uint32_t b0l = *(const uint32_t*)&Kl[kr * SSTR + ko];
                uint32_t b1l = *(const uint32_t*)&Kl[kr * SSTR + ko + 8];
                mma16816(s[j], qfh[ka], b0h, b1h);
                mma16816(s[j], qfh[ka], b0l, b1l);
                mma16816(s[j], qfl[ka], b0h, b1h);
            }
        }

        // ---- tail exclusion for padding keys (exact: weight 0) ----
        if (kb + 64 > cnt1) {
#pragma unroll
            for (int j = 0; j < 8; j++) {
                int kc0 = kb + 8 * j + 2 * tig;
                if (kc0     >= cnt1) { s[j][0] = -1e30f; s[j][2] = -1e30f; }
                if (kc0 + 1 >= cnt1) { s[j][1] = -1e30f; s[j][3] = -1e30f; }
            }
        }

        // ---- online softmax ----
        float rm0 = -1e30f, rm1 = -1e30f;
#pragma unroll
        for (int j = 0; j < 8; j++) {
            rm0 = fmaxf(rm0, fmaxf(s[j][0], s[j][1]));
            rm1 = fmaxf(rm1, fmaxf(s[j][2], s[j][3]));
        }
        rm0 = fmaxf(rm0, __shfl_xor_sync(0xffffffffu, rm0, 1));
        rm0 = fmaxf(rm0, __shfl_xor_sync(0xffffffffu, rm0, 2));
        rm1 = fmaxf(rm1, __shfl_xor_sync(0xffffffffu, rm1, 1));
        rm1 = fmaxf(rm1, __shfl_xor_sync(0xffffffffu, rm1, 2));
        float mn0 = fmaxf(m0, rm0), mn1 = fmaxf(m1, rm1);
        float al0 = __expf(m0 - mn0), al1 = __expf(m1 - mn1);
        m0 = mn0; m1 = mn1;
        float rs0 = 0.f, rs1 = 0.f;
#pragma unroll
        for (int j = 0; j < 8; j++) {
            s[j][0] = __expf(s[j][0] - m0); rs0 += s[j][0];
            s[j][1] = __expf(s[j][1] - m0); rs0 += s[j][1];
            s[j][2] = __expf(s[j][2] - m1); rs1 += s[j][2];
            s[j][3] = __expf(s[j][3] - m1); rs1 += s[j][3];
        }
        rs0 += __shfl_xor_sync(0xffffffffu, rs0, 1);
        rs0 += __shfl_xor_sync(0xffffffffu, rs0, 2);
        rs1 += __shfl_xor_sync(0xffffffffu, rs1, 1);
        rs1 += __shfl_xor_sync(0xffffffffu, rs1, 2);
        l0 = l0 * al0 + rs0;
        l1 = l1 * al1 + rs1;
#pragma unroll
        for (int n = 0; n < 8; n++) {
            o[n][0] *= al0; o[n][1] *= al0; o[n][2] *= al1; o[n][3] *= al1;
        }

        // ---- O += P V (B-frags via ldmatrix.trans) ----
#pragma unroll
        for (int ka = 0; ka < 4; ka++) {
            const int j0 = 2 * ka, j1 = 2 * ka + 1;
            uint32_t ph[4], pl[4];
            {
                bf16 h00, h01, h02, h03, h10, h11, h12, h13;
                bf16 e00, e01, e02, e03, e10, e11, e12, e13;
                split2(s[j0][0], h00, e00); split2(s[j0][1], h01, e01);
                split2(s[j0][2], h02, e02); split2(s[j0][3], h03, e03);
                split2(s[j1][0], h10, e10); split2(s[j1][1], h11, e11);
                split2(s[j1][2], h12, e12); split2(s[j1][3], h13, e13);
                ph[0] = packbf(h00, h01); ph[1] = packbf(h02, h03);
                ph[2] = packbf(h10, h11); ph[3] = packbf(h12, h13);
                pl[0] = packbf(e00, e01); pl[1] = packbf(e02, e03);
                pl[2] = packbf(e10, e11); pl[3] = packbf(e12, e13);
            }
            const uint32_t ksl = (uint32_t)(ka * 16 * SSTR * 2);
#pragma unroll
            for (int n = 0; n < 8; n++) {
                uint32_t b0h, b1h, b0l, b1l;
                ldsm_x2_t(b0h, b1h, vhb + ksl + 16 * n);
                ldsm_x2_t(b0l, b1l, vlb + ksl + 16 * n);
                mma16816(o[n], ph, b0h, b1h);
                mma16816(o[n], pl, b0h, b1h);
                mma16816(o[n], ph, b0l, b1l);
            }
        }
        __syncthreads();
    }

    // ---- virtual tile: masked keys, all with score exactly 1e-9 ----
    float w0c = 0.f, w1c = 0.f, lf0 = l0, lf1 = l1;
    if (cnt0 > 0) {
        float mf0 = fmaxf(m0, 1e-9f);
        float mf1 = fmaxf(m1, 1e-9f);
        float sc0 = __expf(m0 - mf0);
        float sc1 = __expf(m1 - mf1);
        w0c = __expf(1e-9f - mf0);
        w1c = __expf(1e-9f - mf1);
        lf0 = l0 * sc0 + (float)cnt0 * w0c;
        lf1 = l1 * sc1 + (float)cnt0 * w1c;
#pragma unroll
        for (int n = 0; n < 8; n++) {
            o[n][0] *= sc0; o[n][1] *= sc0; o[n][2] *= sc1; o[n][3] *= sc1;
        }
    }

    // ---- epilogue: masked-V correction, normalize, split-store ----
    float inv0 = 1.f / lf0, inv1 = 1.f / lf1;
    int qr = q0 + 16 * w + g;
#pragma unroll
    for (int n = 0; n < 8; n++) {
        int col = cb + 8 * n + 2 * tig;
        float sv0 = sv[b * CDIM + col];
        float sv1 = sv[b * CDIM + col + 1];
        float a0 = (o[n][0] + w0c * sv0) * inv0;
        float a1 = (o[n][1] + w0c * sv1) * inv0;
        float a2 = (o[n][2] + w1c * sv0) * inv1;
        float a3 = (o[n][3] + w1c * sv1) * inv1;
        bf16 h0, h1, h2, h3, e0, e1, e2, e3;
        split2(a0, h0, e0); split2(a1, h1, e1);
        split2(a2, h2, e2); split2(a3, h3, e3);
        *(uint32_t*)&OH[(size_t)(b * CN + qr) * CDIM + col]     = packbf(h0, h1);
        *(uint32_t*)&OL[(size_t)(b * CN + qr) * CDIM + col]     = packbf(e0, e1);
        *(uint32_t*)&OH[(size_t)(b * CN + qr + 8) * CDIM + col] = packbf(h2, h3);
        *(uint32_t*)&OL[(size_t)(b * CN + qr + 8) * CDIM + col] = packbf(e2, e3);
    }
}

// ---------------------------------------------------------------------------
extern "C" void kernel_launch(void* const* d_in, const int* in_sizes, int n_in,
                              void* d_out, int out_size)
{
    const float* x    = (const float*)d_in[0];
    const int*   mask = (const int*)  d_in[1];
    const float* W[4] = { (const float*)d_in[2], (const float*)d_in[3],
                          (const float*)d_in[4], (const float*)d_in[5] };
    float* out = (float*)d_out;

    bf16 *xh, *xl, *qh, *ql, *kh, *kl, *vh, *vl, *oh, *ol, *wh, *wl;
    int *idxl, *cnt;
    float *sv, *xm;
    cudaGetSymbolAddress((void**)&xh, g_xhi);
    cudaGetSymbolAddress((void**)&xl, g_xlo);
    cudaGetSymbolAddress((void**)&qh, g_qh);
    cudaGetSymbolAddress((void**)&ql, g_ql);
    cudaGetSymbolAddress((void**)&kh, g_kh);
    cudaGetSymbolAddress((void**)&kl, g_kl);
    cudaGetSymbolAddress((void**)&vh, g_vh);
    cudaGetSymbolAddress((void**)&vl, g_vl);
    cudaGetSymbolAddress((void**)&oh, g_ohi);
    cudaGetSymbolAddress((void**)&ol, g_olo);
    cudaGetSymbolAddress((void**)&wh, g_wh);
    cudaGetSymbolAddress((void**)&wl, g_wl);
    cudaGetSymbolAddress((void**)&idxl, g_idx);
    cudaGetSymbolAddress((void**)&cnt, g_cnt);
    cudaGetSymbolAddress((void**)&sv, g_sv);
    cudaGetSymbolAddress((void**)&xm, g_xm);

    const int M  = CB * CN;            // 8192
    const int NX = M * CDIM;
    const int NW = CDIM * CDIM;

    split_kernel<<<NX / 4 / 256, 256>>>(x, xh, xl, NX);
    for (int w = 0; w < 4; w++)
        split_kernel<<<NW / 4 / 256, 256>>>(W[w], wh + (size_t)w * NW, wl + (size_t)w * NW, NW);
    scan_kernel<<<CB, 256>>>(mask, idxl, cnt, xm);
    xmsum_kernel<<<dim3(CDIM / 128, CB, 8), 128>>>(x, mask, xm);
    gemv_sv_kernel<<<dim3(CDIM / 128, CB), 128>>>(W[2], xm, sv);

    const int gsm  = 2 * STAGE_B;
    const int asmb = (2 * 4 * 64 + 128) * SSTR * (int)sizeof(bf16);
    cudaFuncSetAttribute(q_gemm_kernel,  cudaFuncAttributeMaxDynamicSharedMemorySize, gsm);
    cudaFuncSetAttribute(kv_gemm_kernel, cudaFuncAttributeMaxDynamicSharedMemorySize, gsm);
    cudaFuncSetAttribute(out_gemm_kernel, cudaFuncAttributeMaxDynamicSharedMemorySize, gsm);
    cudaFuncSetAttribute(attn_mma_kernel, cudaFuncAttributeMaxDynamicSharedMemorySize, asmb);

    q_gemm_kernel<<<dim3(4, M / 128), 256, gsm>>>(
        xh, xl, wh + 0 * (size_t)NW, wl + 0 * (size_t)NW, qh, ql);

    kv_gemm_kernel<<<dim3(8, CB * 16), 256, gsm>>>(
        xh, xl,
        wh + 1 * (size_t)NW, wl + 1 * (size_t)NW,
        wh + 2 * (size_t)NW, wl + 2 * (size_t)NW,
        idxl, cnt, kh, kl, vh, vl);

    attn_mma_kernel<<<dim3(CN / 128, CH * CB), 256, asmb>>>(
        qh, ql, kh, kl, vh, vl, cnt, sv, oh, ol);

    out_gemm_kernel<<<dim3(4, M / 128), 256, gsm>>>(
        oh, ol, wh + 3 * (size_t)NW, wl + 3 * (size_t)NW, out);
}

// round 9
// speedup vs baseline: 1.8829x; 1.1216x over previous
#include <cuda_runtime.h>
#include <cuda_bf16.h>
#include <cstdint>

#define CB   4
#define CN   2048
#define CH   8
#define CDH  64
#define CDIM 512
#define ATT_SCALE 0.125f
#define SSTR 72            // smem row stride in bf16 (64 data + 8 pad) = 144B

typedef __nv_bfloat16 bf16;

// ---------------- scratch (__device__ globals; no allocation allowed) -------
__device__ bf16 g_xhi[CB * CN * CDIM];
__device__ bf16 g_xlo[CB * CN * CDIM];
__device__ bf16 g_qh[CB * CN * CDIM];
__device__ bf16 g_ql[CB * CN * CDIM];
__device__ bf16 g_kh[CB * CN * CDIM];   // compacted K rows
__device__ bf16 g_kl[CB * CN * CDIM];
__device__ bf16 g_vh[CB * CN * CDIM];   // compacted V rows
__device__ bf16 g_vl[CB * CN * CDIM];
__device__ bf16 g_ohi[CB * CN * CDIM];
__device__ bf16 g_olo[CB * CN * CDIM];
__device__ bf16 g_wh[4][CDIM * CDIM];
__device__ bf16 g_wl[4][CDIM * CDIM];
__device__ int  g_idx[CB * CN];
__device__ int  g_cnt[CB];
__device__ float g_sv[CB * CDIM];       // Wv * (sum of masked x)  (exact fp32)
__device__ float g_xm[CB * CDIM];       // sum of x over masked keys

// ---------------- helpers ----------------------------------------------------
__device__ __forceinline__ void mma16816(float* c, const uint32_t* a, uint32_t b0, uint32_t b1) {
    asm volatile(
        "mma.sync.aligned.m16n8k16.row.col.f32.bf16.bf16.f32 "
        "{%0,%1,%2,%3}, {%4,%5,%6,%7}, {%8,%9}, {%0,%1,%2,%3};\n"
        : "+f"(c[0]), "+f"(c[1]), "+f"(c[2]), "+f"(c[3])
        : "r"(a[0]), "r"(a[1]), "r"(a[2]), "r"(a[3]), "r"(b0), "r"(b1));
}
__device__ __forceinline__ void ldsm_x2_t(uint32_t& r0, uint32_t& r1, uint32_t saddr) {
    asm volatile("ldmatrix.sync.aligned.m8n8.x2.trans.shared.b16 {%0,%1}, [%2];"
                 : "=r"(r0), "=r"(r1) : "r"(saddr));
}
__device__ __forceinline__ uint32_t packbf(bf16 x, bf16 y) {
    __nv_bfloat162 t = __halves2bfloat162(x, y);
    return *reinterpret_cast<uint32_t*>(&t);
}
__device__ __forceinline__ uint32_t smem_u32(const void* p) {
    uint32_t a;
    asm("{ .reg .u64 t; cvta.to.shared.u64 t, %1; cvt.u32.u64 %0, t; }" : "=r"(a) : "l"(p));
    return a;
}
__device__ __forceinline__ void cp_async16(uint32_t saddr, const void* g) {
    asm volatile("cp.async.cg.shared.global [%0], [%1], 16;" :: "r"(saddr), "l"(g));
}
__device__ __forceinline__ void cp_commit() { asm volatile("cp.async.commit_group;"); }
template<int N> __device__ __forceinline__ void cp_wait() {
    asm volatile("cp.async.wait_group %0;" :: "n"(N));
}
__device__ __forceinline__ void split2(float v, bf16& h, bf16& l) {
    h = __float2bfloat16(v);
    l = __float2bfloat16(v - __bfloat162float(h));
}
__device__ __forceinline__ void split4_store(const float* __restrict__ src,
                                             bf16* __restrict__ hi, bf16* __restrict__ lo)
{
    float4 v = *(const float4*)src;
    bf16 h0, h1, h2, h3, l0, l1, l2, l3;
    split2(v.x, h0, l0); split2(v.y, h1, l1);
    split2(v.z, h2, l2); split2(v.w, h3, l3);
    *(uint32_t*)(hi)     = packbf(h0, h1);
    *(uint32_t*)(hi + 2) = packbf(h2, h3);
    *(uint32_t*)(lo)     = packbf(l0, l1);
    *(uint32_t*)(lo + 2) = packbf(l2, l3);
}

// ---------------- fused fp32 -> bf16 hi/lo split (x + all 4 weights) ---------
__global__ void split_all_kernel(const float* __restrict__ x,
                                 const float* __restrict__ w0, const float* __restrict__ w1,
                                 const float* __restrict__ w2, const float* __restrict__ w3,
                                 bf16* __restrict__ xh, bf16* __restrict__ xl,
                                 bf16* __restrict__ wh, bf16* __restrict__ wl)
{
    const int NXc = CB * CN * CDIM;
    const int NWc = CDIM * CDIM;
    int i = (blockIdx.x * blockDim.x + threadIdx.x) * 4;
    if (i < NXc) {
        split4_store(x + i, xh + i, xl + i);
    } else {
        int j = i - NXc;
        if (j >= 4 * NWc) return;
        int w = j / NWc, o = j - w * NWc;
        const float* src = (w == 0) ? w0 : (w == 1) ? w1 : (w == 2) ? w2 : w3;
        split4_store(src + o, wh + (size_t)w * NWc + o, wl + (size_t)w * NWc + o);
    }
}

// ---------------- mask scan: compact unmasked key list -----------------------
__global__ void scan_kernel(const int* __restrict__ mask,
                            int* __restrict__ idxl, int* __restrict__ cnt,
                            float* __restrict__ xm)
{
    __shared__ int ps[256];
    const int b = blockIdx.x, t = threadIdx.x;
    xm[b * CDIM + t]       = 0.f;
    xm[b * CDIM + 256 + t] = 0.f;
    int loc[8], c = 0;
#pragma unroll
    for (int i = 0; i < 8; i++) {
        loc[i] = c;
        c += (mask[b * CN + t * 8 + i] != 0);
    }
    ps[t] = c;
    __syncthreads();
    for (int off = 1; off < 256; off <<= 1) {
        int v = (t >= off) ? ps[t - off] : 0;
        __syncthreads();
        ps[t] += v;
        __syncthreads();
    }
    int excl = ps[t] - c;
#pragma unroll
    for (int i = 0; i < 8; i++)
        if (mask[b * CN + t * 8 + i] != 0)
            idxl[b * CN + excl + loc[i]] = t * 8 + i;
    if (t == 255) cnt[b] = ps[255];
}

// ---------------- masked-x column sums ---------------------------------------
__global__ void xmsum_kernel(const float* __restrict__ x, const int* __restrict__ mask,
                             float* __restrict__ xm)
{
    const int c  = blockIdx.x * 128 + threadIdx.x;
    const int b  = blockIdx.y;
    const int r0 = blockIdx.z * 256;
    float s = 0.f;
#pragma unroll 4
    for (int i = 0; i < 256; i++) {
        int t = r0 + i;
        if (mask[b * CN + t] == 0)
            s += x[(size_t)(b * CN + t) * CDIM + c];
    }
    atomicAdd(&xm[b * CDIM + c], s);
}

// ---------------- sv = Wv * xm (warp-per-output GEMV) ------------------------
__global__ void gemv_sv_kernel(const float* __restrict__ Wv, const float* __restrict__ xm,
                               float* __restrict__ sv)
{
    const int warp = threadIdx.x >> 5, lane = threadIdx.x & 31;
    const int n = blockIdx.x * 8 + warp;
    const int b = blockIdx.y;
    const float* wr = Wv + (size_t)n * CDIM;
    const float* xr = xm + b * CDIM;
    float s = 0.f;
#pragma unroll
    for (int c = lane * 4; c < CDIM; c += 128) {
        float4 wv = *(const float4*)(wr + c);
        float4 xv = *(const float4*)(xr + c);
        s += wv.x * xv.x + wv.y * xv.y + wv.z * xv.z + wv.w * xv.w;
    }
    s += __shfl_xor_sync(0xffffffffu, s, 16);
    s += __shfl_xor_sync(0xffffffffu, s, 8);
    s += __shfl_xor_sync(0xffffffffu, s, 4);
    s += __shfl_xor_sync(0xffffffffu, s, 2);
    s += __shfl_xor_sync(0xffffffffu, s, 1);
    if (lane == 0) sv[b * CDIM + n] = s;
}

// ---------------- GEMM mainloop (shared via macro) ---------------------------
#define TEN_B   (128 * SSTR * 2)
#define STAGE_B (4 * TEN_B)

#define GEMM_LOAD_CHUNK(st, kc)                                                   \
    {                                                                             \
        _Pragma("unroll")                                                         \
        for (int i = 0; i < 4; i++) {                                             \
            int idx = tid + 256 * i;                                              \
            int r = idx >> 3, u = idx & 7;                                        \
            uint32_t so = sbase + (uint32_t)((st) * STAGE_B + (r * SSTR + 8 * u) * 2); \
            cp_async16(so + 0 * TEN_B, Ah_g + (size_t)(rowBase + r) * CDIM + (kc) + 8 * u); \
            cp_async16(so + 1 * TEN_B, Al_g + (size_t)(rowBase + r) * CDIM + (kc) + 8 * u); \
            cp_async16(so + 2 * TEN_B, Bh_g + (size_t)(colBase + r) * CDIM + (kc) + 8 * u); \
            cp_async16(so + 3 * TEN_B, Bl_g + (size_t)(colBase + r) * CDIM + (kc) + 8 * u); \
        }                                                                         \
        cp_commit();                                                              \
    }

#define KV_LOAD_CHUNK(st, kc)                                                     \
    {                                                                             \
        _Pragma("unroll")                                                         \
        for (int i = 0; i < 4; i++) {                                             \
            int idx = tid + 256 * i;                                              \
            int r = idx >> 3, u = idx & 7;                                        \
            uint32_t so = sbase + (uint32_t)((st) * STAGE_B + (r * SSTR + 8 * u) * 2); \
            cp_async16(so + 0 * TEN_B, Ah_g + (size_t)(b * CN + toks[i]) * CDIM + (kc) + 8 * u); \
            cp_async16(so + 1 * TEN_B, Al_g + (size_t)(b * CN + toks[i]) * CDIM + (kc) + 8 * u); \
            cp_async16(so + 2 * TEN_B, Bh_g + (size_t)(colBase + r) * CDIM + (kc) + 8 * u); \
            cp_async16(so + 3 * TEN_B, Bl_g + (size_t)(colBase + r) * CDIM + (kc) + 8 * u); \
        }                                                                         \
        cp_commit();                                                              \
    }

#define GEMM_COMPUTE_CHUNK(st)                                                    \
    {                                                                             \
        const bf16* Ah = gs + (st) * 4 * 128 * SSTR;                              \
        const bf16* Al = Ah + 128 * SSTR;                                         \
        const bf16* Bh = Al + 128 * SSTR;                                         \
        const bf16* Bl = Bh + 128 * SSTR;                                         \
        _Pragma("unroll")                                                         \
        for (int ka = 0; ka < 4; ka++) {                                          \
            const int ko = 16 * ka + 2 * tig;                                     \
            uint32_t a_h[2][4], a_l[2][4];                                        \
            _Pragma("unroll")                                                     \
            for (int m = 0; m < 2; m++) {                                         \
                int rb = 32 * wM + 16 * m;                                        \
                a_h[m][0] = *(const uint32_t*)&Ah[(rb + g)     * SSTR + ko];      \
                a_h[m][1] = *(const uint32_t*)&Ah[(rb + g + 8) * SSTR + ko];      \
                a_h[m][2] = *(const uint32_t*)&Ah[(rb + g)     * SSTR + ko + 8];  \
                a_h[m][3] = *(const uint32_t*)&Ah[(rb + g + 8) * SSTR + ko + 8];  \
                a_l[m][0] = *(const uint32_t*)&Al[(rb + g)     * SSTR + ko];      \
                a_l[m][1] = *(const uint32_t*)&Al[(rb + g + 8) * SSTR + ko];      \
                a_l[m][2] = *(const uint32_t*)&Al[(rb + g)     * SSTR + ko + 8];  \
                a_l[m][3] = *(const uint32_t*)&Al[(rb + g + 8) * SSTR + ko + 8];  \
            }                                                                     \
            _Pragma("unroll")                                                     \
            for (int j = 0; j < 8; j++) {                                         \
                int cr = 64 * wN + 8 * j + g;                                     \
                uint32_t b0h = *(const uint32_t*)&Bh[cr * SSTR + ko];             \
                uint32_t b1h = *(const uint32_t*)&Bh[cr * SSTR + ko + 8];         \
                uint32_t b0l = *(const uint32_t*)&Bl[cr * SSTR + ko];             \
                uint32_t b1l = *(const uint32_t*)&Bl[cr * SSTR + ko + 8];         \
                _Pragma("unroll")                                                 \
                for (int m = 0; m < 2; m++) {                                     \
                    mma16816(acc[m][j], a_h[m], b0h, b1h);                        \
                    mma16816(acc[m][j], a_h[m], b0l, b1l);                        \
                    mma16816(acc[m][j], a_l[m], b0h, b1h);                        \
                }                                                                 \
            }                                                                     \
        }                                                                         \
    }

#define GEMM_PREAMBLE()                                                           \
    const int tid  = threadIdx.x;                                                 \
    const int w    = tid >> 5;                                                    \
    const int lane = tid & 31;                                                    \
    const int g    = lane >> 2;                                                   \
    const int tig  = lane & 3;                                                    \
    const int wM   = w >> 1;                                                      \
    const int wN   = w & 1;                                                       \
    float acc[2][8][4];                                                           \
    _Pragma("unroll")                                                             \
    for (int m = 0; m < 2; m++)                                                   \
        _Pragma("unroll")                                                         \
        for (int j = 0; j < 8; j++)                                               \
            _Pragma("unroll")                                                     \
            for (int t = 0; t < 4; t++) acc[m][j][t] = 0.f;

#define GEMM_MAINLOOP(LOADM)                                                      \
    LOADM(0, 0)                                                                   \
    _Pragma("unroll 1")                                                           \
    for (int ch = 0; ch < 8; ch++) {                                              \
        if (ch + 1 < 8) LOADM((ch + 1) & 1, 64 * (ch + 1))                        \
        if (ch + 1 < 8) cp_wait<1>(); else cp_wait<0>();                          \
        __syncthreads();                                                          \
        GEMM_COMPUTE_CHUNK(ch & 1)                                                \
        __syncthreads();                                                          \
    }

#define GEMM_EPI_SPLIT(outH, outL, rowB, scale)                                   \
    _Pragma("unroll")                                                             \
    for (int m = 0; m < 2; m++)                                                   \
        _Pragma("unroll")                                                         \
        for (int j = 0; j < 8; j++) {                                             \
            int row = (rowB) + 32 * wM + 16 * m + g;                              \
            int col = colBase + 64 * wN + 8 * j + 2 * tig;                        \
            bf16 h0, h1, h2, h3, l0, l1, l2, l3;                                  \
            split2(acc[m][j][0] * (scale), h0, l0);                               \
            split2(acc[m][j][1] * (scale), h1, l1);                               \
            split2(acc[m][j][2] * (scale), h2, l2);                               \
            split2(acc[m][j][3] * (scale), h3, l3);                               \
            *(uint32_t*)&(outH)[(size_t)row * CDIM + col]       = packbf(h0, h1); \
            *(uint32_t*)&(outL)[(size_t)row * CDIM + col]       = packbf(l0, l1); \
            *(uint32_t*)&(outH)[(size_t)(row + 8) * CDIM + col] = packbf(h2, h3); \
            *(uint32_t*)&(outL)[(size_t)(row + 8) * CDIM + col] = packbf(l2, l3); \
        }

// ---------------- fused Q + compacted-K/V projection -------------------------
// grid.x in [0,12): 0..3 -> Q tiles (colBase=x*128); 4..11 -> KV (wsel,col).
// grid.y = 64: Q -> rowBase = y*128 ; KV -> b = y>>4, tile = y&15.
__global__ __launch_bounds__(256, 1) void proj_gemm_kernel(
    const bf16* __restrict__ Ah_g, const bf16* __restrict__ Al_g,
    const bf16* __restrict__ wqh, const bf16* __restrict__ wql,
    const bf16* __restrict__ wkh, const bf16* __restrict__ wkl,
    const bf16* __restrict__ wvh, const bf16* __restrict__ wvl,
    const int* __restrict__ idxl, const int* __restrict__ cntp,
    bf16* __restrict__ q_h, bf16* __restrict__ q_l,
    bf16* __restrict__ kch, bf16* __restrict__ kcl,
    bf16* __restrict__ vch, bf16* __restrict__ vcl)
{
    extern __shared__ bf16 gs[];
    const uint32_t sbase = smem_u32(gs);

    if (blockIdx.x < 4) {
        // ---- Q projection over full rows ----
        const int colBase = blockIdx.x * 128;
        const int rowBase = blockIdx.y * 128;
        const bf16* Bh_g = wqh;
        const bf16* Bl_g = wql;
        GEMM_PREAMBLE()
        GEMM_MAINLOOP(GEMM_LOAD_CHUNK)
        GEMM_EPI_SPLIT(q_h, q_l, rowBase, ATT_SCALE)
    } else {
        // ---- K/V projection over compacted rows ----
        const int xx      = blockIdx.x - 4;
        const int wsel    = xx >> 2;
        const int colBase = (xx & 3) * 128;
        const int b       = blockIdx.y >> 4;
        const int tile    = blockIdx.y & 15;
        const int cnt1    = cntp[b];
        const int kend    = (cnt1 + 63) & ~63;
        if (tile * 128 >= kend) return;
        const int* bidx = idxl + b * CN;
        const bf16* Bh_g = wsel ? wvh : wkh;
        const bf16* Bl_g = wsel ? wvl : wkl;
        bf16* outH = wsel ? vch : kch;
        bf16* outL = wsel ? vcl : kcl;

        GEMM_PREAMBLE()

        int toks[4];
#pragma unroll
        for (int i = 0; i < 4; i++) {
            int r = (tid + 256 * i) >> 3;
            int jj = tile * 128 + r;
            toks[i] = bidx[jj < cnt1 ? jj : cnt1 - 1];
        }

        GEMM_MAINLOOP(KV_LOAD_CHUNK)

        const int rowB = b * CN + tile * 128;
        GEMM_EPI_SPLIT(outH, outL, rowB, 1.0f)
    }
}

// ---------------- output projection (fp32 out) -------------------------------
__global__ __launch_bounds__(256, 1) void out_gemm_kernel(
    const bf16* __restrict__ Ah_g, const bf16* __restrict__ Al_g,
    const bf16* __restrict__ Bh_g, const bf16* __restrict__ Bl_g,
    float* __restrict__ C)
{
    extern __shared__ bf16 gs[];
    const uint32_t sbase = smem_u32(gs);
    const int colBase = blockIdx.x * 128;
    const int rowBase = blockIdx.y * 128;

    GEMM_PREAMBLE()
    GEMM_MAINLOOP(GEMM_LOAD_CHUNK)

#pragma unroll
    for (int m = 0; m < 2; m++)
#pragma unroll
        for (int j = 0; j < 8; j++) {
            int row = rowBase + 32 * wM + 16 * m + g;
            int col = colBase + 64 * wN + 8 * j + 2 * tig;
            *(float2*)&C[(size_t)row * CDIM + col]       = make_float2(acc[m][j][0], acc[m][j][1]);
            *(float2*)&C[(size_t)(row + 8) * CDIM + col] = make_float2(acc[m][j][2], acc[m][j][3]);
        }
}

// ---------------- flash attention over compacted (contiguous) keys -----------
#define ATEN (64 * SSTR)
#define ASTG (4 * ATEN)

__global__ __launch_bounds__(256, 1) void attn_mma_kernel(
    const bf16* __restrict__ qh_g, const bf16* __restrict__ ql_g,
    const bf16* __restrict__ kh_g, const bf16* __restrict__ kl_g,
    const bf16* __restrict__ vh_g, const bf16* __restrict__ vl_g,
    const int* __restrict__ cntp, const float* __restrict__ sv,
    bf16* __restrict__ OH, bf16* __restrict__ OL)
{
    extern __shared__ bf16 sm[];       // [2 stages][4 tensors][64*SSTR] + Q staging
    bf16* Qs = sm + 2 * ASTG;

    const uint32_t sbase = smem_u32(sm);
    const int tid  = threadIdx.x;
    const int w    = tid >> 5;
    const int lane = tid & 31;
    const int g    = lane >> 2;
    const int tig  = lane & 3;
    const int q0   = blockIdx.x * 128;
    const int h    = blockIdx.y & 7;
    const int b    = blockIdx.y >> 3;
    const int cb   = h * CDH;

    const int cnt1 = cntp[b];
    const int cnt0 = CN - cnt1;
    const int nt   = (cnt1 + 63) >> 6;

    const uint32_t lrow = (uint32_t)(lane & 15) * SSTR * 2;

    // ---- preload Q fragments (hi then lo via shared staging) ----
    uint32_t qfh[4][4], qfl[4][4];
#pragma unroll
    for (int pass = 0; pass < 2; pass++) {
        const bf16* src = pass ? ql_g : qh_g;
#pragma unroll
        for (int i = 0; i < 4; i++) {
            int idx = tid + 256 * i;
            int r = idx >> 3, u = idx & 7;
            *(uint4*)&Qs[r * SSTR + 8 * u] =
                *((const uint4*)(src + (size_t)(b * CN + q0 + r) * CDIM + cb) + u);
        }
        __syncthreads();
        uint32_t (*dst)[4] = pass ? qfl : qfh;
#pragma unroll
        for (int ka = 0; ka < 4; ka++) {
            int rb = 16 * w;
            int ko = 16 * ka + 2 * tig;
            dst[ka][0] = *(const uint32_t*)&Qs[(rb + g)     * SSTR + ko];
            dst[ka][1] = *(const uint32_t*)&Qs[(rb + g + 8) * SSTR + ko];
            dst[ka][2] = *(const uint32_t*)&Qs[(rb + g)     * SSTR + ko + 8];
            dst[ka][3] = *(const uint32_t*)&Qs[(rb + g + 8) * SSTR + ko + 8];
        }
        __syncthreads();
    }

    float o[8][4];
#pragma unroll
    for (int n = 0; n < 8; n++)
#pragma unroll
        for (int t = 0; t < 4; t++) o[n][t] = 0.f;
    float m0 = -1e30f, m1 = -1e30f, l0 = 0.f, l1 = 0.f;

#define ATT_LOAD(st, kb_)                                                          \
    {                                                                              \
        _Pragma("unroll")                                                          \
        for (int i = 0; i < 2; i++) {                                              \
            int idx = tid + 256 * i;          /* 0..511 */                         \
            int r = idx >> 3, u = idx & 7;                                         \
            size_t grow = (size_t)(b * CN + (kb_) + r) * CDIM + cb + 8 * u;        \
            uint32_t so = sbase + (uint32_t)(((st) * ASTG + r * SSTR + 8 * u) * 2);\
            cp_async16(so + 0 * ATEN * 2, kh_g + grow);                            \
            cp_async16(so + 1 * ATEN * 2, kl_g + grow);                            \
            cp_async16(so + 2 * ATEN * 2, vh_g + grow);                            \
            cp_async16(so + 3 * ATEN * 2, vl_g + grow);                            \
        }                                                                          \
        cp_commit();                                                               \
    }

    if (nt > 0) ATT_LOAD(0, 0)

#pragma unroll 1
    for (int it = 0; it < nt; it++) {
        const int kb = it * 64;
        const int st = it & 1;
        if (it + 1 < nt) ATT_LOAD((it + 1) & 1, kb + 64)
        if (it + 1 < nt) cp_wait<1>(); else cp_wait<0>();
        __syncthreads();

        const bf16* Kh = sm + st * ASTG;
        const bf16* Kl = Kh + ATEN;
        const uint32_t vhb = sbase + (uint32_t)((st * ASTG + 2 * ATEN) * 2) + lrow;
        const uint32_t vlb = vhb + (uint32_t)(ATEN * 2);

        // ---- S = Q K^T (3-pass split) ----
        float s[8][4];
#pragma unroll
        for (int j = 0; j < 8; j++)
#pragma unroll
            for (int t = 0; t < 4; t++) s[j][t] = 0.f;
#pragma unroll
        for (int ka = 0; ka < 4; ka++) {
            const int ko = 16 * ka + 2 * tig;
#pragma unroll
            for (int j = 0; j < 8; j++) {
                int kr = 8 * j + g;
                uint32_t b0h = *(const uint32_t*)&Kh[kr * SSTR + ko];
                uint32_t b1h = *(const uint32_t*)&Kh[kr * SSTR + ko + 8];
                uint32_t b0l = *(const uint32_t*)&Kl[kr * SSTR + ko];
                uint32_t b1l = *(const uint32_t*)&Kl[kr * SSTR + ko + 8];
                mma16816(s[j], qfh[ka], b0h, b1h);
                mma16816(s[j], qfh[ka], b0l, b1l);
                mma16816(s[j], qfl[ka], b0h, b1h);
            }
        }

        // ---- tail exclusion for padding keys (exact: weight 0) ----
        if (kb + 64 > cnt1) {
#pragma unroll
            for (int j = 0; j < 8; j++) {
                int kc0 = kb + 8 * j + 2 * tig;
                if (kc0     >= cnt1) { s[j][0] = -1e30f; s[j][2] = -1e30f; }
                if (kc0 + 1 >= cnt1) { s[j][1] = -1e30f; s[j][3] = -1e30f; }
            }
        }

        // ---- online softmax ----
        float rm0 = -1e30f, rm1 = -1e30f;
#pragma unroll
        for (int j = 0; j < 8; j++) {
            rm0 = fmaxf(rm0, fmaxf(s[j][0], s[j][1]));
            rm1 = fmaxf(rm1, fmaxf(s[j][2], s[j][3]));
        }
        rm0 = fmaxf(rm0, __shfl_xor_sync(0xffffffffu, rm0, 1));
        rm0 = fmaxf(rm0, __shfl_xor_sync(0xffffffffu, rm0, 2));
        rm1 = fmaxf(rm1, __shfl_xor_sync(0xffffffffu, rm1, 1));
        rm1 = fmaxf(rm1, __shfl_xor_sync(0xffffffffu, rm1, 2));
        float mn0 = fmaxf(m0, rm0), mn1 = fmaxf(m1, rm1);
        float al0 = __expf(m0 - mn0), al1 = __expf(m1 - mn1);
        m0 = mn0; m1 = mn1;
        float rs0 = 0.f, rs1 = 0.f;
#pragma unroll
        for (int j = 0; j < 8; j++) {
            s[j][0] = __expf(s[j][0] - m0); rs0 += s[j][0];
            s[j][1] = __expf(s[j][1] - m0); rs0 += s[j][1];
            s[j][2] = __expf(s[j][2] - m1); rs1 += s[j][2];
            s[j][3] = __expf(s[j][3] - m1); rs1 += s[j][3];
        }
        rs0 += __shfl_xor_sync(0xffffffffu, rs0, 1);
        rs0 += __shfl_xor_sync(0xffffffffu, rs0, 2);
        rs1 += __shfl_xor_sync(0xffffffffu, rs1, 1);
        rs1 += __shfl_xor_sync(0xffffffffu, rs1, 2);
        l0 = l0 * al0 + rs0;
        l1 = l1 * al1 + rs1;
#pragma unroll
        for (int n = 0; n < 8; n++) {
            o[n][0] *= al0; o[n][1] *= al0; o[n][2] *= al1; o[n][3] *= al1;
        }

        // ---- O += P V (B-frags via ldmatrix.trans) ----
#pragma unroll
        for (int ka = 0; ka < 4; ka++) {
            const int j0 = 2 * ka, j1 = 2 * ka + 1;
            uint32_t ph[4], pl[4];
            {
                bf16 h00, h01, h02, h03, h10, h11, h12, h13;
                bf16 e00, e01, e02, e03, e10, e11, e12, e13;
                split2(s[j0][0], h00, e00); split2(s[j0][1], h01, e01);
                split2(s[j0][2], h02, e02); split2(s[j0][3], h03, e03);
                split2(s[j1][0], h10, e10); split2(s[j1][1], h11, e11);
                split2(s[j1][2], h12, e12); split2(s[j1][3], h13, e13);
                ph[0] = packbf(h00, h01); ph[1] = packbf(h02, h03);
                ph[2] = packbf(h10, h11); ph[3] = packbf(h12, h13);
                pl[0] = packbf(e00, e01); pl[1] = packbf(e02, e03);
                pl[2] = packbf(e10, e11); pl[3] = packbf(e12, e13);
            }
            const uint32_t ksl = (uint32_t)(ka * 16 * SSTR * 2);
#pragma unroll
            for (int n = 0; n < 8; n++) {
                uint32_t b0h, b1h, b0l, b1l;
                ldsm_x2_t(b0h, b1h, vhb + ksl + 16 * n);
                ldsm_x2_t(b0l, b1l, vlb + ksl + 16 * n);
                mma16816(o[n], ph, b0h, b1h);
                mma16816(o[n], pl, b0h, b1h);
                mma16816(o[n], ph, b0l, b1l);
            }
        }
        __syncthreads();
    }

    // ---- virtual tile: masked keys, all with score exactly 1e-9 ----
    float w0c = 0.f, w1c = 0.f, lf0 = l0, lf1 = l1;
    if (cnt0 > 0) {
        float mf0 = fmaxf(m0, 1e-9f);
        float mf1 = fmaxf(m1, 1e-9f);
        float sc0 = __expf(m0 - mf0);
        float sc1 = __expf(m1 - mf1);
        w0c = __expf(1e-9f - mf0);
        w1c = __expf(1e-9f - mf1);
        lf0 = l0 * sc0 + (float)cnt0 * w0c;
        lf1 = l1 * sc1 + (float)cnt0 * w1c;
#pragma unroll
        for (int n = 0; n < 8; n++) {
            o[n][0] *= sc0; o[n][1] *= sc0; o[n][2] *= sc1; o[n][3] *= sc1;
        }
    }

    // ---- epilogue: masked-V correction, normalize, split-store ----
    float inv0 = 1.f / lf0, inv1 = 1.f / lf1;
    int qr = q0 + 16 * w + g;
#pragma unroll
    for (int n = 0; n < 8; n++) {
        int col = cb + 8 * n + 2 * tig;
        float sv0 = sv[b * CDIM + col];
        float sv1 = sv[b * CDIM + col + 1];
        float a0 = (o[n][0] + w0c * sv0) * inv0;
        float a1 = (o[n][1] + w0c * sv1) * inv0;
        float a2 = (o[n][2] + w1c * sv0) * inv1;
        float a3 = (o[n][3] + w1c * sv1) * inv1;
        bf16 h0, h1, h2, h3, e0, e1, e2, e3;
        split2(a0, h0, e0); split2(a1, h1, e1);
        split2(a2, h2, e2); split2(a3, h3, e3);
        *(uint32_t*)&OH[(size_t)(b * CN + qr) * CDIM + col]     = packbf(h0, h1);
        *(uint32_t*)&OL[(size_t)(b * CN + qr) * CDIM + col]     = packbf(e0, e1);
        *(uint32_t*)&OH[(size_t)(b * CN + qr + 8) * CDIM + col] = packbf(h2, h3);
        *(uint32_t*)&OL[(size_t)(b * CN + qr + 8) * CDIM + col] = packbf(e2, e3);
    }
}

// ---------------------------------------------------------------------------
extern "C" void kernel_launch(void* const* d_in, const int* in_sizes, int n_in,
                              void* d_out, int out_size)
{
    const float* x    = (const float*)d_in[0];
    const int*   mask = (const int*)  d_in[1];
    const float* W[4] = { (const float*)d_in[2], (const float*)d_in[3],
                          (const float*)d_in[4], (const float*)d_in[5] };
    float* out = (float*)d_out;

    bf16 *xh, *xl, *qh, *ql, *kh, *kl, *vh, *vl, *oh, *ol, *wh, *wl;
    int *idxl, *cnt;
    float *sv, *xm;
    cudaGetSymbolAddress((void**)&xh, g_xhi);
    cudaGetSymbolAddress((void**)&xl, g_xlo);
    cudaGetSymbolAddress((void**)&qh, g_qh);
    cudaGetSymbolAddress((void**)&ql, g_ql);
    cudaGetSymbolAddress((void**)&kh, g_kh);
    cudaGetSymbolAddress((void**)&kl, g_kl);
    cudaGetSymbolAddress((void**)&vh, g_vh);
    cudaGetSymbolAddress((void**)&vl, g_vl);
    cudaGetSymbolAddress((void**)&oh, g_ohi);
    cudaGetSymbolAddress((void**)&ol, g_olo);
    cudaGetSymbolAddress((void**)&wh, g_wh);
    cudaGetSymbolAddress((void**)&wl, g_wl);
    cudaGetSymbolAddress((void**)&idxl, g_idx);
    cudaGetSymbolAddress((void**)&cnt, g_cnt);
    cudaGetSymbolAddress((void**)&sv, g_sv);
    cudaGetSymbolAddress((void**)&xm, g_xm);

    const int M  = CB * CN;            // 8192
    const int NX = M * CDIM;
    const int NW = CDIM * CDIM;
    const int NTOT = NX + 4 * NW;      // 5,242,880

    split_all_kernel<<<NTOT / 4 / 256, 256>>>(x, W[0], W[1], W[2], W[3], xh, xl, wh, wl);
    scan_kernel<<<CB, 256>>>(mask, idxl, cnt, xm);
    xmsum_kernel<<<dim3(CDIM / 128, CB, 8), 128>>>(x, mask, xm);
    gemv_sv_kernel<<<dim3(CDIM / 8, CB), 256>>>(W[2], xm, sv);

    const int gsm  = 2 * STAGE_B;
    const int asmb = (2 * 4 * 64 + 128) * SSTR * (int)sizeof(bf16);
    cudaFuncSetAttribute(proj_gemm_kernel, cudaFuncAttributeMaxDynamicSharedMemorySize, gsm);
    cudaFuncSetAttribute(out_gemm_kernel, cudaFuncAttributeMaxDynamicSharedMemorySize, gsm);
    cudaFuncSetAttribute(attn_mma_kernel, cudaFuncAttributeMaxDynamicSharedMemorySize, asmb);

    proj_gemm_kernel<<<dim3(12, 64), 256, gsm>>>(
        xh, xl,
        wh + 0 * (size_t)NW, wl + 0 * (size_t)NW,
        wh + 1 * (size_t)NW, wl + 1 * (size_t)NW,
        wh + 2 * (size_t)NW, wl + 2 * (size_t)NW,
        idxl, cnt, qh, ql, kh, kl, vh, vl);

    attn_mma_kernel<<<dim3(CN / 128, CH * CB), 256, asmb>>>(
        qh, ql, kh, kl, vh, vl, cnt, sv, oh, ol);

    out_gemm_kernel<<<dim3(4, M / 128), 256, gsm>>>(
        oh, ol, wh + 3 * (size_t)NW, wl + 3 * (size_t)NW, out);
}

// round 11
// speedup vs baseline: 2.3999x; 1.2746x over previous
#include <cuda_runtime.h>
#include <cuda_fp16.h>
#include <cstdint>

#define CB   4
#define CN   2048
#define CH   8
#define CDH  64
#define CDIM 512
#define ATT_SCALE 0.125f
#define SSTR 72            // smem row stride in fp16 (64 data + 8 pad) = 144B

typedef __half h16;

// ---------------- scratch (__device__ globals; no allocation allowed) -------
__device__ h16 g_xh[CB * CN * CDIM];
__device__ h16 g_xl[CB * CN * CDIM];
__device__ h16 g_qh[CB * CN * CDIM];
__device__ h16 g_ql[CB * CN * CDIM];
__device__ h16 g_kh[CB * CN * CDIM];    // compacted K rows (hi/lo)
__device__ h16 g_kl[CB * CN * CDIM];
__device__ h16 g_vf[CB * CN * CDIM];    // compacted V rows (single fp16)
__device__ h16 g_oh[CB * CN * CDIM];
__device__ h16 g_ol[CB * CN * CDIM];
__device__ h16 g_wf[4][CDIM * CDIM];    // weights, single fp16
__device__ int  g_idx[CB * CN];
__device__ int  g_cnt[CB];
__device__ float g_sv[CB * CDIM];       // Wv * (sum of masked x)  (exact fp32)
__device__ float g_xm[CB * CDIM];       // sum of x over masked keys

// ---------------- helpers ----------------------------------------------------
__device__ __forceinline__ void mma16816(float* c, const uint32_t* a, uint32_t b0, uint32_t b1) {
    asm volatile(
        "mma.sync.aligned.m16n8k16.row.col.f32.f16.f16.f32 "
        "{%0,%1,%2,%3}, {%4,%5,%6,%7}, {%8,%9}, {%0,%1,%2,%3};\n"
        : "+f"(c[0]), "+f"(c[1]), "+f"(c[2]), "+f"(c[3])
        : "r"(a[0]), "r"(a[1]), "r"(a[2]), "r"(a[3]), "r"(b0), "r"(b1));
}
__device__ __forceinline__ void ldsm_x2_t(uint32_t& r0, uint32_t& r1, uint32_t saddr) {
    asm volatile("ldmatrix.sync.aligned.m8n8.x2.trans.shared.b16 {%0,%1}, [%2];"
                 : "=r"(r0), "=r"(r1) : "r"(saddr));
}
__device__ __forceinline__ uint32_t packh(h16 x, h16 y) {
    __half2 t = __halves2half2(x, y);
    return *reinterpret_cast<uint32_t*>(&t);
}
__device__ __forceinline__ uint32_t smem_u32(const void* p) {
    uint32_t a;
    asm("{ .reg .u64 t; cvta.to.shared.u64 t, %1; cvt.u32.u64 %0, t; }" : "=r"(a) : "l"(p));
    return a;
}
__device__ __forceinline__ void cp_async16(uint32_t saddr, const void* g) {
    asm volatile("cp.async.cg.shared.global [%0], [%1], 16;" :: "r"(saddr), "l"(g));
}
__device__ __forceinline__ void cp_commit() { asm volatile("cp.async.commit_group;"); }
template<int N> __device__ __forceinline__ void cp_wait() {
    asm volatile("cp.async.wait_group %0;" :: "n"(N));
}
__device__ __forceinline__ void split2h(float v, h16& h, h16& l) {
    h = __float2half_rn(v);
    l = __float2half_rn(v - __half2float(h));
}

// ---------------- fused prep: split x, round weights -------------------------
__global__ void split_all_kernel(const float* __restrict__ x,
                                 const float* __restrict__ w0, const float* __restrict__ w1,
                                 const float* __restrict__ w2, const float* __restrict__ w3,
                                 h16* __restrict__ xh, h16* __restrict__ xl,
                                 h16* __restrict__ wf)
{
    const int NXc = CB * CN * CDIM;
    const int NWc = CDIM * CDIM;
    int i = (blockIdx.x * blockDim.x + threadIdx.x) * 4;
    if (i < NXc) {
        float4 v = *(const float4*)(x + i);
        h16 h0, h1, h2, h3, l0, l1, l2, l3;
        split2h(v.x, h0, l0); split2h(v.y, h1, l1);
        split2h(v.z, h2, l2); split2h(v.w, h3, l3);
        *(uint32_t*)(xh + i)     = packh(h0, h1);
        *(uint32_t*)(xh + i + 2) = packh(h2, h3);
        *(uint32_t*)(xl + i)     = packh(l0, l1);
        *(uint32_t*)(xl + i + 2) = packh(l2, l3);
    } else {
        int j = i - NXc;
        if (j >= 4 * NWc) return;
        int w = j / NWc, o = j - w * NWc;
        const float* src = (w == 0) ? w0 : (w == 1) ? w1 : (w == 2) ? w2 : w3;
        float4 v = *(const float4*)(src + o);
        h16* dst = wf + (size_t)w * NWc + o;
        *(uint32_t*)(dst)     = packh(__float2half_rn(v.x), __float2half_rn(v.y));
        *(uint32_t*)(dst + 2) = packh(__float2half_rn(v.z), __float2half_rn(v.w));
    }
}

// ---------------- mask scan: compact unmasked key list -----------------------
__global__ void scan_kernel(const int* __restrict__ mask,
                            int* __restrict__ idxl, int* __restrict__ cnt,
                            float* __restrict__ xm)
{
    __shared__ int ps[256];
    const int b = blockIdx.x, t = threadIdx.x;
    xm[b * CDIM + t]       = 0.f;
    xm[b * CDIM + 256 + t] = 0.f;
    int loc[8], c = 0;
#pragma unroll
    for (int i = 0; i < 8; i++) {
        loc[i] = c;
        c += (mask[b * CN + t * 8 + i] != 0);
    }
    ps[t] = c;
    __syncthreads();
    for (int off = 1; off < 256; off <<= 1) {
        int v = (t >= off) ? ps[t - off] : 0;
        __syncthreads();
        ps[t] += v;
        __syncthreads();
    }
    int excl = ps[t] - c;
#pragma unroll
    for (int i = 0; i < 8; i++)
        if (mask[b * CN + t * 8 + i] != 0)
            idxl[b * CN + excl + loc[i]] = t * 8 + i;
    if (t == 255) cnt[b] = ps[255];
}

// ---------------- masked-x column sums ---------------------------------------
__global__ void xmsum_kernel(const float* __restrict__ x, const int* __restrict__ mask,
                             float* __restrict__ xm)
{
    const int c  = blockIdx.x * 128 + threadIdx.x;
    const int b  = blockIdx.y;
    const int r0 = blockIdx.z * 256;
    float s = 0.f;
#pragma unroll 4
    for (int i = 0; i < 256; i++) {
        int t = r0 + i;
        if (mask[b * CN + t] == 0)
            s += x[(size_t)(b * CN + t) * CDIM + c];
    }
    atomicAdd(&xm[b * CDIM + c], s);
}

// ---------------- sv = Wv * xm (warp-per-output GEMV) ------------------------
__global__ void gemv_sv_kernel(const float* __restrict__ Wv, const float* __restrict__ xm,
                               float* __restrict__ sv)
{
    const int warp = threadIdx.x >> 5, lane = threadIdx.x & 31;
    const int n = blockIdx.x * 8 + warp;
    const int b = blockIdx.y;
    const float* wr = Wv + (size_t)n * CDIM;
    const float* xr = xm + b * CDIM;
    float s = 0.f;
#pragma unroll
    for (int c = lane * 4; c < CDIM; c += 128) {
        float4 wv = *(const float4*)(wr + c);
        float4 xv = *(const float4*)(xr + c);
        s += wv.x * xv.x + wv.y * xv.y + wv.z * xv.z + wv.w * xv.w;
    }
    s += __shfl_xor_sync(0xffffffffu, s, 16);
    s += __shfl_xor_sync(0xffffffffu, s, 8);
    s += __shfl_xor_sync(0xffffffffu, s, 4);
    s += __shfl_xor_sync(0xffffffffu, s, 2);
    s += __shfl_xor_sync(0xffffffffu, s, 1);
    if (lane == 0) sv[b * CDIM + n] = s;
}

// ---------------- GEMM mainloop: A split (hi/lo), B single fp16 --------------
#define TEN_B   (128 * SSTR * 2)
#define STAGE_B (3 * TEN_B)

#define GEMM_LOAD_CHUNK(st, kc)                                                   \
    {                                                                             \
        _Pragma("unroll")                                                         \
        for (int i = 0; i < 4; i++) {                                             \
            int idx = tid + 256 * i;                                              \
            int r = idx >> 3, u = idx & 7;                                        \
            uint32_t so = sbase + (uint32_t)((st) * STAGE_B + (r * SSTR + 8 * u) * 2); \
            cp_async16(so + 0 * TEN_B, Ah_g + (size_t)(rowBase + r) * CDIM + (kc) + 8 * u); \
            cp_async16(so + 1 * TEN_B, Al_g + (size_t)(rowBase + r) * CDIM + (kc) + 8 * u); \
            cp_async16(so + 2 * TEN_B, Bf_g + (size_t)(colBase + r) * CDIM + (kc) + 8 * u); \
        }                                                                         \
        cp_commit();                                                              \
    }

#define KV_LOAD_CHUNK(st, kc)                                                     \
    {                                                                             \
        _Pragma("unroll")                                                         \
        for (int i = 0; i < 4; i++) {                                             \
            int idx = tid + 256 * i;                                              \
            int r = idx >> 3, u = idx & 7;                                        \
            uint32_t so = sbase + (uint32_t)((st) * STAGE_B + (r * SSTR + 8 * u) * 2); \
            cp_async16(so + 0 * TEN_B, Ah_g + (size_t)(b * CN + toks[i]) * CDIM + (kc) + 8 * u); \
            cp_async16(so + 1 * TEN_B, Al_g + (size_t)(b * CN + toks[i]) * CDIM + (kc) + 8 * u); \
            cp_async16(so + 2 * TEN_B, Bf_g + (size_t)(colBase + r) * CDIM + (kc) + 8 * u); \
        }                                                                         \
        cp_commit();                                                              \
    }

#define GEMM_COMPUTE_CHUNK(st)                                                    \
    {                                                                             \
        const h16* Ah = gs + (st) * 3 * 128 * SSTR;                               \
        const h16* Al = Ah + 128 * SSTR;                                          \
        const h16* Bf = Al + 128 * SSTR;                                          \
        _Pragma("unroll")                                                         \
        for (int ka = 0; ka < 4; ka++) {                                          \
            const int ko = 16 * ka + 2 * tig;                                     \
            uint32_t a_h[2][4], a_l[2][4];                                        \
            _Pragma("unroll")                                                     \
            for (int m = 0; m < 2; m++) {                                         \
                int rb = 32 * wM + 16 * m;                                        \
                a_h[m][0] = *(const uint32_t*)&Ah[(rb + g)     * SSTR + ko];      \
                a_h[m][1] = *(const uint32_t*)&Ah[(rb + g + 8) * SSTR + ko];      \
                a_h[m][2] = *(const uint32_t*)&Ah[(rb + g)     * SSTR + ko + 8];  \
                a_h[m][3] = *(const uint32_t*)&Ah[(rb + g + 8) * SSTR + ko + 8];  \
                a_l[m][0] = *(const uint32_t*)&Al[(rb + g)     * SSTR + ko];      \
                a_l[m][1] = *(const uint32_t*)&Al[(rb + g + 8) * SSTR + ko];      \
                a_l[m][2] = *(const uint32_t*)&Al[(rb + g)     * SSTR + ko + 8];  \
                a_l[m][3] = *(const uint32_t*)&Al[(rb + g + 8) * SSTR + ko + 8];  \
            }                                                                     \
            _Pragma("unroll")                                                     \
            for (int j = 0; j < 8; j++) {                                         \
                int cr = 64 * wN + 8 * j + g;                                     \
                uint32_t b0 = *(const uint32_t*)&Bf[cr * SSTR + ko];              \
                uint32_t b1 = *(const uint32_t*)&Bf[cr * SSTR + ko + 8];          \
                _Pragma("unroll")                                                 \
                for (int m = 0; m < 2; m++) {                                     \
                    mma16816(acc[m][j], a_h[m], b0, b1);                          \
                    mma16816(acc[m][j], a_l[m], b0, b1);                          \
                }                                                                 \
            }                                                                     \
        }                                                                         \
    }

#define GEMM_PREAMBLE()                                                           \
    const int tid  = threadIdx.x;                                                 \
    const int w    = tid >> 5;                                                    \
    const int lane = tid & 31;                                                    \
    const int g    = lane >> 2;                                                   \
    const int tig  = lane & 3;                                                    \
    const int wM   = w >> 1;                                                      \
    const int wN   = w & 1;                                                       \
    float acc[2][8][4];                                                           \
    _Pragma("unroll")                                                             \
    for (int m = 0; m < 2; m++)                                                   \
        _Pragma("unroll")                                                         \
        for (int j = 0; j < 8; j++)                                               \
            _Pragma("unroll")                                                     \
            for (int t = 0; t < 4; t++) acc[m][j][t] = 0.f;

#define GEMM_MAINLOOP(LOADM)                                                      \
    LOADM(0, 0)                                                                   \
    _Pragma("unroll 1")                                                           \
    for (int ch = 0; ch < 8; ch++) {                                              \
        if (ch + 1 < 8) LOADM((ch + 1) & 1, 64 * (ch + 1))                        \
        if (ch + 1 < 8) cp_wait<1>(); else cp_wait<0>();                          \
        __syncthreads();                                                          \
        GEMM_COMPUTE_CHUNK(ch & 1)                                                \
        __syncthreads();                                                          \
    }

#define GEMM_EPI_SPLIT(outH, outL, rowB, scale)                                   \
    _Pragma("unroll")                                                             \
    for (int m = 0; m < 2; m++)                                                   \
        _Pragma("unroll")                                                         \
        for (int j = 0; j < 8; j++) {                                             \
            int row = (rowB) + 32 * wM + 16 * m + g;                              \
            int col = colBase + 64 * wN + 8 * j + 2 * tig;                        \
            h16 h0, h1, h2, h3, l0, l1, l2, l3;                                   \
            split2h(acc[m][j][0] * (scale), h0, l0);                              \
            split2h(acc[m][j][1] * (scale), h1, l1);                              \
            split2h(acc[m][j][2] * (scale), h2, l2);                              \
            split2h(acc[m][j][3] * (scale), h3, l3);                              \
            *(uint32_t*)&(outH)[(size_t)row * CDIM + col]       = packh(h0, h1);  \
            *(uint32_t*)&(outL)[(size_t)row * CDIM + col]       = packh(l0, l1);  \
            *(uint32_t*)&(outH)[(size_t)(row + 8) * CDIM + col] = packh(h2, h3);  \
            *(uint32_t*)&(outL)[(size_t)(row + 8) * CDIM + col] = packh(l2, l3);  \
        }

#define GEMM_EPI_SINGLE(outF, rowB)                                               \
    _Pragma("unroll")                                                             \
    for (int m = 0; m < 2; m++)                                                   \
        _Pragma("unroll")                                                         \
        for (int j = 0; j < 8; j++) {                                             \
            int row = (rowB) + 32 * wM + 16 * m + g;                              \
            int col = colBase + 64 * wN + 8 * j + 2 * tig;                        \
            *(uint32_t*)&(outF)[(size_t)row * CDIM + col] =                       \
                packh(__float2half_rn(acc[m][j][0]), __float2half_rn(acc[m][j][1])); \
            *(uint32_t*)&(outF)[(size_t)(row + 8) * CDIM + col] =                 \
                packh(__float2half_rn(acc[m][j][2]), __float2half_rn(acc[m][j][3])); \
        }

// ---------------- fused Q + compacted-K/V projection -------------------------
// grid.x in [0,12): 0..3 -> Q; 4..7 -> K (compact); 8..11 -> V (compact).
__global__ __launch_bounds__(256, 2) void proj_gemm_kernel(
    const h16* __restrict__ Ah_g, const h16* __restrict__ Al_g,
    const h16* __restrict__ wq, const h16* __restrict__ wk, const h16* __restrict__ wv,
    const int* __restrict__ idxl, const int* __restrict__ cntp,
    h16* __restrict__ q_h, h16* __restrict__ q_l,
    h16* __restrict__ kch, h16* __restrict__ kcl,
    h16* __restrict__ vcf)
{
    extern __shared__ h16 gs[];
    const uint32_t sbase = smem_u32(gs);

    if (blockIdx.x < 4) {
        const int colBase = blockIdx.x * 128;
        const int rowBase = blockIdx.y * 128;
        const h16* Bf_g = wq;
        GEMM_PREAMBLE()
        GEMM_MAINLOOP(GEMM_LOAD_CHUNK)
        GEMM_EPI_SPLIT(q_h, q_l, rowBase, ATT_SCALE)
    } else {
        const int xx      = blockIdx.x - 4;
        const int wsel    = xx >> 2;                 // 0 = K, 1 = V
        const int colBase = (xx & 3) * 128;
        const int b       = blockIdx.y >> 4;
        const int tile    = blockIdx.y & 15;
        const int cnt1    = cntp[b];
        const int kend    = (cnt1 + 63) & ~63;
        if (tile * 128 >= kend) return;
        const int* bidx = idxl + b * CN;
        const h16* Bf_g = wsel ? wv : wk;

        GEMM_PREAMBLE()

        int toks[4];
#pragma unroll
        for (int i = 0; i < 4; i++) {
            int r = (tid + 256 * i) >> 3;
            int jj = tile * 128 + r;
            toks[i] = bidx[jj < cnt1 ? jj : cnt1 - 1];
        }

        GEMM_MAINLOOP(KV_LOAD_CHUNK)

        const int rowB = b * CN + tile * 128;
        if (wsel == 0) {
            GEMM_EPI_SPLIT(kch, kcl, rowB, 1.0f)
        } else {
            GEMM_EPI_SINGLE(vcf, rowB)
        }
    }
}

// ---------------- output projection (fp32 out) -------------------------------
__global__ __launch_bounds__(256, 2) void out_gemm_kernel(
    const h16* __restrict__ Ah_g, const h16* __restrict__ Al_g,
    const h16* __restrict__ Bf_g, float* __restrict__ C)
{
    extern __shared__ h16 gs[];
    const uint32_t sbase = smem_u32(gs);
    const int colBase = blockIdx.x * 128;
    const int rowBase = blockIdx.y * 128;

    GEMM_PREAMBLE()
    GEMM_MAINLOOP(GEMM_LOAD_CHUNK)

#pragma unroll
    for (int m = 0; m < 2; m++)
#pragma unroll
        for (int j = 0; j < 8; j++) {
            int row = rowBase + 32 * wM + 16 * m + g;
            int col = colBase + 64 * wN + 8 * j + 2 * tig;
            *(float2*)&C[(size_t)row * CDIM + col]       = make_float2(acc[m][j][0], acc[m][j][1]);
            *(float2*)&C[(size_t)(row + 8) * CDIM + col] = make_float2(acc[m][j][2], acc[m][j][3]);
        }
}

// ---------------- flash attention: QK 3-pass, PV 2-pass ----------------------
#define ATEN (64 * SSTR)
#define ASTG (3 * ATEN)                 // kh, kl, vf

__global__ __launch_bounds__(256, 2) void attn_mma_kernel(
    const h16* __restrict__ qh_g, const h16* __restrict__ ql_g,
    const h16* __restrict__ kh_g, const h16* __restrict__ kl_g,
    const h16* __restrict__ vf_g,
    const int* __restrict__ cntp, const float* __restrict__ sv,
    h16* __restrict__ OH, h16* __restrict__ OL)
{
    extern __shared__ h16 sm[];        // [2 stages][3 tensors][64*SSTR] + Q staging
    h16* Qs = sm + 2 * ASTG;

    const uint32_t sbase = smem_u32(sm);
    const int tid  = threadIdx.x;
    const int w    = tid >> 5;
    const int lane = tid & 31;
    const int g    = lane >> 2;
    const int tig  = lane & 3;
    const int q0   = blockIdx.x * 128;
    const int h    = blockIdx.y & 7;
    const int b    = blockIdx.y >> 3;
    const int cb   = h * CDH;

    const int cnt1 = cntp[b];
    const int cnt0 = CN - cnt1;
    const int nt   = (cnt1 + 63) >> 6;

    const uint32_t lrow = (uint32_t)(lane & 15) * SSTR * 2;

    // ---- preload Q fragments (hi then lo via shared staging) ----
    uint32_t qfh[4][4], qfl[4][4];
#pragma unroll
    for (int pass = 0; pass < 2; pass++) {
        const h16* src = pass ? ql_g : qh_g;
#pragma unroll
        for (int i = 0; i < 4; i++) {
            int idx = tid + 256 * i;
            int r = idx >> 3, u = idx & 7;
            *(uint4*)&Qs[r * SSTR + 8 * u] =
                *((const uint4*)(src + (size_t)(b * CN + q0 + r) * CDIM + cb) + u);
        }
        __syncthreads();
        uint32_t (*dst)[4] = pass ? qfl : qfh;
#pragma unroll
        for (int ka = 0; ka < 4; ka++) {
            int rb = 16 * w;
            int ko = 16 * ka + 2 * tig;
            dst[ka][0] = *(const uint32_t*)&Qs[(rb + g)     * SSTR + ko];
            dst[ka][1] = *(const uint32_t*)&Qs[(rb + g + 8) * SSTR + ko];
            dst[ka][2] = *(const uint32_t*)&Qs[(rb + g)     * SSTR + ko + 8];
            dst[ka][3] = *(const uint32_t*)&Qs[(rb + g + 8) * SSTR + ko + 8];
        }
        __syncthreads();
    }

    float o[8][4];
#pragma unroll
    for (int n = 0; n < 8; n++)
#pragma unroll
        for (int t = 0; t < 4; t++) o[n][t] = 0.f;
    float m0 = -1e30f, m1 = -1e30f, l0 = 0.f, l1 = 0.f;

#define ATT_LOAD(st, kb_)                                                          \
    {                                                                              \
        _Pragma("unroll")                                                          \
        for (int i = 0; i < 2; i++) {                                              \
            int idx = tid + 256 * i;          /* 0..511 */                         \
            int r = idx >> 3, u = idx & 7;                                         \
            size_t grow = (size_t)(b * CN + (kb_) + r) * CDIM + cb + 8 * u;        \
            uint32_t so = sbase + (uint32_t)(((st) * ASTG + r * SSTR + 8 * u) * 2);\
            cp_async16(so + 0 * ATEN * 2, kh_g + grow);                            \
            cp_async16(so + 1 * ATEN * 2, kl_g + grow);                            \
            cp_async16(so + 2 * ATEN * 2, vf_g + grow);                            \
        }                                                                          \
        cp_commit();                                                               \
    }

    if (nt > 0) ATT_LOAD(0, 0)

#pragma unroll 1
    for (int it = 0; it < nt; it++) {
        const int kb = it * 64;
        const int st = it & 1;
        if (it + 1 < nt) ATT_LOAD((it + 1) & 1, kb + 64)
        if (it + 1 < nt) cp_wait<1>(); else cp_wait<0>();
        __syncthreads();

        const h16* Kh = sm + st * ASTG;
        const h16* Kl = Kh + ATEN;
        const uint32_t vfb = sbase + (uint32_t)((st * ASTG + 2 * ATEN) * 2) + lrow;

        // ---- S = Q K^T (3-pass: Qh*Kh + Qh*Kl + Ql*Kh) ----
        float s[8][4];
#pragma unroll
        for (int j = 0; j < 8; j++)
#pragma unroll
            for (int t = 0; t < 4; t++) s[j][t] = 0.f;
#pragma unroll
        for (int ka = 0; ka < 4; ka++) {
            const int ko = 16 * ka + 2 * tig;
#pragma unroll
            for (int j = 0; j < 8; j++) {
                int kr = 8 * j + g;
                uint32_t b0h = *(const uint32_t*)&Kh[kr * SSTR + ko];
                uint32_t b1h = *(const uint32_t*)&Kh[kr * SSTR + ko + 8];
                uint32_t b0l = *(const uint32_t*)&Kl[kr * SSTR + ko];
                uint32_t b1l = *(const uint32_t*)&Kl[kr * SSTR + ko + 8];
                mma16816(s[j], qfh[ka], b0h, b1h);
                mma16816(s[j], qfh[ka], b0l, b1l);
                mma16816(s[j], qfl[ka], b0h, b1h);
            }
        }

        // ---- tail exclusion for padding keys (exact: weight 0) ----
        if (kb + 64 > cnt1) {
#pragma unroll
            for (int j = 0; j < 8; j++) {
                int kc0 = kb + 8 * j + 2 * tig;
                if (kc0     >= cnt1) { s[j][0] = -1e30f; s[j][2] = -1e30f; }
                if (kc0 + 1 >= cnt1) { s[j][1] = -1e30f; s[j][3] = -1e30f; }
            }
        }

        // ---- online softmax ----
        float rm0 = -1e30f, rm1 = -1e30f;
#pragma unroll
        for (int j = 0; j < 8; j++) {
            rm0 = fmaxf(rm0, fmaxf(s[j][0], s[j][1]));
            rm1 = fmaxf(rm1, fmaxf(s[j][2], s[j][3]));
        }
        rm0 = fmaxf(rm0, __shfl_xor_sync(0xffffffffu, rm0, 1));
        rm0 = fmaxf(rm0, __shfl_xor_sync(0xffffffffu, rm0, 2));
        rm1 = fmaxf(rm1, __shfl_xor_sync(0xffffffffu, rm1, 1));
        rm1 = fmaxf(rm1, __shfl_xor_sync(0xffffffffu, rm1, 2));
        float mn0 = fmaxf(m0, rm0), mn1 = fmaxf(m1, rm1);
        float al0 = __expf(m0 - mn0), al1 = __expf(m1 - mn1);
        m0 = mn0; m1 = mn1;
        float rs0 = 0.f, rs1 = 0.f;
#pragma unroll
        for (int j = 0; j < 8; j++) {
            s[j][0] = __expf(s[j][0] - m0); rs0 += s[j][0];
            s[j][1] = __expf(s[j][1] - m0); rs0 += s[j][1];
            s[j][2] = __expf(s[j][2] - m1); rs1 += s[j][2];
            s[j][3] = __expf(s[j][3] - m1); rs1 += s[j][3];
        }
        rs0 += __shfl_xor_sync(0xffffffffu, rs0, 1);
        rs0 += __shfl_xor_sync(0xffffffffu, rs0, 2);
        rs1 += __shfl_xor_sync(0xffffffffu, rs1, 1);
        rs1 += __shfl_xor_sync(0xffffffffu, rs1, 2);
        l0 = l0 * al0 + rs0;
        l1 = l1 * al1 + rs1;
#pragma unroll
        for (int n = 0; n < 8; n++) {
            o[n][0] *= al0; o[n][1] *= al0; o[n][2] *= al1; o[n][3] *= al1;
        }

        // ---- O += P V (P split exact, V single; 2-pass) ----
#pragma unroll
        for (int ka = 0; ka < 4; ka++) {
            const int j0 = 2 * ka, j1 = 2 * ka + 1;
            uint32_t ph[4], pl[4];
            {
                h16 h00, h01, h02, h03, h10, h11, h12, h13;
                h16 e00, e01, e02, e03, e10, e11, e12, e13;
                split2h(s[j0][0], h00, e00); split2h(s[j0][1], h01, e01);
                split2h(s[j0][2], h02, e02); split2h(s[j0][3], h03, e03);
                split2h(s[j1][0], h10, e10); split2h(s[j1][1], h11, e11);
                split2h(s[j1][2], h12, e12); split2h(s[j1][3], h13, e13);
                ph[0] = packh(h00, h01); ph[1] = packh(h02, h03);
                ph[2] = packh(h10, h11); ph[3] = packh(h12, h13);
                pl[0] = packh(e00, e01); pl[1] = packh(e02, e03);
                pl[2] = packh(e10, e11); pl[3] = packh(e12, e13);
            }
            const uint32_t ksl = (uint32_t)(ka * 16 * SSTR * 2);
#pragma unroll
            for (int n = 0; n < 8; n++) {
                uint32_t b0, b1;
                ldsm_x2_t(b0, b1, vfb + ksl + 16 * n);
                mma16816(o[n], ph, b0, b1);
                mma16816(o[n], pl, b0, b1);
            }
        }
        __syncthreads();
    }

    // ---- virtual tile: masked keys, all with score exactly 1e-9 ----
    float w0c = 0.f, w1c = 0.f, lf0 = l0, lf1 = l1;
    if (cnt0 > 0) {
        float mf0 = fmaxf(m0, 1e-9f);
        float mf1 = fmaxf(m1, 1e-9f);
        float sc0 = __expf(m0 - mf0);
        float sc1 = __expf(m1 - mf1);
        w0c = __expf(1e-9f - mf0);
        w1c = __expf(1e-9f - mf1);
        lf0 = l0 * sc0 + (float)cnt0 * w0c;
        lf1 = l1 * sc1 + (float)cnt0 * w1c;
#pragma unroll
        for (int n = 0; n < 8; n++) {
            o[n][0] *= sc0; o[n][1] *= sc0; o[n][2] *= sc1; o[n][3] *= sc1;
        }
    }

    // ---- epilogue: masked-V correction, normalize, split-store ----
    float inv0 = 1.f / lf0, inv1 = 1.f / lf1;
    int qr = q0 + 16 * w + g;
#pragma unroll
    for (int n = 0; n < 8; n++) {
        int col = cb + 8 * n + 2 * tig;
        float sv0 = sv[b * CDIM + col];
        float sv1 = sv[b * CDIM + col + 1];
        float a0 = (o[n][0] + w0c * sv0) * inv0;
        float a1 = (o[n][1] + w0c * sv1) * inv0;
        float a2 = (o[n][2] + w1c * sv0) * inv1;
        float a3 = (o[n][3] + w1c * sv1) * inv1;
        h16 h0, h1, h2, h3, e0, e1, e2, e3;
        split2h(a0, h0, e0); split2h(a1, h1, e1);
        split2h(a2, h2, e2); split2h(a3, h3, e3);
        *(uint32_t*)&OH[(size_t)(b * CN + qr) * CDIM + col]     = packh(h0, h1);
        *(uint32_t*)&OL[(size_t)(b * CN + qr) * CDIM + col]     = packh(e0, e1);
        *(uint32_t*)&OH[(size_t)(b * CN + qr + 8) * CDIM + col] = packh(h2, h3);
        *(uint32_t*)&OL[(size_t)(b * CN + qr + 8) * CDIM + col] = packh(e2, e3);
    }
}

// ---------------------------------------------------------------------------
extern "C" void kernel_launch(void* const* d_in, const int* in_sizes, int n_in,
                              void* d_out, int out_size)
{
    const float* x    = (const float*)d_in[0];
    const int*   mask = (const int*)  d_in[1];
    const float* W[4] = { (const float*)d_in[2], (const float*)d_in[3],
                          (const float*)d_in[4], (const float*)d_in[5] };
    float* out = (float*)d_out;

    h16 *xh, *xl, *qh, *ql, *kh, *kl, *vf, *oh, *ol, *wf;
    int *idxl, *cnt;
    float *sv, *xm;
    cudaGetSymbolAddress((void**)&xh, g_xh);
    cudaGetSymbolAddress((void**)&xl, g_xl);
    cudaGetSymbolAddress((void**)&qh, g_qh);
    cudaGetSymbolAddress((void**)&ql, g_ql);
    cudaGetSymbolAddress((void**)&kh, g_kh);
    cudaGetSymbolAddress((void**)&kl, g_kl);
    cudaGetSymbolAddress((void**)&vf, g_vf);
    cudaGetSymbolAddress((void**)&oh, g_oh);
    cudaGetSymbolAddress((void**)&ol, g_ol);
    cudaGetSymbolAddress((void**)&wf, g_wf);
    cudaGetSymbolAddress((void**)&idxl, g_idx);
    cudaGetSymbolAddress((void**)&cnt, g_cnt);
    cudaGetSymbolAddress((void**)&sv, g_sv);
    cudaGetSymbolAddress((void**)&xm, g_xm);

    const int M  = CB * CN;            // 8192
    const int NX = M * CDIM;
    const int NW = CDIM * CDIM;
    const int NTOT = NX + 4 * NW;

    split_all_kernel<<<NTOT / 4 / 256, 256>>>(x, W[0], W[1], W[2], W[3], xh, xl, wf);
    scan_kernel<<<CB, 256>>>(mask, idxl, cnt, xm);
    xmsum_kernel<<<dim3(CDIM / 128, CB, 8), 128>>>(x, mask, xm);
    gemv_sv_kernel<<<dim3(CDIM / 8, CB), 256>>>(W[2], xm, sv);

    const int gsm  = 2 * STAGE_B;                                       // 110592 B
    const int asmb = (2 * 3 * 64 + 128) * SSTR * (int)sizeof(h16);      // 73728 B
    cudaFuncSetAttribute(proj_gemm_kernel, cudaFuncAttributeMaxDynamicSharedMemorySize, gsm);
    cudaFuncSetAttribute(out_gemm_kernel, cudaFuncAttributeMaxDynamicSharedMemorySize, gsm);
    cudaFuncSetAttribute(attn_mma_kernel, cudaFuncAttributeMaxDynamicSharedMemorySize, asmb);

    proj_gemm_kernel<<<dim3(12, 64), 256, gsm>>>(
        xh, xl,
        wf + 0 * (size_t)NW, wf + 1 * (size_t)NW, wf + 2 * (size_t)NW,
        idxl, cnt, qh, ql, kh, kl, vf);

    attn_mma_kernel<<<dim3(CN / 128, CH * CB), 256, asmb>>>(
        qh, ql, kh, kl, vf, cnt, sv, oh, ol);

    out_gemm_kernel<<<dim3(4, M / 128), 256, gsm>>>(
        oh, ol, wf + 3 * (size_t)NW, out);
}

// round 12
// speedup vs baseline: 2.8587x; 1.1912x over previous
#include <cuda_runtime.h>
#include <cuda_fp16.h>
#include <cstdint>

#define CB   4
#define CN   2048
#define CH   8
#define CDH  64
#define CDIM 512
#define ATT_SCALE 0.125f
#define SSTR 72            // smem row stride in fp16 (64 data + 8 pad) = 144B

typedef __half h16;

// ---------------- scratch (__device__ globals; no allocation allowed) -------
__device__ h16 g_xh[CB * CN * CDIM];
__device__ h16 g_xl[CB * CN * CDIM];
__device__ h16 g_qh[CB * CN * CDIM];
__device__ h16 g_ql[CB * CN * CDIM];
__device__ h16 g_kf[CB * CN * CDIM];    // compacted K rows (single fp16)
__device__ h16 g_vf[CB * CN * CDIM];    // compacted V rows (single fp16)
__device__ h16 g_oh[CB * CN * CDIM];
__device__ h16 g_ol[CB * CN * CDIM];
__device__ h16 g_wf[4][CDIM * CDIM];    // weights, single fp16
__device__ int  g_idx[CB * CN];
__device__ int  g_cnt[CB];
__device__ float g_sv[CB * CDIM];       // Wv * (sum of masked x)  (exact fp32)
__device__ float g_xm[CB * CDIM];       // sum of x over masked keys

// ---------------- helpers ----------------------------------------------------
__device__ __forceinline__ void mma16816(float* c, const uint32_t* a, uint32_t b0, uint32_t b1) {
    asm volatile(
        "mma.sync.aligned.m16n8k16.row.col.f32.f16.f16.f32 "
        "{%0,%1,%2,%3}, {%4,%5,%6,%7}, {%8,%9}, {%0,%1,%2,%3};\n"
        : "+f"(c[0]), "+f"(c[1]), "+f"(c[2]), "+f"(c[3])
        : "r"(a[0]), "r"(a[1]), "r"(a[2]), "r"(a[3]), "r"(b0), "r"(b1));
}
__device__ __forceinline__ void ldsm_x2_t(uint32_t& r0, uint32_t& r1, uint32_t saddr) {
    asm volatile("ldmatrix.sync.aligned.m8n8.x2.trans.shared.b16 {%0,%1}, [%2];"
                 : "=r"(r0), "=r"(r1) : "r"(saddr));
}
__device__ __forceinline__ uint32_t packh(h16 x, h16 y) {
    __half2 t = __halves2half2(x, y);
    return *reinterpret_cast<uint32_t*>(&t);
}
__device__ __forceinline__ uint32_t smem_u32(const void* p) {
    uint32_t a;
    asm("{ .reg .u64 t; cvta.to.shared.u64 t, %1; cvt.u32.u64 %0, t; }" : "=r"(a) : "l"(p));
    return a;
}
__device__ __forceinline__ void cp_async16(uint32_t saddr, const void* g) {
    asm volatile("cp.async.cg.shared.global [%0], [%1], 16;" :: "r"(saddr), "l"(g));
}
__device__ __forceinline__ void cp_commit() { asm volatile("cp.async.commit_group;"); }
template<int N> __device__ __forceinline__ void cp_wait() {
    asm volatile("cp.async.wait_group %0;" :: "n"(N));
}
__device__ __forceinline__ void split2h(float v, h16& h, h16& l) {
    h = __float2half_rn(v);
    l = __float2half_rn(v - __half2float(h));
}

// ---------------- fused prep: split x, round weights -------------------------
__global__ void split_all_kernel(const float* __restrict__ x,
                                 const float* __restrict__ w0, const float* __restrict__ w1,
                                 const float* __restrict__ w2, const float* __restrict__ w3,
                                 h16* __restrict__ xh, h16* __restrict__ xl,
                                 h16* __restrict__ wf)
{
    const int NXc = CB * CN * CDIM;
    const int NWc = CDIM * CDIM;
    int i = (blockIdx.x * blockDim.x + threadIdx.x) * 4;
    if (i < NXc) {
        float4 v = *(const float4*)(x + i);
        h16 h0, h1, h2, h3, l0, l1, l2, l3;
        split2h(v.x, h0, l0); split2h(v.y, h1, l1);
        split2h(v.z, h2, l2); split2h(v.w, h3, l3);
        *(uint32_t*)(xh + i)     = packh(h0, h1);
        *(uint32_t*)(xh + i + 2) = packh(h2, h3);
        *(uint32_t*)(xl + i)     = packh(l0, l1);
        *(uint32_t*)(xl + i + 2) = packh(l2, l3);
    } else {
        int j = i - NXc;
        if (j >= 4 * NWc) return;
        int w = j / NWc, o = j - w * NWc;
        const float* src = (w == 0) ? w0 : (w == 1) ? w1 : (w == 2) ? w2 : w3;
        float4 v = *(const float4*)(src + o);
        h16* dst = wf + (size_t)w * NWc + o;
        *(uint32_t*)(dst)     = packh(__float2half_rn(v.x), __float2half_rn(v.y));
        *(uint32_t*)(dst + 2) = packh(__float2half_rn(v.z), __float2half_rn(v.w));
    }
}

// ---------------- mask scan: compact unmasked key list -----------------------
__global__ void scan_kernel(const int* __restrict__ mask,
                            int* __restrict__ idxl, int* __restrict__ cnt,
                            float* __restrict__ xm)
{
    __shared__ int ps[256];
    const int b = blockIdx.x, t = threadIdx.x;
    xm[b * CDIM + t]       = 0.f;
    xm[b * CDIM + 256 + t] = 0.f;
    int loc[8], c = 0;
#pragma unroll
    for (int i = 0; i < 8; i++) {
        loc[i] = c;
        c += (mask[b * CN + t * 8 + i] != 0);
    }
    ps[t] = c;
    __syncthreads();
    for (int off = 1; off < 256; off <<= 1) {
        int v = (t >= off) ? ps[t - off] : 0;
        __syncthreads();
        ps[t] += v;
        __syncthreads();
    }
    int excl = ps[t] - c;
#pragma unroll
    for (int i = 0; i < 8; i++)
        if (mask[b * CN + t * 8 + i] != 0)
            idxl[b * CN + excl + loc[i]] = t * 8 + i;
    if (t == 255) cnt[b] = ps[255];
}

// ---------------- masked-x column sums ---------------------------------------
__global__ void xmsum_kernel(const float* __restrict__ x, const int* __restrict__ mask,
                             float* __restrict__ xm)
{
    const int c  = blockIdx.x * 128 + threadIdx.x;
    const int b  = blockIdx.y;
    const int r0 = blockIdx.z * 256;
    float s = 0.f;
#pragma unroll 4
    for (int i = 0; i < 256; i++) {
        int t = r0 + i;
        if (mask[b * CN + t] == 0)
            s += x[(size_t)(b * CN + t) * CDIM + c];
    }
    atomicAdd(&xm[b * CDIM + c], s);
}

// ---------------- sv = Wv * xm (warp-per-output GEMV) ------------------------
__global__ void gemv_sv_kernel(const float* __restrict__ Wv, const float* __restrict__ xm,
                               float* __restrict__ sv)
{
    const int warp = threadIdx.x >> 5, lane = threadIdx.x & 31;
    const int n = blockIdx.x * 8 + warp;
    const int b = blockIdx.y;
    const float* wr = Wv + (size_t)n * CDIM;
    const float* xr = xm + b * CDIM;
    float s = 0.f;
#pragma unroll
    for (int c = lane * 4; c < CDIM; c += 128) {
        float4 wv = *(const float4*)(wr + c);
        float4 xv = *(const float4*)(xr + c);
        s += wv.x * xv.x + wv.y * xv.y + wv.z * xv.z + wv.w * xv.w;
    }
    s += __shfl_xor_sync(0xffffffffu, s, 16);
    s += __shfl_xor_sync(0xffffffffu, s, 8);
    s += __shfl_xor_sync(0xffffffffu, s, 4);
    s += __shfl_xor_sync(0xffffffffu, s, 2);
    s += __shfl_xor_sync(0xffffffffu, s, 1);
    if (lane == 0) sv[b * CDIM + n] = s;
}

// ---------------- GEMM mainloop: A split (hi/lo), B single fp16 --------------
#define TEN_B   (128 * SSTR * 2)
#define STAGE_B (3 * TEN_B)

#define GEMM_LOAD_CHUNK(st, kc)                                                   \
    {                                                                             \
        _Pragma("unroll")                                                         \
        for (int i = 0; i < 4; i++) {                                             \
            int idx = tid + 256 * i;                                              \
            int r = idx >> 3, u = idx & 7;                                        \
            uint32_t so = sbase + (uint32_t)((st) * STAGE_B + (r * SSTR + 8 * u) * 2); \
            cp_async16(so + 0 * TEN_B, Ah_g + (size_t)(rowBase + r) * CDIM + (kc) + 8 * u); \
            cp_async16(so + 1 * TEN_B, Al_g + (size_t)(rowBase + r) * CDIM + (kc) + 8 * u); \
            cp_async16(so + 2 * TEN_B, Bf_g + (size_t)(colBase + r) * CDIM + (kc) + 8 * u); \
        }                                                                         \
        cp_commit();                                                              \
    }

#define KV_LOAD_CHUNK(st, kc)                                                     \
    {                                                                             \
        _Pragma("unroll")                                                         \
        for (int i = 0; i < 4; i++) {                                             \
            int idx = tid + 256 * i;                                              \
            int r = idx >> 3, u = idx & 7;                                        \
            uint32_t so = sbase + (uint32_t)((st) * STAGE_B + (r * SSTR + 8 * u) * 2); \
            cp_async16(so + 0 * TEN_B, Ah_g + (size_t)(b * CN + toks[i]) * CDIM + (kc) + 8 * u); \
            cp_async16(so + 1 * TEN_B, Al_g + (size_t)(b * CN + toks[i]) * CDIM + (kc) + 8 * u); \
            cp_async16(so + 2 * TEN_B, Bf_g + (size_t)(colBase + r) * CDIM + (kc) + 8 * u); \
        }                                                                         \
        cp_commit();                                                              \
    }

#define GEMM_COMPUTE_CHUNK(st)                                                    \
    {                                                                             \
        const h16* Ah = gs + (st) * 3 * 128 * SSTR;                               \
        const h16* Al = Ah + 128 * SSTR;                                          \
        const h16* Bf = Al + 128 * SSTR;                                          \
        _Pragma("unroll")                                                         \
        for (int ka = 0; ka < 4; ka++) {                                          \
            const int ko = 16 * ka + 2 * tig;                                     \
            uint32_t a_h[2][4], a_l[2][4];                                        \
            _Pragma("unroll")                                                     \
            for (int m = 0; m < 2; m++) {                                         \
                int rb = 32 * wM + 16 * m;                                        \
                a_h[m][0] = *(const uint32_t*)&Ah[(rb + g)     * SSTR + ko];      \
                a_h[m][1] = *(const uint32_t*)&Ah[(rb + g + 8) * SSTR + ko];      \
                a_h[m][2] = *(const uint32_t*)&Ah[(rb + g)     * SSTR + ko + 8];  \
                a_h[m][3] = *(const uint32_t*)&Ah[(rb + g + 8) * SSTR + ko + 8];  \
                a_l[m][0] = *(const uint32_t*)&Al[(rb + g)     * SSTR + ko];      \
                a_l[m][1] = *(const uint32_t*)&Al[(rb + g + 8) * SSTR + ko];      \
                a_l[m][2] = *(const uint32_t*)&Al[(rb + g)     * SSTR + ko + 8];  \
                a_l[m][3] = *(const uint32_t*)&Al[(rb + g + 8) * SSTR + ko + 8];  \
            }                                                                     \
            _Pragma("unroll")                                                     \
            for (int j = 0; j < 8; j++) {                                         \
                int cr = 64 * wN + 8 * j + g;                                     \
                uint32_t b0 = *(const uint32_t*)&Bf[cr * SSTR + ko];              \
                uint32_t b1 = *(const uint32_t*)&Bf[cr * SSTR + ko + 8];          \
                _Pragma("unroll")                                                 \
                for (int m = 0; m < 2; m++) {                                     \
                    mma16816(acc[m][j], a_h[m], b0, b1);                          \
                    mma16816(acc[m][j], a_l[m], b0, b1);                          \
                }                                                                 \
            }                                                                     \
        }                                                                         \
    }

#define GEMM_PREAMBLE()                                                           \
    const int tid  = threadIdx.x;                                                 \
    const int w    = tid >> 5;                                                    \
    const int lane = tid & 31;                                                    \
    const int g    = lane >> 2;                                                   \
    const int tig  = lane & 3;                                                    \
    const int wM   = w >> 1;                                                      \
    const int wN   = w & 1;                                                       \
    float acc[2][8][4];                                                           \
    _Pragma("unroll")                                                             \
    for (int m = 0; m < 2; m++)                                                   \
        _Pragma("unroll")                                                         \
        for (int j = 0; j < 8; j++)                                               \
            _Pragma("unroll")                                                     \
            for (int t = 0; t < 4; t++) acc[m][j][t] = 0.f;

#define GEMM_MAINLOOP(LOADM)                                                      \
    LOADM(0, 0)                                                                   \
    _Pragma("unroll 1")                                                           \
    for (int ch = 0; ch < 8; ch++) {                                              \
        if (ch + 1 < 8) LOADM((ch + 1) & 1, 64 * (ch + 1))                        \
        if (ch + 1 < 8) cp_wait<1>(); else cp_wait<0>();                          \
        __syncthreads();                                                          \
        GEMM_COMPUTE_CHUNK(ch & 1)                                                \
        __syncthreads();                                                          \
    }

#define GEMM_EPI_SPLIT(outH, outL, rowB, scale)                                   \
    _Pragma("unroll")                                                             \
    for (int m = 0; m < 2; m++)                                                   \
        _Pragma("unroll")                                                         \
        for (int j = 0; j < 8; j++) {                                             \
            int row = (rowB) + 32 * wM + 16 * m + g;                              \
            int col = colBase + 64 * wN + 8 * j + 2 * tig;                        \
            h16 h0, h1, h2, h3, l0, l1, l2, l3;                                   \
            split2h(acc[m][j][0] * (scale), h0, l0);                              \
            split2h(acc[m][j][1] * (scale), h1, l1);                              \
            split2h(acc[m][j][2] * (scale), h2, l2);                              \
            split2h(acc[m][j][3] * (scale), h3, l3);                              \
            *(uint32_t*)&(outH)[(size_t)row * CDIM + col]       = packh(h0, h1);  \
            *(uint32_t*)&(outL)[(size_t)row * CDIM + col]       = packh(l0, l1);  \
            *(uint32_t*)&(outH)[(size_t)(row + 8) * CDIM + col] = packh(h2, h3);  \
            *(uint32_t*)&(outL)[(size_t)(row + 8) * CDIM + col] = packh(l2, l3);  \
        }

#define GEMM_EPI_SINGLE(outF, rowB)                                               \
    _Pragma("unroll")                                                             \
    for (int m = 0; m < 2; m++)                                                   \
        _Pragma("unroll")                                                         \
        for (int j = 0; j < 8; j++) {                                             \
            int row = (rowB) + 32 * wM + 16 * m + g;                              \
            int col = colBase + 64 * wN + 8 * j + 2 * tig;                        \
            *(uint32_t*)&(outF)[(size_t)row * CDIM + col] =                       \
                packh(__float2half_rn(acc[m][j][0]), __float2half_rn(acc[m][j][1])); \
            *(uint32_t*)&(outF)[(size_t)(row + 8) * CDIM + col] =                 \
                packh(__float2half_rn(acc[m][j][2]), __float2half_rn(acc[m][j][3])); \
        }

// ---------------- fused Q + compacted-K/V projection -------------------------
// grid.x in [0,12): 0..3 -> Q; 4..7 -> K (compact); 8..11 -> V (compact).
__global__ __launch_bounds__(256, 2) void proj_gemm_kernel(
    const h16* __restrict__ Ah_g, const h16* __restrict__ Al_g,
    const h16* __restrict__ wq, const h16* __restrict__ wk, const h16* __restrict__ wv,
    const int* __restrict__ idxl, const int* __restrict__ cntp,
    h16* __restrict__ q_h, h16* __restrict__ q_l,
    h16* __restrict__ kcf, h16* __restrict__ vcf)
{
    extern __shared__ h16 gs[];
    const uint32_t sbase = smem_u32(gs);

    if (blockIdx.x < 4) {
        const int colBase = blockIdx.x * 128;
        const int rowBase = blockIdx.y * 128;
        const h16* Bf_g = wq;
        GEMM_PREAMBLE()
        GEMM_MAINLOOP(GEMM_LOAD_CHUNK)
        GEMM_EPI_SPLIT(q_h, q_l, rowBase, ATT_SCALE)
    } else {
        const int xx      = blockIdx.x - 4;
        const int wsel    = xx >> 2;                 // 0 = K, 1 = V
        const int colBase = (xx & 3) * 128;
        const int b       = blockIdx.y >> 4;
        const int tile    = blockIdx.y & 15;
        const int cnt1    = cntp[b];
        const int kend    = (cnt1 + 63) & ~63;
        if (tile * 128 >= kend) return;
        const int* bidx = idxl + b * CN;
        const h16* Bf_g = wsel ? wv : wk;

        GEMM_PREAMBLE()

        int toks[4];
#pragma unroll
        for (int i = 0; i < 4; i++) {
            int r = (tid + 256 * i) >> 3;
            int jj = tile * 128 + r;
            toks[i] = bidx[jj < cnt1 ? jj : cnt1 - 1];
        }

        GEMM_MAINLOOP(KV_LOAD_CHUNK)

        const int rowB = b * CN + tile * 128;
        if (wsel == 0) {
            GEMM_EPI_SINGLE(kcf, rowB)
        } else {
            GEMM_EPI_SINGLE(vcf, rowB)
        }
    }
}

// ---------------- output projection (fp32 out) -------------------------------
__global__ __launch_bounds__(256, 2) void out_gemm_kernel(
    const h16* __restrict__ Ah_g, const h16* __restrict__ Al_g,
    const h16* __restrict__ Bf_g, float* __restrict__ C)
{
    extern __shared__ h16 gs[];
    const uint32_t sbase = smem_u32(gs);
    const int colBase = blockIdx.x * 128;
    const int rowBase = blockIdx.y * 128;

    GEMM_PREAMBLE()
    GEMM_MAINLOOP(GEMM_LOAD_CHUNK)

#pragma unroll
    for (int m = 0; m < 2; m++)
#pragma unroll
        for (int j = 0; j < 8; j++) {
            int row = rowBase + 32 * wM + 16 * m + g;
            int col = colBase + 64 * wN + 8 * j + 2 * tig;
            *(float2*)&C[(size_t)row * CDIM + col]       = make_float2(acc[m][j][0], acc[m][j][1]);
            *(float2*)&C[(size_t)(row + 8) * CDIM + col] = make_float2(acc[m][j][2], acc[m][j][3]);
        }
}

// ---------------- flash attention: QK 2-pass, PV 1-pass ----------------------
#define ATEN (64 * SSTR)
#define ASTG (2 * ATEN)                 // kf, vf

__global__ __launch_bounds__(256, 2) void attn_mma_kernel(
    const h16* __restrict__ qh_g, const h16* __restrict__ ql_g,
    const h16* __restrict__ kf_g, const h16* __restrict__ vf_g,
    const int* __restrict__ cntp, const float* __restrict__ sv,
    h16* __restrict__ OH, h16* __restrict__ OL)
{
    extern __shared__ h16 sm[];        // [2 stages][2 tensors][64*SSTR] + Q staging
    h16* Qs = sm + 2 * ASTG;

    const uint32_t sbase = smem_u32(sm);
    const int tid  = threadIdx.x;
    const int w    = tid >> 5;
    const int lane = tid & 31;
    const int g    = lane >> 2;
    const int tig  = lane & 3;
    const int q0   = blockIdx.x * 128;
    const int h    = blockIdx.y & 7;
    const int b    = blockIdx.y >> 3;
    const int cb   = h * CDH;

    const int cnt1 = cntp[b];
    const int cnt0 = CN - cnt1;
    const int nt   = (cnt1 + 63) >> 6;

    const uint32_t lrow = (uint32_t)(lane & 15) * SSTR * 2;

    // ---- preload Q fragments (hi then lo via shared staging) ----
    uint32_t qfh[4][4], qfl[4][4];
#pragma unroll
    for (int pass = 0; pass < 2; pass++) {
        const h16* src = pass ? ql_g : qh_g;
#pragma unroll
        for (int i = 0; i < 4; i++) {
            int idx = tid + 256 * i;
            int r = idx >> 3, u = idx & 7;
            *(uint4*)&Qs[r * SSTR + 8 * u] =
                *((const uint4*)(src + (size_t)(b * CN + q0 + r) * CDIM + cb) + u);
        }
        __syncthreads();
        uint32_t (*dst)[4] = pass ? qfl : qfh;
#pragma unroll
        for (int ka = 0; ka < 4; ka++) {
            int rb = 16 * w;
            int ko = 16 * ka + 2 * tig;
            dst[ka][0] = *(const uint32_t*)&Qs[(rb + g)     * SSTR + ko];
            dst[ka][1] = *(const uint32_t*)&Qs[(rb + g + 8) * SSTR + ko];
            dst[ka][2] = *(const uint32_t*)&Qs[(rb + g)     * SSTR + ko + 8];
            dst[ka][3] = *(const uint32_t*)&Qs[(rb + g + 8) * SSTR + ko + 8];
        }
        __syncthreads();
    }

    float o[8][4];
#pragma unroll
    for (int n = 0; n < 8; n++)
#pragma unroll
        for (int t = 0; t < 4; t++) o[n][t] = 0.f;
    float m0 = -1e30f, m1 = -1e30f, l0 = 0.f, l1 = 0.f;

#define ATT_LOAD(st, kb_)                                                          \
    {                                                                              \
        _Pragma("unroll")                                                          \
        for (int i = 0; i < 2; i++) {                                              \
            int idx = tid + 256 * i;          /* 0..511 */                         \
            int r = idx >> 3, u = idx & 7;                                         \
            size_t grow = (size_t)(b * CN + (kb_) + r) * CDIM + cb + 8 * u;        \
            uint32_t so = sbase + (uint32_t)(((st) * ASTG + r * SSTR + 8 * u) * 2);\
            cp_async16(so + 0 * ATEN * 2, kf_g + grow);                            \
            cp_async16(so + 1 * ATEN * 2, vf_g + grow);                            \
        }                                                                          \
        cp_commit();                                                               \
    }

    if (nt > 0) ATT_LOAD(0, 0)

#pragma unroll 1
    for (int it = 0; it < nt; it++) {
        const int kb = it * 64;
        const int st = it & 1;
        if (it + 1 < nt) ATT_LOAD((it + 1) & 1, kb + 64)
        if (it + 1 < nt) cp_wait<1>(); else cp_wait<0>();
        __syncthreads();

        const h16* Kf = sm + st * ASTG;
        const uint32_t vfb = sbase + (uint32_t)((st * ASTG + ATEN) * 2) + lrow;

        // ---- S = Q K^T (2-pass: Qh*K + Ql*K; Q exact, K single) ----
        float s[8][4];
#pragma unroll
        for (int j = 0; j < 8; j++)
#pragma unroll
            for (int t = 0; t < 4; t++) s[j][t] = 0.f;
#pragma unroll
        for (int ka = 0; ka < 4; ka++) {
            const int ko = 16 * ka + 2 * tig;
#pragma unroll
            for (int j = 0; j < 8; j++) {
                int kr = 8 * j + g;
                uint32_t b0 = *(const uint32_t*)&Kf[kr * SSTR + ko];
                uint32_t b1 = *(const uint32_t*)&Kf[kr * SSTR + ko + 8];
                mma16816(s[j], qfh[ka], b0, b1);
                mma16816(s[j], qfl[ka], b0, b1);
            }
        }

        // ---- tail exclusion for padding keys (exact: weight 0) ----
        if (kb + 64 > cnt1) {
#pragma unroll
            for (int j = 0; j < 8; j++) {
                int kc0 = kb + 8 * j + 2 * tig;
                if (kc0     >= cnt1) { s[j][0] = -1e30f; s[j][2] = -1e30f; }
                if (kc0 + 1 >= cnt1) { s[j][1] = -1e30f; s[j][3] = -1e30f; }
            }
        }

        // ---- online softmax ----
        float rm0 = -1e30f, rm1 = -1e30f;
#pragma unroll
        for (int j = 0; j < 8; j++) {
            rm0 = fmaxf(rm0, fmaxf(s[j][0], s[j][1]));
            rm1 = fmaxf(rm1, fmaxf(s[j][2], s[j][3]));
        }
        rm0 = fmaxf(rm0, __shfl_xor_sync(0xffffffffu, rm0, 1));
        rm0 = fmaxf(rm0, __shfl_xor_sync(0xffffffffu, rm0, 2));
        rm1 = fmaxf(rm1, __shfl_xor_sync(0xffffffffu, rm1, 1));
        rm1 = fmaxf(rm1, __shfl_xor_sync(0xffffffffu, rm1, 2));
        float mn0 = fmaxf(m0, rm0), mn1 = fmaxf(m1, rm1);
        float al0 = __expf(m0 - mn0), al1 = __expf(m1 - mn1);
        m0 = mn0; m1 = mn1;
        float rs0 = 0.f, rs1 = 0.f;
#pragma unroll
        for (int j = 0; j < 8; j++) {
            s[j][0] = __expf(s[j][0] - m0); rs0 += s[j][0];
            s[j][1] = __expf(s[j][1] - m0); rs0 += s[j][1];
            s[j][2] = __expf(s[j][2] - m1); rs1 += s[j][2];
            s[j][3] = __expf(s[j][3] - m1); rs1 += s[j][3];
        }
        rs0 += __shfl_xor_sync(0xffffffffu, rs0, 1);
        rs0 += __shfl_xor_sync(0xffffffffu, rs0, 2);
        rs1 += __shfl_xor_sync(0xffffffffu, rs1, 1);
        rs1 += __shfl_xor_sync(0xffffffffu, rs1, 2);
        l0 = l0 * al0 + rs0;
        l1 = l1 * al1 + rs1;
#pragma unroll
        for (int n = 0; n < 8; n++) {
            o[n][0] *= al0; o[n][1] *= al0; o[n][2] *= al1; o[n][3] *= al1;
        }

        // ---- O += P V (P single fp16, V single; 1-pass) ----
#pragma unroll
        for (int ka = 0; ka < 4; ka++) {
            const int j0 = 2 * ka, j1 = 2 * ka + 1;
            uint32_t ph[4];
            ph[0] = packh(__float2half_rn(s[j0][0]), __float2half_rn(s[j0][1]));
            ph[1] = packh(__float2half_rn(s[j0][2]), __float2half_rn(s[j0][3]));
            ph[2] = packh(__float2half_rn(s[j1][0]), __float2half_rn(s[j1][1]));
            ph[3] = packh(__float2half_rn(s[j1][2]), __float2half_rn(s[j1][3]));
            const uint32_t ksl = (uint32_t)(ka * 16 * SSTR * 2);
#pragma unroll
            for (int n = 0; n < 8; n++) {
                uint32_t b0, b1;
                ldsm_x2_t(b0, b1, vfb + ksl + 16 * n);
                mma16816(o[n], ph, b0, b1);
            }
        }
        __syncthreads();
    }

    // ---- virtual tile: masked keys, all with score exactly 1e-9 ----
    float w0c = 0.f, w1c = 0.f, lf0 = l0, lf1 = l1;
    if (cnt0 > 0) {
        float mf0 = fmaxf(m0, 1e-9f);
        float mf1 = fmaxf(m1, 1e-9f);
        float sc0 = __expf(m0 - mf0);
        float sc1 = __expf(m1 - mf1);
        w0c = __expf(1e-9f - mf0);
        w1c = __expf(1e-9f - mf1);
        lf0 = l0 * sc0 + (float)cnt0 * w0c;
        lf1 = l1 * sc1 + (float)cnt0 * w1c;
#pragma unroll
        for (int n = 0; n < 8; n++) {
            o[n][0] *= sc0; o[n][1] *= sc0; o[n][2] *= sc1; o[n][3] *= sc1;
        }
    }

    // ---- epilogue: masked-V correction, normalize, split-store ----
    float inv0 = 1.f / lf0, inv1 = 1.f / lf1;
    int qr = q0 + 16 * w + g;
#pragma unroll
    for (int n = 0; n < 8; n++) {
        int col = cb + 8 * n + 2 * tig;
        float sv0 = sv[b * CDIM + col];
        float sv1 = sv[b * CDIM + col + 1];
        float a0 = (o[n][0] + w0c * sv0) * inv0;
        float a1 = (o[n][1] + w0c * sv1) * inv0;
        float a2 = (o[n][2] + w1c * sv0) * inv1;
        float a3 = (o[n][3] + w1c * sv1) * inv1;
        h16 h0, h1, h2, h3, e0, e1, e2, e3;
        split2h(a0, h0, e0); split2h(a1, h1, e1);
        split2h(a2, h2, e2); split2h(a3, h3, e3);
        *(uint32_t*)&OH[(size_t)(b * CN + qr) * CDIM + col]     = packh(h0, h1);
        *(uint32_t*)&OL[(size_t)(b * CN + qr) * CDIM + col]     = packh(e0, e1);
        *(uint32_t*)&OH[(size_t)(b * CN + qr + 8) * CDIM + col] = packh(h2, h3);
        *(uint32_t*)&OL[(size_t)(b * CN + qr + 8) * CDIM + col] = packh(e2, e3);
    }
}

// ---------------------------------------------------------------------------
extern "C" void kernel_launch(void* const* d_in, const int* in_sizes, int n_in,
                              void* d_out, int out_size)
{
    const float* x    = (const float*)d_in[0];
    const int*   mask = (const int*)  d_in[1];
    const float* W[4] = { (const float*)d_in[2], (const float*)d_in[3],
                          (const float*)d_in[4], (const float*)d_in[5] };
    float* out = (float*)d_out;

    h16 *xh, *xl, *qh, *ql, *kf, *vf, *oh, *ol, *wf;
    int *idxl, *cnt;
    float *sv, *xm;
    cudaGetSymbolAddress((void**)&xh, g_xh);
    cudaGetSymbolAddress((void**)&xl, g_xl);
    cudaGetSymbolAddress((void**)&qh, g_qh);
    cudaGetSymbolAddress((void**)&ql, g_ql);
    cudaGetSymbolAddress((void**)&kf, g_kf);
    cudaGetSymbolAddress((void**)&vf, g_vf);
    cudaGetSymbolAddress((void**)&oh, g_oh);
    cudaGetSymbolAddress((void**)&ol, g_ol);
    cudaGetSymbolAddress((void**)&wf, g_wf);
    cudaGetSymbolAddress((void**)&idxl, g_idx);
    cudaGetSymbolAddress((void**)&cnt, g_cnt);
    cudaGetSymbolAddress((void**)&sv, g_sv);
    cudaGetSymbolAddress((void**)&xm, g_xm);

    const int M  = CB * CN;            // 8192
    const int NX = M * CDIM;
    const int NW = CDIM * CDIM;
    const int NTOT = NX + 4 * NW;

    split_all_kernel<<<NTOT / 4 / 256, 256>>>(x, W[0], W[1], W[2], W[3], xh, xl, wf);
    scan_kernel<<<CB, 256>>>(mask, idxl, cnt, xm);
    xmsum_kernel<<<dim3(CDIM / 128, CB, 8), 128>>>(x, mask, xm);
    gemv_sv_kernel<<<dim3(CDIM / 8, CB), 256>>>(W[2], xm, sv);

    const int gsm  = 2 * STAGE_B;                                       // 110592 B
    const int asmb = (2 * 2 * 64 + 128) * SSTR * (int)sizeof(h16);      // 55296 B
    cudaFuncSetAttribute(proj_gemm_kernel, cudaFuncAttributeMaxDynamicSharedMemorySize, gsm);
    cudaFuncSetAttribute(out_gemm_kernel, cudaFuncAttributeMaxDynamicSharedMemorySize, gsm);
    cudaFuncSetAttribute(attn_mma_kernel, cudaFuncAttributeMaxDynamicSharedMemorySize, asmb);

    proj_gemm_kernel<<<dim3(12, 64), 256, gsm>>>(
        xh, xl,
        wf + 0 * (size_t)NW, wf + 1 * (size_t)NW, wf + 2 * (size_t)NW,
        idxl, cnt, qh, ql, kf, vf);

    attn_mma_kernel<<<dim3(CN / 128, CH * CB), 256, asmb>>>(
        qh, ql, kf, vf, cnt, sv, oh, ol);

    out_gemm_kernel<<<dim3(4, M / 128), 256, gsm>>>(
        oh, ol, wf + 3 * (size_t)NW, out);
}

// round 13
// speedup vs baseline: 4.0500x; 1.4167x over previous
#include <cuda_runtime.h>
#include <cuda_fp16.h>
#include <cstdint>

#define CB   4
#define CN   2048
#define CH   8
#define CDH  64
#define CDIM 512
#define ATT_SCALE 0.125f
#define SSTR 72            // smem row stride in fp16 (64 data + 8 pad) = 144B

typedef __half h16;

// ---------------- scratch (__device__ globals; no allocation allowed) -------
__device__ h16 g_xf[CB * CN * CDIM];    // x, single fp16
__device__ h16 g_qf[CB * CN * CDIM];    // Q (pre-scaled), single fp16
__device__ h16 g_kf[CB * CN * CDIM];    // compacted K rows, single fp16
__device__ h16 g_vf[CB * CN * CDIM];    // compacted V rows, single fp16
__device__ h16 g_of[CB * CN * CDIM];    // attention output, single fp16
__device__ h16 g_wf[4][CDIM * CDIM];    // weights, single fp16
__device__ int  g_idx[CB * CN];
__device__ int  g_cnt[CB];
__device__ float g_sv[CB * CDIM];       // Wv * (sum of masked x)  (exact fp32)
__device__ float g_xm[CB * CDIM];       // sum of x over masked keys

// ---------------- helpers ----------------------------------------------------
__device__ __forceinline__ void mma16816(float* c, const uint32_t* a, uint32_t b0, uint32_t b1) {
    asm volatile(
        "mma.sync.aligned.m16n8k16.row.col.f32.f16.f16.f32 "
        "{%0,%1,%2,%3}, {%4,%5,%6,%7}, {%8,%9}, {%0,%1,%2,%3};\n"
        : "+f"(c[0]), "+f"(c[1]), "+f"(c[2]), "+f"(c[3])
        : "r"(a[0]), "r"(a[1]), "r"(a[2]), "r"(a[3]), "r"(b0), "r"(b1));
}
__device__ __forceinline__ void ldsm_x2_t(uint32_t& r0, uint32_t& r1, uint32_t saddr) {
    asm volatile("ldmatrix.sync.aligned.m8n8.x2.trans.shared.b16 {%0,%1}, [%2];"
                 : "=r"(r0), "=r"(r1) : "r"(saddr));
}
__device__ __forceinline__ uint32_t packh(h16 x, h16 y) {
    __half2 t = __halves2half2(x, y);
    return *reinterpret_cast<uint32_t*>(&t);
}
__device__ __forceinline__ uint32_t smem_u32(const void* p) {
    uint32_t a;
    asm("{ .reg .u64 t; cvta.to.shared.u64 t, %1; cvt.u32.u64 %0, t; }" : "=r"(a) : "l"(p));
    return a;
}
__device__ __forceinline__ void cp_async16(uint32_t saddr, const void* g) {
    asm volatile("cp.async.cg.shared.global [%0], [%1], 16;" :: "r"(saddr), "l"(g));
}
__device__ __forceinline__ void cp_commit() { asm volatile("cp.async.commit_group;"); }
template<int N> __device__ __forceinline__ void cp_wait() {
    asm volatile("cp.async.wait_group %0;" :: "n"(N));
}

// ---------------- fused prep: convert x + all 4 weights to fp16 --------------
__global__ void conv_all_kernel(const float* __restrict__ x,
                                const float* __restrict__ w0, const float* __restrict__ w1,
                                const float* __restrict__ w2, const float* __restrict__ w3,
                                h16* __restrict__ xf, h16* __restrict__ wf)
{
    const int NXc = CB * CN * CDIM;
    const int NWc = CDIM * CDIM;
    int i = (blockIdx.x * blockDim.x + threadIdx.x) * 4;
    const float* src;
    h16* dst;
    if (i < NXc) {
        src = x + i;
        dst = xf + i;
    } else {
        int j = i - NXc;
        if (j >= 4 * NWc) return;
        int w = j / NWc, o = j - w * NWc;
        src = ((w == 0) ? w0 : (w == 1) ? w1 : (w == 2) ? w2 : w3) + o;
        dst = wf + (size_t)w * NWc + o;
    }
    float4 v = *(const float4*)src;
    *(uint32_t*)(dst)     = packh(__float2half_rn(v.x), __float2half_rn(v.y));
    *(uint32_t*)(dst + 2) = packh(__float2half_rn(v.z), __float2half_rn(v.w));
}

// ---------------- mask scan: compact unmasked key list -----------------------
__global__ void scan_kernel(const int* __restrict__ mask,
                            int* __restrict__ idxl, int* __restrict__ cnt,
                            float* __restrict__ xm)
{
    __shared__ int ps[256];
    const int b = blockIdx.x, t = threadIdx.x;
    xm[b * CDIM + t]       = 0.f;
    xm[b * CDIM + 256 + t] = 0.f;
    int loc[8], c = 0;
#pragma unroll
    for (int i = 0; i < 8; i++) {
        loc[i] = c;
        c += (mask[b * CN + t * 8 + i] != 0);
    }
    ps[t] = c;
    __syncthreads();
    for (int off = 1; off < 256; off <<= 1) {
        int v = (t >= off) ? ps[t - off] : 0;
        __syncthreads();
        ps[t] += v;
        __syncthreads();
    }
    int excl = ps[t] - c;
#pragma unroll
    for (int i = 0; i < 8; i++)
        if (mask[b * CN + t * 8 + i] != 0)
            idxl[b * CN + excl + loc[i]] = t * 8 + i;
    if (t == 255) cnt[b] = ps[255];
}

// ---------------- masked-x column sums ---------------------------------------
__global__ void xmsum_kernel(const float* __restrict__ x, const int* __restrict__ mask,
                             float* __restrict__ xm)
{
    const int c  = blockIdx.x * 128 + threadIdx.x;
    const int b  = blockIdx.y;
    const int r0 = blockIdx.z * 256;
    float s = 0.f;
#pragma unroll 4
    for (int i = 0; i < 256; i++) {
        int t = r0 + i;
        if (mask[b * CN + t] == 0)
            s += x[(size_t)(b * CN + t) * CDIM + c];
    }
    atomicAdd(&xm[b * CDIM + c], s);
}

// ---------------- sv = Wv * xm (warp-per-output GEMV) ------------------------
__global__ void gemv_sv_kernel(const float* __restrict__ Wv, const float* __restrict__ xm,
                               float* __restrict__ sv)
{
    const int warp = threadIdx.x >> 5, lane = threadIdx.x & 31;
    const int n = blockIdx.x * 8 + warp;
    const int b = blockIdx.y;
    const float* wr = Wv + (size_t)n * CDIM;
    const float* xr = xm + b * CDIM;
    float s = 0.f;
#pragma unroll
    for (int c = lane * 4; c < CDIM; c += 128) {
        float4 wv = *(const float4*)(wr + c);
        float4 xv = *(const float4*)(xr + c);
        s += wv.x * xv.x + wv.y * xv.y + wv.z * xv.z + wv.w * xv.w;
    }
    s += __shfl_xor_sync(0xffffffffu, s, 16);
    s += __shfl_xor_sync(0xffffffffu, s, 8);
    s += __shfl_xor_sync(0xffffffffu, s, 4);
    s += __shfl_xor_sync(0xffffffffu, s, 2);
    s += __shfl_xor_sync(0xffffffffu, s, 1);
    if (lane == 0) sv[b * CDIM + n] = s;
}

// ---------------- GEMM mainloop: single fp16, 1-pass -------------------------
#define TEN_B   (128 * SSTR * 2)
#define STAGE_B (2 * TEN_B)

#define GEMM_LOAD_CHUNK(st, kc)                                                   \
    {                                                                             \
        _Pragma("unroll")                                                         \
        for (int i = 0; i < 4; i++) {                                             \
            int idx = tid + 256 * i;                                              \
            int r = idx >> 3, u = idx & 7;                                        \
            uint32_t so = sbase + (uint32_t)((st) * STAGE_B + (r * SSTR + 8 * u) * 2); \
            cp_async16(so + 0 * TEN_B, Af_g + (size_t)(rowBase + r) * CDIM + (kc) + 8 * u); \
            cp_async16(so + 1 * TEN_B, Bf_g + (size_t)(colBase + r) * CDIM + (kc) + 8 * u); \
        }                                                                         \
        cp_commit();                                                              \
    }

#define KV_LOAD_CHUNK(st, kc)                                                     \
    {                                                                             \
        _Pragma("unroll")                                                         \
        for (int i = 0; i < 4; i++) {                                             \
            int idx = tid + 256 * i;                                              \
            int r = idx >> 3, u = idx & 7;                                        \
            uint32_t so = sbase + (uint32_t)((st) * STAGE_B + (r * SSTR + 8 * u) * 2); \
            cp_async16(so + 0 * TEN_B, Af_g + (size_t)(b * CN + toks[i]) * CDIM + (kc) + 8 * u); \
            cp_async16(so + 1 * TEN_B, Bf_g + (size_t)(colBase + r) * CDIM + (kc) + 8 * u); \
        }                                                                         \
        cp_commit();                                                              \
    }

#define GEMM_COMPUTE_CHUNK(st)                                                    \
    {                                                                             \
        const h16* Af = gs + (st) * 2 * 128 * SSTR;                               \
        const h16* Bf = Af + 128 * SSTR;                                          \
        _Pragma("unroll")                                                         \
        for (int ka = 0; ka < 4; ka++) {                                          \
            const int ko = 16 * ka + 2 * tig;                                     \
            uint32_t af[2][4];                                                    \
            _Pragma("unroll")                                                     \
            for (int m = 0; m < 2; m++) {                                         \
                int rb = 32 * wM + 16 * m;                                        \
                af[m][0] = *(const uint32_t*)&Af[(rb + g)     * SSTR + ko];       \
                af[m][1] = *(const uint32_t*)&Af[(rb + g + 8) * SSTR + ko];       \
                af[m][2] = *(const uint32_t*)&Af[(rb + g)     * SSTR + ko + 8];   \
                af[m][3] = *(const uint32_t*)&Af[(rb + g + 8) * SSTR + ko + 8];   \
            }                                                                     \
            _Pragma("unroll")                                                     \
            for (int j = 0; j < 8; j++) {                                         \
                int cr = 64 * wN + 8 * j + g;                                     \
                uint32_t b0 = *(const uint32_t*)&Bf[cr * SSTR + ko];              \
                uint32_t b1 = *(const uint32_t*)&Bf[cr * SSTR + ko + 8];          \
                mma16816(acc[0][j], af[0], b0, b1);                               \
                mma16816(acc[1][j], af[1], b0, b1);                               \
            }                                                                     \
        }                                                                         \
    }

#define GEMM_PREAMBLE()                                                           \
    const int tid  = threadIdx.x;                                                 \
    const int w    = tid >> 5;                                                    \
    const int lane = tid & 31;                                                    \
    const int g    = lane >> 2;                                                   \
    const int tig  = lane & 3;                                                    \
    const int wM   = w >> 1;                                                      \
    const int wN   = w & 1;                                                       \
    float acc[2][8][4];                                                           \
    _Pragma("unroll")                                                             \
    for (int m = 0; m < 2; m++)                                                   \
        _Pragma("unroll")                                                         \
        for (int j = 0; j < 8; j++)                                               \
            _Pragma("unroll")                                                     \
            for (int t = 0; t < 4; t++) acc[m][j][t] = 0.f;

#define GEMM_MAINLOOP(LOADM)                                                      \
    LOADM(0, 0)                                                                   \
    _Pragma("unroll 1")                                                           \
    for (int ch = 0; ch < 8; ch++) {                                              \
        if (ch + 1 < 8) LOADM((ch + 1) & 1, 64 * (ch + 1))                        \
        if (ch + 1 < 8) cp_wait<1>(); else cp_wait<0>();                          \
        __syncthreads();                                                          \
        GEMM_COMPUTE_CHUNK(ch & 1)                                                \
        __syncthreads();                                                          \
    }

#define GEMM_EPI_SINGLE(outF, rowB, scale)                                        \
    _Pragma("unroll")                                                             \
    for (int m = 0; m < 2; m++)                                                   \
        _Pragma("unroll")                                                         \
        for (int j = 0; j < 8; j++) {                                             \
            int row = (rowB) + 32 * wM + 16 * m + g;                              \
            int col = colBase + 64 * wN + 8 * j + 2 * tig;                        \
            *(uint32_t*)&(outF)[(size_t)row * CDIM + col] =                       \
                packh(__float2half_rn(acc[m][j][0] * (scale)),                    \
                      __float2half_rn(acc[m][j][1] * (scale)));                   \
            *(uint32_t*)&(outF)[(size_t)(row + 8) * CDIM + col] =                 \
                packh(__float2half_rn(acc[m][j][2] * (scale)),                    \
                      __float2half_rn(acc[m][j][3] * (scale)));                   \
        }

// ---------------- fused Q + compacted-K/V projection (1-pass) ----------------
// grid.x in [0,12): 0..3 -> Q; 4..7 -> K (compact); 8..11 -> V (compact).
__global__ __launch_bounds__(256, 2) void proj_gemm_kernel(
    const h16* __restrict__ Af_g,
    const h16* __restrict__ wq, const h16* __restrict__ wk, const h16* __restrict__ wv,
    const int* __restrict__ idxl, const int* __restrict__ cntp,
    h16* __restrict__ qf, h16* __restrict__ kcf, h16* __restrict__ vcf)
{
    extern __shared__ h16 gs[];
    const uint32_t sbase = smem_u32(gs);

    if (blockIdx.x < 4) {
        const int colBase = blockIdx.x * 128;
        const int rowBase = blockIdx.y * 128;
        const h16* Bf_g = wq;
        GEMM_PREAMBLE()
        GEMM_MAINLOOP(GEMM_LOAD_CHUNK)
        GEMM_EPI_SINGLE(qf, rowBase, ATT_SCALE)
    } else {
        const int xx      = blockIdx.x - 4;
        const int wsel    = xx >> 2;                 // 0 = K, 1 = V
        const int colBase = (xx & 3) * 128;
        const int b       = blockIdx.y >> 4;
        const int tile    = blockIdx.y & 15;
        const int cnt1    = cntp[b];
        const int kend    = (cnt1 + 63) & ~63;
        if (tile * 128 >= kend) return;
        const int* bidx = idxl + b * CN;
        const h16* Bf_g = wsel ? wv : wk;

        GEMM_PREAMBLE()

        int toks[4];
#pragma unroll
        for (int i = 0; i < 4; i++) {
            int r = (tid + 256 * i) >> 3;
            int jj = tile * 128 + r;
            toks[i] = bidx[jj < cnt1 ? jj : cnt1 - 1];
        }

        GEMM_MAINLOOP(KV_LOAD_CHUNK)

        const int rowB = b * CN + tile * 128;
        if (wsel == 0) {
            GEMM_EPI_SINGLE(kcf, rowB, 1.0f)
        } else {
            GEMM_EPI_SINGLE(vcf, rowB, 1.0f)
        }
    }
}

// ---------------- output projection (1-pass, fp32 out) -----------------------
__global__ __launch_bounds__(256, 2) void out_gemm_kernel(
    const h16* __restrict__ Af_g, const h16* __restrict__ Bf_g, float* __restrict__ C)
{
    extern __shared__ h16 gs[];
    const uint32_t sbase = smem_u32(gs);
    const int colBase = blockIdx.x * 128;
    const int rowBase = blockIdx.y * 128;

    GEMM_PREAMBLE()
    GEMM_MAINLOOP(GEMM_LOAD_CHUNK)

#pragma unroll
    for (int m = 0; m < 2; m++)
#pragma unroll
        for (int j = 0; j < 8; j++) {
            int row = rowBase + 32 * wM + 16 * m + g;
            int col = colBase + 64 * wN + 8 * j + 2 * tig;
            *(float2*)&C[(size_t)row * CDIM + col]       = make_float2(acc[m][j][0], acc[m][j][1]);
            *(float2*)&C[(size_t)(row + 8) * CDIM + col] = make_float2(acc[m][j][2], acc[m][j][3]);
        }
}

// ---------------- flash attention: QK 1-pass, PV 1-pass ----------------------
#define ATEN (64 * SSTR)
#define ASTG (2 * ATEN)                 // kf, vf

__global__ __launch_bounds__(256, 2) void attn_mma_kernel(
    const h16* __restrict__ qf_g,
    const h16* __restrict__ kf_g, const h16* __restrict__ vf_g,
    const int* __restrict__ cntp, const float* __restrict__ sv,
    h16* __restrict__ OF)
{
    extern __shared__ h16 sm[];        // [2 stages][2 tensors][64*SSTR] + Q staging
    h16* Qs = sm + 2 * ASTG;

    const uint32_t sbase = smem_u32(sm);
    const int tid  = threadIdx.x;
    const int w    = tid >> 5;
    const int lane = tid & 31;
    const int g    = lane >> 2;
    const int tig  = lane & 3;
    const int q0   = blockIdx.x * 128;
    const int h    = blockIdx.y & 7;
    const int b    = blockIdx.y >> 3;
    const int cb   = h * CDH;

    const int cnt1 = cntp[b];
    const int cnt0 = CN - cnt1;
    const int nt   = (cnt1 + 63) >> 6;

    const uint32_t lrow = (uint32_t)(lane & 15) * SSTR * 2;

    // ---- preload Q fragments (single pass via shared staging) ----
    uint32_t qf[4][4];
    {
#pragma unroll
        for (int i = 0; i < 4; i++) {
            int idx = tid + 256 * i;
            int r = idx >> 3, u = idx & 7;
            *(uint4*)&Qs[r * SSTR + 8 * u] =
                *((const uint4*)(qf_g + (size_t)(b * CN + q0 + r) * CDIM + cb) + u);
        }
        __syncthreads();
#pragma unroll
        for (int ka = 0; ka < 4; ka++) {
            int rb = 16 * w;
            int ko = 16 * ka + 2 * tig;
            qf[ka][0] = *(const uint32_t*)&Qs[(rb + g)     * SSTR + ko];
            qf[ka][1] = *(const uint32_t*)&Qs[(rb + g + 8) * SSTR + ko];
            qf[ka][2] = *(const uint32_t*)&Qs[(rb + g)     * SSTR + ko + 8];
            qf[ka][3] = *(const uint32_t*)&Qs[(rb + g + 8) * SSTR + ko + 8];
        }
        __syncthreads();
    }

    float o[8][4];
#pragma unroll
    for (int n = 0; n < 8; n++)
#pragma unroll
        for (int t = 0; t < 4; t++) o[n][t] = 0.f;
    float m0 = -1e30f, m1 = -1e30f, l0 = 0.f, l1 = 0.f;

#define ATT_LOAD(st, kb_)                                                          \
    {                                                                              \
        _Pragma("unroll")                                                          \
        for (int i = 0; i < 2; i++) {                                              \
            int idx = tid + 256 * i;          /* 0..511 */                         \
            int r = idx >> 3, u = idx & 7;                                         \
            size_t grow = (size_t)(b * CN + (kb_) + r) * CDIM + cb + 8 * u;        \
            uint32_t so = sbase + (uint32_t)(((st) * ASTG + r * SSTR + 8 * u) * 2);\
            cp_async16(so + 0 * ATEN * 2, kf_g + grow);                            \
            cp_async16(so + 1 * ATEN * 2, vf_g + grow);                            \
        }                                                                          \
        cp_commit();                                                               \
    }

    if (nt > 0) ATT_LOAD(0, 0)

#pragma unroll 1
    for (int it = 0; it < nt; it++) {
        const int kb = it * 64;
        const int st = it & 1;
        if (it + 1 < nt) ATT_LOAD((it + 1) & 1, kb + 64)
        if (it + 1 < nt) cp_wait<1>(); else cp_wait<0>();
        __syncthreads();

        const h16* Kf = sm + st * ASTG;
        const uint32_t vfb = sbase + (uint32_t)((st * ASTG + ATEN) * 2) + lrow;

        // ---- S = Q K^T (1-pass) ----
        float s[8][4];
#pragma unroll
        for (int j = 0; j < 8; j++)
#pragma unroll
            for (int t = 0; t < 4; t++) s[j][t] = 0.f;
#pragma unroll
        for (int ka = 0; ka < 4; ka++) {
            const int ko = 16 * ka + 2 * tig;
#pragma unroll
            for (int j = 0; j < 8; j++) {
                int kr = 8 * j + g;
                uint32_t b0 = *(const uint32_t*)&Kf[kr * SSTR + ko];
                uint32_t b1 = *(const uint32_t*)&Kf[kr * SSTR + ko + 8];
                mma16816(s[j], qf[ka], b0, b1);
            }
        }

        // ---- tail exclusion for padding keys (exact: weight 0) ----
        if (kb + 64 > cnt1) {
#pragma unroll
            for (int j = 0; j < 8; j++) {
                int kc0 = kb + 8 * j + 2 * tig;
                if (kc0     >= cnt1) { s[j][0] = -1e30f; s[j][2] = -1e30f; }
                if (kc0 + 1 >= cnt1) { s[j][1] = -1e30f; s[j][3] = -1e30f; }
            }
        }

        // ---- online softmax ----
        float rm0 = -1e30f, rm1 = -1e30f;
#pragma unroll
        for (int j = 0; j < 8; j++) {
            rm0 = fmaxf(rm0, fmaxf(s[j][0], s[j][1]));
            rm1 = fmaxf(rm1, fmaxf(s[j][2], s[j][3]));
        }
        rm0 = fmaxf(rm0, __shfl_xor_sync(0xffffffffu, rm0, 1));
        rm0 = fmaxf(rm0, __shfl_xor_sync(0xffffffffu, rm0, 2));
        rm1 = fmaxf(rm1, __shfl_xor_sync(0xffffffffu, rm1, 1));
        rm1 = fmaxf(rm1, __shfl_xor_sync(0xffffffffu, rm1, 2));
        float mn0 = fmaxf(m0, rm0), mn1 = fmaxf(m1, rm1);
        float al0 = __expf(m0 - mn0), al1 = __expf(m1 - mn1);
        m0 = mn0; m1 = mn1;
        float rs0 = 0.f, rs1 = 0.f;
#pragma unroll
        for (int j = 0; j < 8; j++) {
            s[j][0] = __expf(s[j][0] - m0); rs0 += s[j][0];
            s[j][1] = __expf(s[j][1] - m0); rs0 += s[j][1];
            s[j][2] = __expf(s[j][2] - m1); rs1 += s[j][2];
            s[j][3] = __expf(s[j][3] - m1); rs1 += s[j][3];
        }
        rs0 += __shfl_xor_sync(0xffffffffu, rs0, 1);
        rs0 += __shfl_xor_sync(0xffffffffu, rs0, 2);
        rs1 += __shfl_xor_sync(0xffffffffu, rs1, 1);
        rs1 += __shfl_xor_sync(0xffffffffu, rs1, 2);
        l0 = l0 * al0 + rs0;
        l1 = l1 * al1 + rs1;
#pragma unroll
        for (int n = 0; n < 8; n++) {
            o[n][0] *= al0; o[n][1] *= al0; o[n][2] *= al1; o[n][3] *= al1;
        }

        // ---- O += P V (P single fp16, V single; 1-pass) ----
#pragma unroll
        for (int ka = 0; ka < 4; ka++) {
            const int j0 = 2 * ka, j1 = 2 * ka + 1;
            uint32_t ph[4];
            ph[0] = packh(__float2half_rn(s[j0][0]), __float2half_rn(s[j0][1]));
            ph[1] = packh(__float2half_rn(s[j0][2]), __float2half_rn(s[j0][3]));
            ph[2] = packh(__float2half_rn(s[j1][0]), __float2half_rn(s[j1][1]));
            ph[3] = packh(__float2half_rn(s[j1][2]), __float2half_rn(s[j1][3]));
            const uint32_t ksl = (uint32_t)(ka * 16 * SSTR * 2);
#pragma unroll
            for (int n = 0; n < 8; n++) {
                uint32_t b0, b1;
                ldsm_x2_t(b0, b1, vfb + ksl + 16 * n);
                mma16816(o[n], ph, b0, b1);
            }
        }
        __syncthreads();
    }

    // ---- virtual tile: masked keys, all with score exactly 1e-9 ----
    float w0c = 0.f, w1c = 0.f, lf0 = l0, lf1 = l1;
    if (cnt0 > 0) {
        float mf0 = fmaxf(m0, 1e-9f);
        float mf1 = fmaxf(m1, 1e-9f);
        float sc0 = __expf(m0 - mf0);
        float sc1 = __expf(m1 - mf1);
        w0c = __expf(1e-9f - mf0);
        w1c = __expf(1e-9f - mf1);
        lf0 = l0 * sc0 + (float)cnt0 * w0c;
        lf1 = l1 * sc1 + (float)cnt0 * w1c;
#pragma unroll
        for (int n = 0; n < 8; n++) {
            o[n][0] *= sc0; o[n][1] *= sc0; o[n][2] *= sc1; o[n][3] *= sc1;
        }
    }

    // ---- epilogue: masked-V correction, normalize, fp16 store ----
    float inv0 = 1.f / lf0, inv1 = 1.f / lf1;
    int qr = q0 + 16 * w + g;
#pragma unroll
    for (int n = 0; n < 8; n++) {
        int col = cb + 8 * n + 2 * tig;
        float sv0 = sv[b * CDIM + col];
        float sv1 = sv[b * CDIM + col + 1];
        float a0 = (o[n][0] + w0c * sv0) * inv0;
        float a1 = (o[n][1] + w0c * sv1) * inv0;
        float a2 = (o[n][2] + w1c * sv0) * inv1;
        float a3 = (o[n][3] + w1c * sv1) * inv1;
        *(uint32_t*)&OF[(size_t)(b * CN + qr) * CDIM + col] =
            packh(__float2half_rn(a0), __float2half_rn(a1));
        *(uint32_t*)&OF[(size_t)(b * CN + qr + 8) * CDIM + col] =
            packh(__float2half_rn(a2), __float2half_rn(a3));
    }
}

// ---------------------------------------------------------------------------
extern "C" void kernel_launch(void* const* d_in, const int* in_sizes, int n_in,
                              void* d_out, int out_size)
{
    const float* x    = (const float*)d_in[0];
    const int*   mask = (const int*)  d_in[1];
    const float* W[4] = { (const float*)d_in[2], (const float*)d_in[3],
                          (const float*)d_in[4], (const float*)d_in[5] };
    float* out = (float*)d_out;

    h16 *xf, *qf, *kf, *vf, *of, *wf;
    int *idxl, *cnt;
    float *sv, *xm;
    cudaGetSymbolAddress((void**)&xf, g_xf);
    cudaGetSymbolAddress((void**)&qf, g_qf);
    cudaGetSymbolAddress((void**)&kf, g_kf);
    cudaGetSymbolAddress((void**)&vf, g_vf);
    cudaGetSymbolAddress((void**)&of, g_of);
    cudaGetSymbolAddress((void**)&wf, g_wf);
    cudaGetSymbolAddress((void**)&idxl, g_idx);
    cudaGetSymbolAddress((void**)&cnt, g_cnt);
    cudaGetSymbolAddress((void**)&sv, g_sv);
    cudaGetSymbolAddress((void**)&xm, g_xm);

    const int M  = CB * CN;            // 8192
    const int NX = M * CDIM;
    const int NW = CDIM * CDIM;
    const int NTOT = NX + 4 * NW;

    conv_all_kernel<<<NTOT / 4 / 256, 256>>>(x, W[0], W[1], W[2], W[3], xf, wf);
    scan_kernel<<<CB, 256>>>(mask, idxl, cnt, xm);
    xmsum_kernel<<<dim3(CDIM / 128, CB, 8), 128>>>(x, mask, xm);
    gemv_sv_kernel<<<dim3(CDIM / 8, CB), 256>>>(W[2], xm, sv);

    const int gsm  = 2 * STAGE_B;                                       // 73728 B
    const int asmb = (2 * 2 * 64 + 128) * SSTR * (int)sizeof(h16);      // 55296 B
    cudaFuncSetAttribute(proj_gemm_kernel, cudaFuncAttributeMaxDynamicSharedMemorySize, gsm);
    cudaFuncSetAttribute(out_gemm_kernel, cudaFuncAttributeMaxDynamicSharedMemorySize, gsm);
    cudaFuncSetAttribute(attn_mma_kernel, cudaFuncAttributeMaxDynamicSharedMemorySize, asmb);

    proj_gemm_kernel<<<dim3(12, 64), 256, gsm>>>(
        xf,
        wf + 0 * (size_t)NW, wf + 1 * (size_t)NW, wf + 2 * (size_t)NW,
        idxl, cnt, qf, kf, vf);

    attn_mma_kernel<<<dim3(CN / 128, CH * CB), 256, asmb>>>(
        qf, kf, vf, cnt, sv, of);

    out_gemm_kernel<<<dim3(4, M / 128), 256, gsm>>>(
        of, wf + 3 * (size_t)NW, out);
}

// round 14
// speedup vs baseline: 4.4583x; 1.1008x over previous
#include <cuda_runtime.h>
#include <cuda_fp16.h>
#include <cstdint>

#define CB   4
#define CN   2048
#define CH   8
#define CDH  64
#define CDIM 512
#define ATT_SCALE 0.125f
#define SSTR 72            // smem row stride in fp16 (64 data + 8 pad) = 144B

typedef __half h16;

// ---------------- scratch (__device__ globals; no allocation allowed) -------
__device__ h16 g_xf[CB * CN * CDIM];
__device__ h16 g_qf[CB * CN * CDIM];
__device__ h16 g_kf[CB * CN * CDIM];    // compacted K rows
__device__ h16 g_vf[CB * CN * CDIM];    // compacted V rows
__device__ h16 g_of[CB * CN * CDIM];
__device__ h16 g_wf[4][CDIM * CDIM];
__device__ int  g_idx[CB * CN];
__device__ int  g_cnt[CB];
__device__ float g_sv[CB * CDIM];
__device__ float g_xm[CB * CDIM];

// ---------------- helpers ----------------------------------------------------
__device__ __forceinline__ void mma16816(float* c, const uint32_t* a, uint32_t b0, uint32_t b1) {
    asm volatile(
        "mma.sync.aligned.m16n8k16.row.col.f32.f16.f16.f32 "
        "{%0,%1,%2,%3}, {%4,%5,%6,%7}, {%8,%9}, {%0,%1,%2,%3};\n"
        : "+f"(c[0]), "+f"(c[1]), "+f"(c[2]), "+f"(c[3])
        : "r"(a[0]), "r"(a[1]), "r"(a[2]), "r"(a[3]), "r"(b0), "r"(b1));
}
__device__ __forceinline__ void ldsm_x2_t(uint32_t& r0, uint32_t& r1, uint32_t saddr) {
    asm volatile("ldmatrix.sync.aligned.m8n8.x2.trans.shared.b16 {%0,%1}, [%2];"
                 : "=r"(r0), "=r"(r1) : "r"(saddr));
}
__device__ __forceinline__ uint32_t packh(h16 x, h16 y) {
    __half2 t = __halves2half2(x, y);
    return *reinterpret_cast<uint32_t*>(&t);
}
__device__ __forceinline__ uint32_t smem_u32(const void* p) {
    uint32_t a;
    asm("{ .reg .u64 t; cvta.to.shared.u64 t, %1; cvt.u32.u64 %0, t; }" : "=r"(a) : "l"(p));
    return a;
}
__device__ __forceinline__ void cp_async16(uint32_t saddr, const void* g) {
    asm volatile("cp.async.cg.shared.global [%0], [%1], 16;" :: "r"(saddr), "l"(g));
}
__device__ __forceinline__ void cp_commit() { asm volatile("cp.async.commit_group;"); }
template<int N> __device__ __forceinline__ void cp_wait() {
    asm volatile("cp.async.wait_group %0;" :: "n"(N));
}

// ---------------- fused prep: convert x + weights to fp16, zero xm -----------
__global__ void conv_all_kernel(const float* __restrict__ x,
                                const float* __restrict__ w0, const float* __restrict__ w1,
                                const float* __restrict__ w2, const float* __restrict__ w3,
                                h16* __restrict__ xf, h16* __restrict__ wf,
                                float* __restrict__ xm)
{
    const int NXc = CB * CN * CDIM;
    const int NWc = CDIM * CDIM;
    const int NB  = (NXc + 4 * NWc) / 1024;   // data blocks
    if ((int)blockIdx.x >= NB) {
        int z = (blockIdx.x - NB) * 1024 + threadIdx.x * 4;
        if (z < CB * CDIM) {
            *(float4*)&xm[z] = make_float4(0.f, 0.f, 0.f, 0.f);
        }
        return;
    }
    int i = (blockIdx.x * blockDim.x + threadIdx.x) * 4;
    const float* src;
    h16* dst;
    if (i < NXc) {
        src = x + i;
        dst = xf + i;
    } else {
        int j = i - NXc;
        int w = j / NWc, o = j - w * NWc;
        src = ((w == 0) ? w0 : (w == 1) ? w1 : (w == 2) ? w2 : w3) + o;
        dst = wf + (size_t)w * NWc + o;
    }
    float4 v = *(const float4*)src;
    *(uint32_t*)(dst)     = packh(__float2half_rn(v.x), __float2half_rn(v.y));
    *(uint32_t*)(dst + 2) = packh(__float2half_rn(v.z), __float2half_rn(v.w));
}

// ---------------- merged scan (blocks 0..3) + masked-x sums (rest) -----------
__global__ void prep_kernel(const int* __restrict__ mask, const float* __restrict__ x,
                            int* __restrict__ idxl, int* __restrict__ cnt,
                            float* __restrict__ xm)
{
    const int t = threadIdx.x;
    if (blockIdx.x < CB) {
        // ---- compaction scan for batch b ----
        __shared__ int ps[256];
        const int b = blockIdx.x;
        int loc[8], c = 0;
#pragma unroll
        for (int i = 0; i < 8; i++) {
            loc[i] = c;
            c += (mask[b * CN + t * 8 + i] != 0);
        }
        ps[t] = c;
        __syncthreads();
        for (int off = 1; off < 256; off <<= 1) {
            int v = (t >= off) ? ps[t - off] : 0;
            __syncthreads();
            ps[t] += v;
            __syncthreads();
        }
        int excl = ps[t] - c;
#pragma unroll
        for (int i = 0; i < 8; i++)
            if (mask[b * CN + t * 8 + i] != 0)
                idxl[b * CN + excl + loc[i]] = t * 8 + i;
        if (t == 255) cnt[b] = ps[255];
    } else {
        // ---- masked-x column sums: idx -> (chalf, b, seg of 64 rows) ----
        int idx   = blockIdx.x - CB;
        int chalf = idx & 1;
        int b     = (idx >> 1) & 3;
        int seg   = idx >> 3;           // 0..31
        int c     = chalf * 256 + t;
        int r0    = seg * 64;
        float s = 0.f;
#pragma unroll 4
        for (int i = 0; i < 64; i++) {
            int row = r0 + i;
            if (mask[b * CN + row] == 0)
                s += x[(size_t)(b * CN + row) * CDIM + c];
        }
        atomicAdd(&xm[b * CDIM + c], s);
    }
}

// ---------------- sv = Wv * xm (warp-per-output GEMV) ------------------------
__global__ void gemv_sv_kernel(const float* __restrict__ Wv, const float* __restrict__ xm,
                               float* __restrict__ sv)
{
    const int warp = threadIdx.x >> 5, lane = threadIdx.x & 31;
    const int n = blockIdx.x * 8 + warp;
    const int b = blockIdx.y;
    const float* wr = Wv + (size_t)n * CDIM;
    const float* xr = xm + b * CDIM;
    float s = 0.f;
#pragma unroll
    for (int c = lane * 4; c < CDIM; c += 128) {
        float4 wv = *(const float4*)(wr + c);
        float4 xv = *(const float4*)(xr + c);
        s += wv.x * xv.x + wv.y * xv.y + wv.z * xv.z + wv.w * xv.w;
    }
    s += __shfl_xor_sync(0xffffffffu, s, 16);
    s += __shfl_xor_sync(0xffffffffu, s, 8);
    s += __shfl_xor_sync(0xffffffffu, s, 4);
    s += __shfl_xor_sync(0xffffffffu, s, 2);
    s += __shfl_xor_sync(0xffffffffu, s, 1);
    if (lane == 0) sv[b * CDIM + n] = s;
}

// ---------------- GEMM mainloop: single fp16, 1-pass, 3-stage pipeline -------
#define TEN_B   (128 * SSTR * 2)
#define STAGE_B (2 * TEN_B)

#define GEMM_LOAD_CHUNK(st, kc)                                                   \
    {                                                                             \
        _Pragma("unroll")                                                         \
        for (int i = 0; i < 4; i++) {                                             \
            int idx = tid + 256 * i;                                              \
            int r = idx >> 3, u = idx & 7;                                        \
            uint32_t so = sbase + (uint32_t)((st) * STAGE_B + (r * SSTR + 8 * u) * 2); \
            cp_async16(so + 0 * TEN_B, Af_g + (size_t)(rowBase + r) * CDIM + (kc) + 8 * u); \
            cp_async16(so + 1 * TEN_B, Bf_g + (size_t)(colBase + r) * CDIM + (kc) + 8 * u); \
        }                                                                         \
        cp_commit();                                                              \
    }

#define KV_LOAD_CHUNK(st, kc)                                                     \
    {                                                                             \
        _Pragma("unroll")                                                         \
        for (int i = 0; i < 4; i++) {                                             \
            int idx = tid + 256 * i;                                              \
            int r = idx >> 3, u = idx & 7;                                        \
            uint32_t so = sbase + (uint32_t)((st) * STAGE_B + (r * SSTR + 8 * u) * 2); \
            cp_async16(so + 0 * TEN_B, Af_g + (size_t)(b * CN + toks[i]) * CDIM + (kc) + 8 * u); \
            cp_async16(so + 1 * TEN_B, Bf_g + (size_t)(colBase + r) * CDIM + (kc) + 8 * u); \
        }                                                                         \
        cp_commit();                                                              \
    }

#define GEMM_COMPUTE_CHUNK(st)                                                    \
    {                                                                             \
        const h16* Af = gs + (st) * 2 * 128 * SSTR;                               \
        const h16* Bf = Af + 128 * SSTR;                                          \
        _Pragma("unroll")                                                         \
        for (int ka = 0; ka < 4; ka++) {                                          \
            const int ko = 16 * ka + 2 * tig;                                     \
            uint32_t af[2][4];                                                    \
            _Pragma("unroll")                                                     \
            for (int m = 0; m < 2; m++) {                                         \
                int rb = 32 * wM + 16 * m;                                        \
                af[m][0] = *(const uint32_t*)&Af[(rb + g)     * SSTR + ko];       \
                af[m][1] = *(const uint32_t*)&Af[(rb + g + 8) * SSTR + ko];       \
                af[m][2] = *(const uint32_t*)&Af[(rb + g)     * SSTR + ko + 8];   \
                af[m][3] = *(const uint32_t*)&Af[(rb + g + 8) * SSTR + ko + 8];   \
            }                                                                     \
            _Pragma("unroll")                                                     \
            for (int j = 0; j < 8; j++) {                                         \
                int cr = 64 * wN + 8 * j + g;                                     \
                uint32_t b0 = *(const uint32_t*)&Bf[cr * SSTR + ko];              \
                uint32_t b1 = *(const uint32_t*)&Bf[cr * SSTR + ko + 8];          \
                mma16816(acc[0][j], af[0], b0, b1);                               \
                mma16816(acc[1][j], af[1], b0, b1);                               \
            }                                                                     \
        }                                                                         \
    }

#define GEMM_PREAMBLE()                                                           \
    const int tid  = threadIdx.x;                                                 \
    const int w    = tid >> 5;                                                    \
    const int lane = tid & 31;                                                    \
    const int g    = lane >> 2;                                                   \
    const int tig  = lane & 3;                                                    \
    const int wM   = w >> 1;                                                      \
    const int wN   = w & 1;                                                       \
    float acc[2][8][4];                                                           \
    _Pragma("unroll")                                                             \
    for (int m = 0; m < 2; m++)                                                   \
        _Pragma("unroll")                                                         \
        for (int j = 0; j < 8; j++)                                               \
            _Pragma("unroll")                                                     \
            for (int t = 0; t < 4; t++) acc[m][j][t] = 0.f;

// 3-stage, single sync per chunk: issue chunk ch+2 AFTER the sync so the stage
// being overwritten ((ch+2)%3 == (ch-1)%3) is provably drained by all warps.
#define GEMM_MAINLOOP(LOADM)                                                      \
    LOADM(0, 0)                                                                   \
    LOADM(1, 64)                                                                  \
    _Pragma("unroll 1")                                                           \
    for (int ch = 0; ch < 8; ch++) {                                              \
        if (ch < 6) cp_wait<1>(); else cp_wait<0>();                              \
        __syncthreads();                                                          \
        if (ch + 2 < 8) LOADM((ch + 2) % 3, 64 * (ch + 2))                        \
        GEMM_COMPUTE_CHUNK(ch % 3)                                                \
    }

#define GEMM_EPI_SINGLE(outF, rowB, scale)                                        \
    _Pragma("unroll")                                                             \
    for (int m = 0; m < 2; m++)                                                   \
        _Pragma("unroll")                                                         \
        for (int j = 0; j < 8; j++) {                                             \
            int row = (rowB) + 32 * wM + 16 * m + g;                              \
            int col = colBase + 64 * wN + 8 * j + 2 * tig;                        \
            *(uint32_t*)&(outF)[(size_t)row * CDIM + col] =                       \
                packh(__float2half_rn(acc[m][j][0] * (scale)),                    \
                      __float2half_rn(acc[m][j][1] * (scale)));                   \
            *(uint32_t*)&(outF)[(size_t)(row + 8) * CDIM + col] =                 \
                packh(__float2half_rn(acc[m][j][2] * (scale)),                    \
                      __float2half_rn(acc[m][j][3] * (scale)));                   \
        }

// ---------------- fused Q + compacted-K/V projection (1-pass) ----------------
__global__ __launch_bounds__(256, 2) void proj_gemm_kernel(
    const h16* __restrict__ Af_g,
    const h16* __restrict__ wq, const h16* __restrict__ wk, const h16* __restrict__ wv,
    const int* __restrict__ idxl, const int* __restrict__ cntp,
    h16* __restrict__ qf, h16* __restrict__ kcf, h16* __restrict__ vcf)
{
    extern __shared__ h16 gs[];
    const uint32_t sbase = smem_u32(gs);

    if (blockIdx.x < 4) {
        const int colBase = blockIdx.x * 128;
        const int rowBase = blockIdx.y * 128;
        const h16* Bf_g = wq;
        GEMM_PREAMBLE()
        GEMM_MAINLOOP(GEMM_LOAD_CHUNK)
        GEMM_EPI_SINGLE(qf, rowBase, ATT_SCALE)
    } else {
        const int xx      = blockIdx.x - 4;
        const int wsel    = xx >> 2;                 // 0 = K, 1 = V
        const int colBase = (xx & 3) * 128;
        const int b       = blockIdx.y >> 4;
        const int tile    = blockIdx.y & 15;
        const int cnt1    = cntp[b];
        const int kend    = (cnt1 + 63) & ~63;
        if (tile * 128 >= kend) return;
        const int* bidx = idxl + b * CN;
        const h16* Bf_g = wsel ? wv : wk;

        GEMM_PREAMBLE()

        int toks[4];
#pragma unroll
        for (int i = 0; i < 4; i++) {
            int r = (tid + 256 * i) >> 3;
            int jj = tile * 128 + r;
            toks[i] = bidx[jj < cnt1 ? jj : cnt1 - 1];
        }

        GEMM_MAINLOOP(KV_LOAD_CHUNK)

        const int rowB = b * CN + tile * 128;
        if (wsel == 0) {
            GEMM_EPI_SINGLE(kcf, rowB, 1.0f)
        } else {
            GEMM_EPI_SINGLE(vcf, rowB, 1.0f)
        }
    }
}

// ---------------- output projection (1-pass, fp32 out) -----------------------
__global__ __launch_bounds__(256, 2) void out_gemm_kernel(
    const h16* __restrict__ Af_g, const h16* __restrict__ Bf_g, float* __restrict__ C)
{
    extern __shared__ h16 gs[];
    const uint32_t sbase = smem_u32(gs);
    const int colBase = blockIdx.x * 128;
    const int rowBase = blockIdx.y * 128;

    GEMM_PREAMBLE()
    GEMM_MAINLOOP(GEMM_LOAD_CHUNK)

#pragma unroll
    for (int m = 0; m < 2; m++)
#pragma unroll
        for (int j = 0; j < 8; j++) {
            int row = rowBase + 32 * wM + 16 * m + g;
            int col = colBase + 64 * wN + 8 * j + 2 * tig;
            *(float2*)&C[(size_t)row * CDIM + col]       = make_float2(acc[m][j][0], acc[m][j][1]);
            *(float2*)&C[(size_t)(row + 8) * CDIM + col] = make_float2(acc[m][j][2], acc[m][j][3]);
        }
}

// ---------------- flash attention: 1-pass QK/PV, 3-stage pipeline ------------
#define ATEN (64 * SSTR)
#define ASTG (2 * ATEN)                 // kf, vf

__global__ __launch_bounds__(256, 2) void attn_mma_kernel(
    const h16* __restrict__ qf_g,
    const h16* __restrict__ kf_g, const h16* __restrict__ vf_g,
    const int* __restrict__ cntp, const float* __restrict__ sv,
    h16* __restrict__ OF)
{
    extern __shared__ h16 sm[];        // [3 stages][2 tensors][64*SSTR] + Q staging
    h16* Qs = sm + 3 * ASTG;

    const uint32_t sbase = smem_u32(sm);
    const int tid  = threadIdx.x;
    const int w    = tid >> 5;
    const int lane = tid & 31;
    const int g    = lane >> 2;
    const int tig  = lane & 3;
    const int q0   = blockIdx.x * 128;
    const int h    = blockIdx.y & 7;
    const int b    = blockIdx.y >> 3;
    const int cb   = h * CDH;

    const int cnt1 = cntp[b];
    const int cnt0 = CN - cnt1;
    const int nt   = (cnt1 + 63) >> 6;

    const uint32_t lrow = (uint32_t)(lane & 15) * SSTR * 2;

#define ATT_LOAD(st, kb_)                                                          \
    {                                                                              \
        _Pragma("unroll")                                                          \
        for (int i = 0; i < 2; i++) {                                              \
            int idx = tid + 256 * i;          /* 0..511 */                         \
            int r = idx >> 3, u = idx & 7;                                         \
            size_t grow = (size_t)(b * CN + (kb_) + r) * CDIM + cb + 8 * u;        \
            uint32_t so = sbase + (uint32_t)(((st) * ASTG + r * SSTR + 8 * u) * 2);\
            cp_async16(so + 0 * ATEN * 2, kf_g + grow);                            \
            cp_async16(so + 1 * ATEN * 2, vf_g + grow);                            \
        }                                                                          \
        cp_commit();                                                               \
    }

    // prime pipeline before Q staging (distinct smem regions)
    if (nt > 0) ATT_LOAD(0, 0)
    if (nt > 1) ATT_LOAD(1, 64)

    // ---- preload Q fragments via shared staging ----
    uint32_t qf[4][4];
    {
#pragma unroll
        for (int i = 0; i < 4; i++) {
            int idx = tid + 256 * i;
            int r = idx >> 3, u = idx & 7;
            *(uint4*)&Qs[r * SSTR + 8 * u] =
                *((const uint4*)(qf_g + (size_t)(b * CN + q0 + r) * CDIM + cb) + u);
        }
        __syncthreads();
#pragma unroll
        for (int ka = 0; ka < 4; ka++) {
            int rb = 16 * w;
            int ko = 16 * ka + 2 * tig;
            qf[ka][0] = *(const uint32_t*)&Qs[(rb + g)     * SSTR + ko];
            qf[ka][1] = *(const uint32_t*)&Qs[(rb + g + 8) * SSTR + ko];
            qf[ka][2] = *(const uint32_t*)&Qs[(rb + g)     * SSTR + ko + 8];
            qf[ka][3] = *(const uint32_t*)&Qs[(rb + g + 8) * SSTR + ko + 8];
        }
    }

    float o[8][4];
#pragma unroll
    for (int n = 0; n < 8; n++)
#pragma unroll
        for (int t = 0; t < 4; t++) o[n][t] = 0.f;
    float m0 = -1e30f, m1 = -1e30f, l0 = 0.f, l1 = 0.f;

#pragma unroll 1
    for (int it = 0; it < nt; it++) {
        const int kb = it * 64;
        const int st = it % 3;
        if (it < nt - 2) cp_wait<1>(); else cp_wait<0>();
        __syncthreads();
        if (it + 2 < nt) ATT_LOAD((it + 2) % 3, kb + 128)

        const h16* Kf = sm + st * ASTG;
        const uint32_t vfb = sbase + (uint32_t)((st * ASTG + ATEN) * 2) + lrow;

        // ---- S = Q K^T (1-pass) ----
        float s[8][4];
#pragma unroll
        for (int j = 0; j < 8; j++)
#pragma unroll
            for (int t = 0; t < 4; t++) s[j][t] = 0.f;
#pragma unroll
        for (int ka = 0; ka < 4; ka++) {
            const int ko = 16 * ka + 2 * tig;
#pragma unroll
            for (int j = 0; j < 8; j++) {
                int kr = 8 * j + g;
                uint32_t b0 = *(const uint32_t*)&Kf[kr * SSTR + ko];
                uint32_t b1 = *(const uint32_t*)&Kf[kr * SSTR + ko + 8];
                mma16816(s[j], qf[ka], b0, b1);
            }
        }

        // ---- tail exclusion for padding keys (exact: weight 0) ----
        if (kb + 64 > cnt1) {
#pragma unroll
            for (int j = 0; j < 8; j++) {
                int kc0 = kb + 8 * j + 2 * tig;
                if (kc0     >= cnt1) { s[j][0] = -1e30f; s[j][2] = -1e30f; }
                if (kc0 + 1 >= cnt1) { s[j][1] = -1e30f; s[j][3] = -1e30f; }
            }
        }

        // ---- online softmax ----
        float rm0 = -1e30f, rm1 = -1e30f;
#pragma unroll
        for (int j = 0; j < 8; j++) {
            rm0 = fmaxf(rm0, fmaxf(s[j][0], s[j][1]));
            rm1 = fmaxf(rm1, fmaxf(s[j][2], s[j][3]));
        }
        rm0 = fmaxf(rm0, __shfl_xor_sync(0xffffffffu, rm0, 1));
        rm0 = fmaxf(rm0, __shfl_xor_sync(0xffffffffu, rm0, 2));
        rm1 = fmaxf(rm1, __shfl_xor_sync(0xffffffffu, rm1, 1));
        rm1 = fmaxf(rm1, __shfl_xor_sync(0xffffffffu, rm1, 2));
        float mn0 = fmaxf(m0, rm0), mn1 = fmaxf(m1, rm1);
        float al0 = __expf(m0 - mn0), al1 = __expf(m1 - mn1);
        m0 = mn0; m1 = mn1;
        float rs0 = 0.f, rs1 = 0.f;
#pragma unroll
        for (int j = 0; j < 8; j++) {
            s[j][0] = __expf(s[j][0] - m0); rs0 += s[j][0];
            s[j][1] = __expf(s[j][1] - m0); rs0 += s[j][1];
            s[j][2] = __expf(s[j][2] - m1); rs1 += s[j][2];
            s[j][3] = __expf(s[j][3] - m1); rs1 += s[j][3];
        }
        rs0 += __shfl_xor_sync(0xffffffffu, rs0, 1);
        rs0 += __shfl_xor_sync(0xffffffffu, rs0, 2);
        rs1 += __shfl_xor_sync(0xffffffffu, rs1, 1);
        rs1 += __shfl_xor_sync(0xffffffffu, rs1, 2);
        l0 = l0 * al0 + rs0;
        l1 = l1 * al1 + rs1;
#pragma unroll
        for (int n = 0; n < 8; n++) {
            o[n][0] *= al0; o[n][1] *= al0; o[n][2] *= al1; o[n][3] *= al1;
        }

        // ---- O += P V (1-pass, ldmatrix.trans B-frags) ----
#pragma unroll
        for (int ka = 0; ka < 4; ka++) {
            const int j0 = 2 * ka, j1 = 2 * ka + 1;
            uint32_t ph[4];
            ph[0] = packh(__float2half_rn(s[j0][0]), __float2half_rn(s[j0][1]));
            ph[1] = packh(__float2half_rn(s[j0][2]), __float2half_rn(s[j0][3]));
            ph[2] = packh(__float2half_rn(s[j1][0]), __float2half_rn(s[j1][1]));
            ph[3] = packh(__float2half_rn(s[j1][2]), __float2half_rn(s[j1][3]));
            const uint32_t ksl = (uint32_t)(ka * 16 * SSTR * 2);
#pragma unroll
            for (int n = 0; n < 8; n++) {
                uint32_t b0, b1;
                ldsm_x2_t(b0, b1, vfb + ksl + 16 * n);
                mma16816(o[n], ph, b0, b1);
            }
        }
        // no trailing sync: stage reuse protected by the next iteration's top sync
    }

    // ---- virtual tile: masked keys, all with score exactly 1e-9 ----
    float w0c = 0.f, w1c = 0.f, lf0 = l0, lf1 = l1;
    if (cnt0 > 0) {
        float mf0 = fmaxf(m0, 1e-9f);
        float mf1 = fmaxf(m1, 1e-9f);
        float sc0 = __expf(m0 - mf0);
        float sc1 = __expf(m1 - mf1);
        w0c = __expf(1e-9f - mf0);
        w1c = __expf(1e-9f - mf1);
        lf0 = l0 * sc0 + (float)cnt0 * w0c;
        lf1 = l1 * sc1 + (float)cnt0 * w1c;
#pragma unroll
        for (int n = 0; n < 8; n++) {
            o[n][0] *= sc0; o[n][1] *= sc0; o[n][2] *= sc1; o[n][3] *= sc1;
        }
    }

    // ---- epilogue: masked-V correction, normalize, fp16 store ----
    float inv0 = 1.f / lf0, inv1 = 1.f / lf1;
    int qr = q0 + 16 * w + g;
#pragma unroll
    for (int n = 0; n < 8; n++) {
        int col = cb + 8 * n + 2 * tig;
        float sv0 = sv[b * CDIM + col];
        float sv1 = sv[b * CDIM + col + 1];
        float a0 = (o[n][0] + w0c * sv0) * inv0;
        float a1 = (o[n][1] + w0c * sv1) * inv0;
        float a2 = (o[n][2] + w1c * sv0) * inv1;
        float a3 = (o[n][3] + w1c * sv1) * inv1;
        *(uint32_t*)&OF[(size_t)(b * CN + qr) * CDIM + col] =
            packh(__float2half_rn(a0), __float2half_rn(a1));
        *(uint32_t*)&OF[(size_t)(b * CN + qr + 8) * CDIM + col] =
            packh(__float2half_rn(a2), __float2half_rn(a3));
    }
}

// ---------------------------------------------------------------------------
extern "C" void kernel_launch(void* const* d_in, const int* in_sizes, int n_in,
                              void* d_out, int out_size)
{
    const float* x    = (const float*)d_in[0];
    const int*   mask = (const int*)  d_in[1];
    const float* W[4] = { (const float*)d_in[2], (const float*)d_in[3],
                          (const float*)d_in[4], (const float*)d_in[5] };
    float* out = (float*)d_out;

    h16 *xf, *qf, *kf, *vf, *of, *wf;
    int *idxl, *cnt;
    float *sv, *xm;
    cudaGetSymbolAddress((void**)&xf, g_xf);
    cudaGetSymbolAddress((void**)&qf, g_qf);
    cudaGetSymbolAddress((void**)&kf, g_kf);
    cudaGetSymbolAddress((void**)&vf, g_vf);
    cudaGetSymbolAddress((void**)&of, g_of);
    cudaGetSymbolAddress((void**)&wf, g_wf);
    cudaGetSymbolAddress((void**)&idxl, g_idx);
    cudaGetSymbolAddress((void**)&cnt, g_cnt);
    cudaGetSymbolAddress((void**)&sv, g_sv);
    cudaGetSymbolAddress((void**)&xm, g_xm);

    const int M  = CB * CN;            // 8192
    const int NX = M * CDIM;
    const int NW = CDIM * CDIM;
    const int NTOT = NX + 4 * NW;
    const int NB   = NTOT / 1024;      // 5120 data blocks
    const int NZB  = (CB * CDIM + 1023) / 1024;  // 2 xm-zero blocks

    conv_all_kernel<<<NB + NZB, 256>>>(x, W[0], W[1], W[2], W[3], xf, wf, xm);
    prep_kernel<<<CB + 256, 256>>>(mask, x, idxl, cnt, xm);
    gemv_sv_kernel<<<dim3(CDIM / 8, CB), 256>>>(W[2], xm, sv);

    const int gsm  = 3 * STAGE_B;                                       // 110592 B
    const int asmb = 3 * ASTG * (int)sizeof(h16) + 128 * SSTR * (int)sizeof(h16); // 73728 B
    cudaFuncSetAttribute(proj_gemm_kernel, cudaFuncAttributeMaxDynamicSharedMemorySize, gsm);
    cudaFuncSetAttribute(out_gemm_kernel, cudaFuncAttributeMaxDynamicSharedMemorySize, gsm);
    cudaFuncSetAttribute(attn_mma_kernel, cudaFuncAttributeMaxDynamicSharedMemorySize, asmb);

    proj_gemm_kernel<<<dim3(12, 64), 256, gsm>>>(
        xf,
        wf + 0 * (size_t)NW, wf + 1 * (size_t)NW, wf + 2 * (size_t)NW,
        idxl, cnt, qf, kf, vf);

    attn_mma_kernel<<<dim3(CN / 128, CH * CB), 256, asmb>>>(
        qf, kf, vf, cnt, sv, of);

    out_gemm_kernel<<<dim3(4, M / 128), 256, gsm>>>(
        of, wf + 3 * (size_t)NW, out);
}

// round 15
// speedup vs baseline: 4.6140x; 1.0349x over previous
#include <cuda_runtime.h>
#include <cuda_fp16.h>
#include <cstdint>

#define CB   4
#define CN   2048
#define CH   8
#define CDH  64
#define CDIM 512
#define ATT_SCALE 0.125f
#define SSTR 72            // smem row stride in fp16 (64 data + 8 pad) = 144B

typedef __half h16;

// ---------------- scratch (__device__ globals; no allocation allowed) -------
__device__ h16 g_xf[CB * CN * CDIM];
__device__ h16 g_qf[CB * CN * CDIM];
__device__ h16 g_kf[CB * CN * CDIM];    // compacted K rows
__device__ h16 g_vf[CB * CN * CDIM];    // compacted V rows
__device__ h16 g_of[CB * CN * CDIM];
__device__ h16 g_wf[4][CDIM * CDIM];
__device__ int  g_idx[CB * CN];
__device__ int  g_cnt[CB];
__device__ float g_sv[CB * CDIM];
__device__ float g_xmp[CB * 32 * CDIM]; // masked-x partial sums (per 64-row segment)

// ---------------- helpers ----------------------------------------------------
__device__ __forceinline__ void mma16816(float* c, const uint32_t* a, uint32_t b0, uint32_t b1) {
    asm volatile(
        "mma.sync.aligned.m16n8k16.row.col.f32.f16.f16.f32 "
        "{%0,%1,%2,%3}, {%4,%5,%6,%7}, {%8,%9}, {%0,%1,%2,%3};\n"
        : "+f"(c[0]), "+f"(c[1]), "+f"(c[2]), "+f"(c[3])
        : "r"(a[0]), "r"(a[1]), "r"(a[2]), "r"(a[3]), "r"(b0), "r"(b1));
}
__device__ __forceinline__ void ldsm_x2_t(uint32_t& r0, uint32_t& r1, uint32_t saddr) {
    asm volatile("ldmatrix.sync.aligned.m8n8.x2.trans.shared.b16 {%0,%1}, [%2];"
                 : "=r"(r0), "=r"(r1) : "r"(saddr));
}
__device__ __forceinline__ uint32_t packh(h16 x, h16 y) {
    __half2 t = __halves2half2(x, y);
    return *reinterpret_cast<uint32_t*>(&t);
}
__device__ __forceinline__ uint32_t smem_u32(const void* p) {
    uint32_t a;
    asm("{ .reg .u64 t; cvta.to.shared.u64 t, %1; cvt.u32.u64 %0, t; }" : "=r"(a) : "l"(p));
    return a;
}
__device__ __forceinline__ void cp_async16(uint32_t saddr, const void* g) {
    asm volatile("cp.async.cg.shared.global [%0], [%1], 16;" :: "r"(saddr), "l"(g));
}
__device__ __forceinline__ void cp_commit() { asm volatile("cp.async.commit_group;"); }
template<int N> __device__ __forceinline__ void cp_wait() {
    asm volatile("cp.async.wait_group %0;" :: "n"(N));
}

// ---------------- ONE prep launch: convert + scan + masked-x partials --------
// blocks [0, NB)        : fp32 -> fp16 conversion of x and the 4 weights
// blocks [NB, NB+4)     : per-batch compaction scan
// blocks [NB+4, NB+260) : masked-x 64-row segment partial sums (no atomics)
__global__ void prep_all_kernel(const float* __restrict__ x,
                                const float* __restrict__ w0, const float* __restrict__ w1,
                                const float* __restrict__ w2, const float* __restrict__ w3,
                                const int* __restrict__ mask,
                                h16* __restrict__ xf, h16* __restrict__ wf,
                                int* __restrict__ idxl, int* __restrict__ cnt,
                                float* __restrict__ xmp)
{
    const int NXc = CB * CN * CDIM;
    const int NWc = CDIM * CDIM;
    const int NB  = (NXc + 4 * NWc) / 1024;
    const int t   = threadIdx.x;

    if ((int)blockIdx.x < NB) {
        int i = (blockIdx.x * blockDim.x + t) * 4;
        const float* src;
        h16* dst;
        if (i < NXc) {
            src = x + i;
            dst = xf + i;
        } else {
            int j = i - NXc;
            int w = j / NWc, o = j - w * NWc;
            src = ((w == 0) ? w0 : (w == 1) ? w1 : (w == 2) ? w2 : w3) + o;
            dst = wf + (size_t)w * NWc + o;
        }
        float4 v = *(const float4*)src;
        *(uint32_t*)(dst)     = packh(__float2half_rn(v.x), __float2half_rn(v.y));
        *(uint32_t*)(dst + 2) = packh(__float2half_rn(v.z), __float2half_rn(v.w));
    } else if ((int)blockIdx.x < NB + CB) {
        // ---- compaction scan for batch b ----
        __shared__ int ps[256];
        const int b = blockIdx.x - NB;
        int loc[8], c = 0;
#pragma unroll
        for (int i = 0; i < 8; i++) {
            loc[i] = c;
            c += (mask[b * CN + t * 8 + i] != 0);
        }
        ps[t] = c;
        __syncthreads();
        for (int off = 1; off < 256; off <<= 1) {
            int v = (t >= off) ? ps[t - off] : 0;
            __syncthreads();
            ps[t] += v;
            __syncthreads();
        }
        int excl = ps[t] - c;
#pragma unroll
        for (int i = 0; i < 8; i++)
            if (mask[b * CN + t * 8 + i] != 0)
                idxl[b * CN + excl + loc[i]] = t * 8 + i;
        if (t == 255) cnt[b] = ps[255];
    } else {
        // ---- masked-x partial sums: idx -> (chalf, b, seg) ----
        int idx   = blockIdx.x - NB - CB;     // 0..255
        int chalf = idx & 1;
        int b     = (idx >> 1) & 3;
        int seg   = idx >> 3;                 // 0..31
        int c     = chalf * 256 + t;
        int r0    = seg * 64;
        float s = 0.f;
#pragma unroll 4
        for (int i = 0; i < 64; i++) {
            int row = r0 + i;
            if (mask[b * CN + row] == 0)
                s += x[(size_t)(b * CN + row) * CDIM + c];
        }
        xmp[((size_t)b * 32 + seg) * CDIM + c] = s;
    }
}

// ---------------- GEMM mainloop: single fp16, 1-pass, 3-stage pipeline -------
#define TEN_B   (128 * SSTR * 2)
#define STAGE_B (2 * TEN_B)

#define GEMM_LOAD_CHUNK(st, kc)                                                   \
    {                                                                             \
        _Pragma("unroll")                                                         \
        for (int i = 0; i < 4; i++) {                                             \
            int idx = tid + 256 * i;                                              \
            int r = idx >> 3, u = idx & 7;                                        \
            uint32_t so = sbase + (uint32_t)((st) * STAGE_B + (r * SSTR + 8 * u) * 2); \
            cp_async16(so + 0 * TEN_B, Af_g + (size_t)(rowBase + r) * CDIM + (kc) + 8 * u); \
            cp_async16(so + 1 * TEN_B, Bf_g + (size_t)(colBase + r) * CDIM + (kc) + 8 * u); \
        }                                                                         \
        cp_commit();                                                              \
    }

#define KV_LOAD_CHUNK(st, kc)                                                     \
    {                                                                             \
        _Pragma("unroll")                                                         \
        for (int i = 0; i < 4; i++) {                                             \
            int idx = tid + 256 * i;                                              \
            int r = idx >> 3, u = idx & 7;                                        \
            uint32_t so = sbase + (uint32_t)((st) * STAGE_B + (r * SSTR + 8 * u) * 2); \
            cp_async16(so + 0 * TEN_B, Af_g + (size_t)(b * CN + toks[i]) * CDIM + (kc) + 8 * u); \
            cp_async16(so + 1 * TEN_B, Bf_g + (size_t)(colBase + r) * CDIM + (kc) + 8 * u); \
        }                                                                         \
        cp_commit();                                                              \
    }

#define GEMM_COMPUTE_CHUNK(st)                                                    \
    {                                                                             \
        const h16* Af = gs + (st) * 2 * 128 * SSTR;                               \
        const h16* Bf = Af + 128 * SSTR;                                          \
        _Pragma("unroll")                                                         \
        for (int ka = 0; ka < 4; ka++) {                                          \
            const int ko = 16 * ka + 2 * tig;                                     \
            uint32_t af[2][4];                                                    \
            _Pragma("unroll")                                                     \
            for (int m = 0; m < 2; m++) {                                         \
                int rb = 32 * wM + 16 * m;                                        \
                af[m][0] = *(const uint32_t*)&Af[(rb + g)     * SSTR + ko];       \
                af[m][1] = *(const uint32_t*)&Af[(rb + g + 8) * SSTR + ko];       \
                af[m][2] = *(const uint32_t*)&Af[(rb + g)     * SSTR + ko + 8];   \
                af[m][3] = *(const uint32_t*)&Af[(rb + g + 8) * SSTR + ko + 8];   \
            }                                                                     \
            _Pragma("unroll")                                                     \
            for (int j = 0; j < 8; j++) {                                         \
                int cr = 64 * wN + 8 * j + g;                                     \
                uint32_t b0 = *(const uint32_t*)&Bf[cr * SSTR + ko];              \
                uint32_t b1 = *(const uint32_t*)&Bf[cr * SSTR + ko + 8];          \
                mma16816(acc[0][j], af[0], b0, b1);                               \
                mma16816(acc[1][j], af[1], b0, b1);                               \
            }                                                                     \
        }                                                                         \
    }

#define GEMM_PREAMBLE()                                                           \
    const int tid  = threadIdx.x;                                                 \
    const int w    = tid >> 5;                                                    \
    const int lane = tid & 31;                                                    \
    const int g    = lane >> 2;                                                   \
    const int tig  = lane & 3;                                                    \
    const int wM   = w >> 1;                                                      \
    const int wN   = w & 1;                                                       \
    float acc[2][8][4];                                                           \
    _Pragma("unroll")                                                             \
    for (int m = 0; m < 2; m++)                                                   \
        _Pragma("unroll")                                                         \
        for (int j = 0; j < 8; j++)                                               \
            _Pragma("unroll")                                                     \
            for (int t = 0; t < 4; t++) acc[m][j][t] = 0.f;

#define GEMM_MAINLOOP(LOADM)                                                      \
    LOADM(0, 0)                                                                   \
    LOADM(1, 64)                                                                  \
    _Pragma("unroll 1")                                                           \
    for (int ch = 0; ch < 8; ch++) {                                              \
        if (ch < 6) cp_wait<1>(); else cp_wait<0>();                              \
        __syncthreads();                                                          \
        if (ch + 2 < 8) LOADM((ch + 2) % 3, 64 * (ch + 2))                        \
        GEMM_COMPUTE_CHUNK(ch % 3)                                                \
    }

#define GEMM_EPI_SINGLE(outF, rowB, scale)                                        \
    _Pragma("unroll")                                                             \
    for (int m = 0; m < 2; m++)                                                   \
        _Pragma("unroll")                                                         \
        for (int j = 0; j < 8; j++) {                                             \
            int row = (rowB) + 32 * wM + 16 * m + g;                              \
            int col = colBase + 64 * wN + 8 * j + 2 * tig;                        \
            *(uint32_t*)&(outF)[(size_t)row * CDIM + col] =                       \
                packh(__float2half_rn(acc[m][j][0] * (scale)),                    \
                      __float2half_rn(acc[m][j][1] * (scale)));                   \
            *(uint32_t*)&(outF)[(size_t)(row + 8) * CDIM + col] =                 \
                packh(__float2half_rn(acc[m][j][2] * (scale)),                    \
                      __float2half_rn(acc[m][j][3] * (scale)));                   \
        }

// ---------------- fused Q + compacted-K/V projection + sv GEMV ---------------
// grid (13, 64):  x 0..3 -> Q; 4..7 -> K; 8..11 -> V; 12 -> sv reduction+GEMV.
__global__ __launch_bounds__(256, 2) void proj_gemm_kernel(
    const h16* __restrict__ Af_g,
    const h16* __restrict__ wq, const h16* __restrict__ wk, const h16* __restrict__ wv,
    const float* __restrict__ Wv32, const float* __restrict__ xmp,
    const int* __restrict__ idxl, const int* __restrict__ cntp,
    h16* __restrict__ qf, h16* __restrict__ kcf, h16* __restrict__ vcf,
    float* __restrict__ sv)
{
    extern __shared__ h16 gs[];
    const uint32_t sbase = smem_u32(gs);

    if (blockIdx.x == 12) {
        // ---- sv block: y = b*16 + nchunk ----
        float* xsum = (float*)gs;           // 512 floats
        const int b      = blockIdx.y >> 4;
        const int nchunk = blockIdx.y & 15; // 32 outputs per block
        const int t = threadIdx.x;
        // reduce 32 partials for 2 channels per thread
#pragma unroll
        for (int p = 0; p < 2; p++) {
            int c = t + 256 * p;
            float s = 0.f;
#pragma unroll 8
            for (int seg = 0; seg < 32; seg++)
                s += xmp[((size_t)b * 32 + seg) * CDIM + c];
            xsum[c] = s;
        }
        __syncthreads();
        // warp dots: 8 warps x 4 outputs
        const int warp = t >> 5, lane = t & 31;
#pragma unroll
        for (int i = 0; i < 4; i++) {
            int n = nchunk * 32 + warp * 4 + i;
            const float* wr = Wv32 + (size_t)n * CDIM;
            float s = 0.f;
#pragma unroll
            for (int c = lane * 4; c < CDIM; c += 128) {
                float4 wv = *(const float4*)(wr + c);
                float4 xv = *(const float4*)(xsum + c);
                s += wv.x * xv.x + wv.y * xv.y + wv.z * xv.z + wv.w * xv.w;
            }
            s += __shfl_xor_sync(0xffffffffu, s, 16);
            s += __shfl_xor_sync(0xffffffffu, s, 8);
            s += __shfl_xor_sync(0xffffffffu, s, 4);
            s += __shfl_xor_sync(0xffffffffu, s, 2);
            s += __shfl_xor_sync(0xffffffffu, s, 1);
            if (lane == 0) sv[b * CDIM + n] = s;
        }
        return;
    }

    if (blockIdx.x < 4) {
        const int colBase = blockIdx.x * 128;
        const int rowBase = blockIdx.y * 128;
        const h16* Bf_g = wq;
        GEMM_PREAMBLE()
        GEMM_MAINLOOP(GEMM_LOAD_CHUNK)
        GEMM_EPI_SINGLE(qf, rowBase, ATT_SCALE)
    } else {
        const int xx      = blockIdx.x - 4;
        const int wsel    = xx >> 2;                 // 0 = K, 1 = V
        const int colBase = (xx & 3) * 128;
        const int b       = blockIdx.y >> 4;
        const int tile    = blockIdx.y & 15;
        const int cnt1    = cntp[b];
        const int kend    = (cnt1 + 63) & ~63;
        if (tile * 128 >= kend) return;
        const int* bidx = idxl + b * CN;
        const h16* Bf_g = wsel ? wv : wk;

        GEMM_PREAMBLE()

        int toks[4];
#pragma unroll
        for (int i = 0; i < 4; i++) {
            int r = (tid + 256 * i) >> 3;
            int jj = tile * 128 + r;
            toks[i] = bidx[jj < cnt1 ? jj : cnt1 - 1];
        }

        GEMM_MAINLOOP(KV_LOAD_CHUNK)

        const int rowB = b * CN + tile * 128;
        if (wsel == 0) {
            GEMM_EPI_SINGLE(kcf, rowB, 1.0f)
        } else {
            GEMM_EPI_SINGLE(vcf, rowB, 1.0f)
        }
    }
}

// ---------------- output projection (1-pass, fp32 out) -----------------------
__global__ __launch_bounds__(256, 2) void out_gemm_kernel(
    const h16* __restrict__ Af_g, const h16* __restrict__ Bf_g, float* __restrict__ C)
{
    extern __shared__ h16 gs[];
    const uint32_t sbase = smem_u32(gs);
    const int colBase = blockIdx.x * 128;
    const int rowBase = blockIdx.y * 128;

    GEMM_PREAMBLE()
    GEMM_MAINLOOP(GEMM_LOAD_CHUNK)

#pragma unroll
    for (int m = 0; m < 2; m++)
#pragma unroll
        for (int j = 0; j < 8; j++) {
            int row = rowBase + 32 * wM + 16 * m + g;
            int col = colBase + 64 * wN + 8 * j + 2 * tig;
            *(float2*)&C[(size_t)row * CDIM + col]       = make_float2(acc[m][j][0], acc[m][j][1]);
            *(float2*)&C[(size_t)(row + 8) * CDIM + col] = make_float2(acc[m][j][2], acc[m][j][3]);
        }
}

// ---------------- flash attention: 1-pass QK/PV, 3-stage pipeline ------------
#define ATEN (64 * SSTR)
#define ASTG (2 * ATEN)                 // kf, vf

__global__ __launch_bounds__(256, 2) void attn_mma_kernel(
    const h16* __restrict__ qf_g,
    const h16* __restrict__ kf_g, const h16* __restrict__ vf_g,
    const int* __restrict__ cntp, const float* __restrict__ sv,
    h16* __restrict__ OF)
{
    extern __shared__ h16 sm[];        // [3 stages][2 tensors][64*SSTR] + Q staging
    h16* Qs = sm + 3 * ASTG;

    const uint32_t sbase = smem_u32(sm);
    const int tid  = threadIdx.x;
    const int w    = tid >> 5;
    const int lane = tid & 31;
    const int g    = lane >> 2;
    const int tig  = lane & 3;
    const int q0   = blockIdx.x * 128;
    const int h    = blockIdx.y & 7;
    const int b    = blockIdx.y >> 3;
    const int cb   = h * CDH;

    const int cnt1 = cntp[b];
    const int cnt0 = CN - cnt1;
    const int nt   = (cnt1 + 63) >> 6;

    const uint32_t lrow = (uint32_t)(lane & 15) * SSTR * 2;

#define ATT_LOAD(st, kb_)                                                          \
    {                                                                              \
        _Pragma("unroll")                                                          \
        for (int i = 0; i < 2; i++) {                                              \
            int idx = tid + 256 * i;          /* 0..511 */                         \
            int r = idx >> 3, u = idx & 7;                                         \
            size_t grow = (size_t)(b * CN + (kb_) + r) * CDIM + cb + 8 * u;        \
            uint32_t so = sbase + (uint32_t)(((st) * ASTG + r * SSTR + 8 * u) * 2);\
            cp_async16(so + 0 * ATEN * 2, kf_g + grow);                            \
            cp_async16(so + 1 * ATEN * 2, vf_g + grow);                            \
        }                                                                          \
        cp_commit();                                                               \
    }

    if (nt > 0) ATT_LOAD(0, 0)
    if (nt > 1) ATT_LOAD(1, 64)

    // ---- preload Q fragments via shared staging ----
    uint32_t qf[4][4];
    {
#pragma unroll
        for (int i = 0; i < 4; i++) {
            int idx = tid + 256 * i;
            int r = idx >> 3, u = idx & 7;
            *(uint4*)&Qs[r * SSTR + 8 * u] =
                *((const uint4*)(qf_g + (size_t)(b * CN + q0 + r) * CDIM + cb) + u);
        }
        __syncthreads();
#pragma unroll
        for (int ka = 0; ka < 4; ka++) {
            int rb = 16 * w;
            int ko = 16 * ka + 2 * tig;
            qf[ka][0] = *(const uint32_t*)&Qs[(rb + g)     * SSTR + ko];
            qf[ka][1] = *(const uint32_t*)&Qs[(rb + g + 8) * SSTR + ko];
            qf[ka][2] = *(const uint32_t*)&Qs[(rb + g)     * SSTR + ko + 8];
            qf[ka][3] = *(const uint32_t*)&Qs[(rb + g + 8) * SSTR + ko + 8];
        }
    }

    float o[8][4];
#pragma unroll
    for (int n = 0; n < 8; n++)
#pragma unroll
        for (int t = 0; t < 4; t++) o[n][t] = 0.f;
    float m0 = -1e30f, m1 = -1e30f, l0 = 0.f, l1 = 0.f;

#pragma unroll 1
    for (int it = 0; it < nt; it++) {
        const int kb = it * 64;
        const int st = it % 3;
        if (it < nt - 2) cp_wait<1>(); else cp_wait<0>();
        __syncthreads();
        if (it + 2 < nt) ATT_LOAD((it + 2) % 3, kb + 128)

        const h16* Kf = sm + st * ASTG;
        const uint32_t vfb = sbase + (uint32_t)((st * ASTG + ATEN) * 2) + lrow;

        // ---- S = Q K^T (1-pass) ----
        float s[8][4];
#pragma unroll
        for (int j = 0; j < 8; j++)
#pragma unroll
            for (int t = 0; t < 4; t++) s[j][t] = 0.f;
#pragma unroll
        for (int ka = 0; ka < 4; ka++) {
            const int ko = 16 * ka + 2 * tig;
#pragma unroll
            for (int j = 0; j < 8; j++) {
                int kr = 8 * j + g;
                uint32_t b0 = *(const uint32_t*)&Kf[kr * SSTR + ko];
                uint32_t b1 = *(const uint32_t*)&Kf[kr * SSTR + ko + 8];
                mma16816(s[j], qf[ka], b0, b1);
            }
        }

        // ---- tail exclusion for padding keys (exact: weight 0) ----
        if (kb + 64 > cnt1) {
#pragma unroll
            for (int j = 0; j < 8; j++) {
                int kc0 = kb + 8 * j + 2 * tig;
                if (kc0     >= cnt1) { s[j][0] = -1e30f; s[j][2] = -1e30f; }
                if (kc0 + 1 >= cnt1) { s[j][1] = -1e30f; s[j][3] = -1e30f; }
            }
        }

        // ---- online softmax ----
        float rm0 = -1e30f, rm1 = -1e30f;
#pragma unroll
        for (int j = 0; j < 8; j++) {
            rm0 = fmaxf(rm0, fmaxf(s[j][0], s[j][1]));
            rm1 = fmaxf(rm1, fmaxf(s[j][2], s[j][3]));
        }
        rm0 = fmaxf(rm0, __shfl_xor_sync(0xffffffffu, rm0, 1));
        rm0 = fmaxf(rm0, __shfl_xor_sync(0xffffffffu, rm0, 2));
        rm1 = fmaxf(rm1, __shfl_xor_sync(0xffffffffu, rm1, 1));
        rm1 = fmaxf(rm1, __shfl_xor_sync(0xffffffffu, rm1, 2));
        float mn0 = fmaxf(m0, rm0), mn1 = fmaxf(m1, rm1);
        float al0 = __expf(m0 - mn0), al1 = __expf(m1 - mn1);
        m0 = mn0; m1 = mn1;
        float rs0 = 0.f, rs1 = 0.f;
#pragma unroll
        for (int j = 0; j < 8; j++) {
            s[j][0] = __expf(s[j][0] - m0); rs0 += s[j][0];
            s[j][1] = __expf(s[j][1] - m0); rs0 += s[j][1];
            s[j][2] = __expf(s[j][2] - m1); rs1 += s[j][2];
            s[j][3] = __expf(s[j][3] - m1); rs1 += s[j][3];
        }
        rs0 += __shfl_xor_sync(0xffffffffu, rs0, 1);
        rs0 += __shfl_xor_sync(0xffffffffu, rs0, 2);
        rs1 += __shfl_xor_sync(0xffffffffu, rs1, 1);
        rs1 += __shfl_xor_sync(0xffffffffu, rs1, 2);
        l0 = l0 * al0 + rs0;
        l1 = l1 * al1 + rs1;
#pragma unroll
        for (int n = 0; n < 8; n++) {
            o[n][0] *= al0; o[n][1] *= al0; o[n][2] *= al1; o[n][3] *= al1;
        }

        // ---- O += P V (1-pass, ldmatrix.trans B-frags) ----
#pragma unroll
        for (int ka = 0; ka < 4; ka++) {
            const int j0 = 2 * ka, j1 = 2 * ka + 1;
            uint32_t ph[4];
            ph[0] = packh(__float2half_rn(s[j0][0]), __float2half_rn(s[j0][1]));
            ph[1] = packh(__float2half_rn(s[j0][2]), __float2half_rn(s[j0][3]));
            ph[2] = packh(__float2half_rn(s[j1][0]), __float2half_rn(s[j1][1]));
            ph[3] = packh(__float2half_rn(s[j1][2]), __float2half_rn(s[j1][3]));
            const uint32_t ksl = (uint32_t)(ka * 16 * SSTR * 2);
#pragma unroll
            for (int n = 0; n < 8; n++) {
                uint32_t b0, b1;
                ldsm_x2_t(b0, b1, vfb + ksl + 16 * n);
                mma16816(o[n], ph, b0, b1);
            }
        }
    }

    // ---- virtual tile: masked keys, all with score exactly 1e-9 ----
    float w0c = 0.f, w1c = 0.f, lf0 = l0, lf1 = l1;
    if (cnt0 > 0) {
        float mf0 = fmaxf(m0, 1e-9f);
        float mf1 = fmaxf(m1, 1e-9f);
        float sc0 = __expf(m0 - mf0);
        float sc1 = __expf(m1 - mf1);
        w0c = __expf(1e-9f - mf0);
        w1c = __expf(1e-9f - mf1);
        lf0 = l0 * sc0 + (float)cnt0 * w0c;
        lf1 = l1 * sc1 + (float)cnt0 * w1c;
#pragma unroll
        for (int n = 0; n < 8; n++) {
            o[n][0] *= sc0; o[n][1] *= sc0; o[n][2] *= sc1; o[n][3] *= sc1;
        }
    }

    // ---- epilogue: masked-V correction, normalize, fp16 store ----
    float inv0 = 1.f / lf0, inv1 = 1.f / lf1;
    int qr = q0 + 16 * w + g;
#pragma unroll
    for (int n = 0; n < 8; n++) {
        int col = cb + 8 * n + 2 * tig;
        float sv0 = sv[b * CDIM + col];
        float sv1 = sv[b * CDIM + col + 1];
        float a0 = (o[n][0] + w0c * sv0) * inv0;
        float a1 = (o[n][1] + w0c * sv1) * inv0;
        float a2 = (o[n][2] + w1c * sv0) * inv1;
        float a3 = (o[n][3] + w1c * sv1) * inv1;
        *(uint32_t*)&OF[(size_t)(b * CN + qr) * CDIM + col] =
            packh(__float2half_rn(a0), __float2half_rn(a1));
        *(uint32_t*)&OF[(size_t)(b * CN + qr + 8) * CDIM + col] =
            packh(__float2half_rn(a2), __float2half_rn(a3));
    }
}

// ---------------------------------------------------------------------------
extern "C" void kernel_launch(void* const* d_in, const int* in_sizes, int n_in,
                              void* d_out, int out_size)
{
    const float* x    = (const float*)d_in[0];
    const int*   mask = (const int*)  d_in[1];
    const float* W[4] = { (const float*)d_in[2], (const float*)d_in[3],
                          (const float*)d_in[4], (const float*)d_in[5] };
    float* out = (float*)d_out;

    h16 *xf, *qf, *kf, *vf, *of, *wf;
    int *idxl, *cnt;
    float *sv, *xmp;
    cudaGetSymbolAddress((void**)&xf, g_xf);
    cudaGetSymbolAddress((void**)&qf, g_qf);
    cudaGetSymbolAddress((void**)&kf, g_kf);
    cudaGetSymbolAddress((void**)&vf, g_vf);
    cudaGetSymbolAddress((void**)&of, g_of);
    cudaGetSymbolAddress((void**)&wf, g_wf);
    cudaGetSymbolAddress((void**)&idxl, g_idx);
    cudaGetSymbolAddress((void**)&cnt, g_cnt);
    cudaGetSymbolAddress((void**)&sv, g_sv);
    cudaGetSymbolAddress((void**)&xmp, g_xmp);

    const int M  = CB * CN;            // 8192
    const int NX = M * CDIM;
    const int NW = CDIM * CDIM;
    const int NB = (NX + 4 * NW) / 1024;  // 5120

    prep_all_kernel<<<NB + CB + 256, 256>>>(x, W[0], W[1], W[2], W[3], mask,
                                            xf, wf, idxl, cnt, xmp);

    const int gsm  = 3 * STAGE_B;                                       // 110592 B
    const int asmb = 3 * ASTG * (int)sizeof(h16) + 128 * SSTR * (int)sizeof(h16); // 73728 B
    cudaFuncSetAttribute(proj_gemm_kernel, cudaFuncAttributeMaxDynamicSharedMemorySize, gsm);
    cudaFuncSetAttribute(out_gemm_kernel, cudaFuncAttributeMaxDynamicSharedMemorySize, gsm);
    cudaFuncSetAttribute(attn_mma_kernel, cudaFuncAttributeMaxDynamicSharedMemorySize, asmb);

    proj_gemm_kernel<<<dim3(13, 64), 256, gsm>>>(
        xf,
        wf + 0 * (size_t)NW, wf + 1 * (size_t)NW, wf + 2 * (size_t)NW,
        W[2], xmp, idxl, cnt, qf, kf, vf, sv);

    attn_mma_kernel<<<dim3(CN / 128, CH * CB), 256, asmb>>>(
        qf, kf, vf, cnt, sv, of);

    out_gemm_kernel<<<dim3(4, M / 128), 256, gsm>>>(
        of, wf + 3 * (size_t)NW, out);
}